// round 1
// baseline (speedup 1.0000x reference)
#include <cuda_runtime.h>
#include <cuda_bf16.h>

// ---------------- problem constants ----------------
#define BATCH  2
#define SEQ    4096
#define DMODEL 1024
#define DINNER 2048
#define DSTATE 128
#define NHEADS 32
#define HDIM   64
#define CDIM   2304        // DINNER + 2*DSTATE
#define NIN    4384        // 2*DINNER + 2*DSTATE + NHEADS
#define QC     64          // chunk length
#define NCH    64          // SEQ / QC
#define BL     8192        // BATCH * SEQ
#define DTMIN  0.001f
#define DTMAX  0.1f

// ---------------- scratch (device globals; no allocs allowed) ----------------
__device__ float g_zxbcdt[(size_t)BL * NIN];       // in_proj output
__device__ float g_xbc[(size_t)BL * CDIM];         // conv+silu output (x_ssm | B | C)
__device__ float g_dt[(size_t)BL * NHEADS];        // dt after sigmoid mapping
__device__ float g_Acum[(size_t)BATCH * NCH * NHEADS * QC];
__device__ float g_cdecay[(size_t)BATCH * NCH * NHEADS];
__device__ float g_states[(size_t)BATCH * NCH * NHEADS * HDIM * DSTATE];
__device__ float g_prevs [(size_t)BATCH * NCH * NHEADS * HDIM * DSTATE];
__device__ float g_Y[(size_t)BL * DINNER];         // Yd then += Yo + skip, then gated+rmsnormed in place
__device__ float g_out[(size_t)BL * DMODEL];       // out_proj output (pre-LN)

// ---------------- helpers ----------------
__device__ __forceinline__ float block_sum(float v) {
    __shared__ float sh[32];
    __syncthreads();                    // safe for repeated use
    int lane = threadIdx.x & 31, wid = threadIdx.x >> 5;
    #pragma unroll
    for (int o = 16; o > 0; o >>= 1) v += __shfl_xor_sync(0xffffffffu, v, o);
    if (lane == 0) sh[wid] = v;
    __syncthreads();
    float r = (threadIdx.x < (blockDim.x >> 5)) ? sh[threadIdx.x] : 0.f;
    if (wid == 0) {
        #pragma unroll
        for (int o = 16; o > 0; o >>= 1) r += __shfl_xor_sync(0xffffffffu, r, o);
        if (lane == 0) sh[0] = r;
    }
    __syncthreads();
    return sh[0];
}

__device__ __forceinline__ float silu(float x) { return x / (1.f + __expf(-x)); }

// ---------------- tiled SGEMM: C[M,N] = A[M,K] * B[N,K]^T (both K-contiguous) ----------------
#define GBM 128
#define GBN 128
#define GBK 16
__device__ __forceinline__ void sgemm_nt(const float* __restrict__ A,
                                         const float* __restrict__ B,
                                         float* __restrict__ C,
                                         int M, int N, int K) {
    __shared__ float As[GBK][GBM];
    __shared__ float Bs[GBK][GBN];
    const int tid = threadIdx.x;                  // 256 threads
    const int bm = blockIdx.y * GBM;
    const int bn = blockIdx.x * GBN;
    const int tx = tid & 15, ty = tid >> 4;       // 16x16 thread grid
    const int tr = ty * 8, tc = tx * 8;           // 8x8 per thread
    const int lrow = tid >> 2;                    // 0..63
    const int lcol = (tid & 3) * 4;               // 0,4,8,12

    float acc[8][8];
    #pragma unroll
    for (int i = 0; i < 8; i++)
        #pragma unroll
        for (int j = 0; j < 8; j++) acc[i][j] = 0.f;

    for (int k0 = 0; k0 < K; k0 += GBK) {
        #pragma unroll
        for (int h = 0; h < 2; h++) {
            int r = lrow + h * 64;
            int gr = bm + r;
            float4 v = make_float4(0.f, 0.f, 0.f, 0.f);
            if (gr < M) v = *(const float4*)&A[(long long)gr * K + k0 + lcol];
            As[lcol + 0][r] = v.x; As[lcol + 1][r] = v.y;
            As[lcol + 2][r] = v.z; As[lcol + 3][r] = v.w;
        }
        #pragma unroll
        for (int h = 0; h < 2; h++) {
            int r = lrow + h * 64;
            int gr = bn + r;
            float4 v = make_float4(0.f, 0.f, 0.f, 0.f);
            if (gr < N) v = *(const float4*)&B[(long long)gr * K + k0 + lcol];
            Bs[lcol + 0][r] = v.x; Bs[lcol + 1][r] = v.y;
            Bs[lcol + 2][r] = v.z; Bs[lcol + 3][r] = v.w;
        }
        __syncthreads();
        #pragma unroll
        for (int k = 0; k < GBK; k++) {
            float a[8], b[8];
            #pragma unroll
            for (int i = 0; i < 8; i++) a[i] = As[k][tr + i];
            #pragma unroll
            for (int j = 0; j < 8; j++) b[j] = Bs[k][tc + j];
            #pragma unroll
            for (int i = 0; i < 8; i++)
                #pragma unroll
                for (int j = 0; j < 8; j++)
                    acc[i][j] = fmaf(a[i], b[j], acc[i][j]);
        }
        __syncthreads();
    }
    #pragma unroll
    for (int i = 0; i < 8; i++) {
        int gr = bm + tr + i;
        if (gr >= M) continue;
        #pragma unroll
        for (int j = 0; j < 8; j += 4) {
            int gc = bn + tc + j;
            if (gc + 3 < N) {
                *(float4*)&C[(long long)gr * N + gc] =
                    make_float4(acc[i][j], acc[i][j+1], acc[i][j+2], acc[i][j+3]);
            } else {
                #pragma unroll
                for (int jj = 0; jj < 4; jj++)
                    if (gc + jj < N) C[(long long)gr * N + gc + jj] = acc[i][j + jj];
            }
        }
    }
}

__global__ void k_gemm1(const float* __restrict__ x, const float* __restrict__ w) {
    sgemm_nt(x, w, g_zxbcdt, BL, NIN, DMODEL);
}
__global__ void k_gemm2(const float* __restrict__ w) {
    sgemm_nt(g_Y, w, g_out, BL, DMODEL, DINNER);
}

// ---------------- conv1d (K=4, causal) + bias + SiLU ----------------
__global__ void k_conv(const float* __restrict__ conv_w, const float* __restrict__ conv_b) {
    long long idx = (long long)blockIdx.x * blockDim.x + threadIdx.x;
    if (idx >= (long long)BL * CDIM) return;
    int ch = (int)(idx % CDIM);
    int bl = (int)(idx / CDIM);
    int l  = bl & (SEQ - 1);
    const float4 w = *(const float4*)&conv_w[ch * 4];
    float acc = conv_b[ch];
    float v0 = (l >= 3) ? g_zxbcdt[(long long)(bl - 3) * NIN + DINNER + ch] : 0.f;
    float v1 = (l >= 2) ? g_zxbcdt[(long long)(bl - 2) * NIN + DINNER + ch] : 0.f;
    float v2 = (l >= 1) ? g_zxbcdt[(long long)(bl - 1) * NIN + DINNER + ch] : 0.f;
    float v3 = g_zxbcdt[(long long)bl * NIN + DINNER + ch];
    acc += v0 * w.x + v1 * w.y + v2 * w.z + v3 * w.w;
    g_xbc[(long long)bl * CDIM + ch] = silu(acc);
}

// ---------------- dt = DTMIN + (DTMAX-DTMIN)*sigmoid(dt_raw + bias) ----------------
__global__ void k_dtk(const float* __restrict__ dt_bias) {
    int idx = blockIdx.x * blockDim.x + threadIdx.x;
    if (idx >= BL * NHEADS) return;
    int h = idx & (NHEADS - 1);
    int bl = idx / NHEADS;
    float raw = g_zxbcdt[(long long)bl * NIN + DINNER + CDIM + h] + dt_bias[h];
    float sg = 1.f / (1.f + __expf(-raw));
    g_dt[idx] = DTMIN + (DTMAX - DTMIN) * sg;
}

// ---------------- per-chunk: CB^T*Lmat, Yd, states, decay ----------------
// smem layout (floats):  Bs[64*129] Cs[64*129] xs[64*65] CBL[64*65] dt[64] Acum[64] ws[64]
#define BS_STR 129
#define XS_STR 65
#define SMEM_CHUNK_FLOATS (64*129 + 64*129 + 64*65 + 64*65 + 64 + 64 + 64)

__global__ void k_chunk(const float* __restrict__ A_log) {
    extern __shared__ float sm[];
    float* Bs   = sm;
    float* Cs   = Bs + 64 * BS_STR;
    float* xs   = Cs + 64 * BS_STR;
    float* CBL  = xs + 64 * XS_STR;
    float* dt_s = CBL + 64 * XS_STR;
    float* Ac_s = dt_s + 64;
    float* ws   = Ac_s + 64;

    const int tid = threadIdx.x;
    const int bc = blockIdx.x;                 // 0..BATCH*NCH-1
    const int h  = blockIdx.y;
    const int b  = bc / NCH, cc = bc % NCH;
    const long long base_bl = (long long)b * SEQ + (long long)cc * QC;

    // load B, C chunks (64 x 128) as float4 into padded rows
    #pragma unroll
    for (int it = 0; it < 8; it++) {
        int i4 = tid + it * 256;               // 2048 float4s
        int q = i4 >> 5, n4 = (i4 & 31) * 4;
        float4 v = *(const float4*)&g_xbc[(base_bl + q) * CDIM + DINNER + n4];
        Bs[q * BS_STR + n4 + 0] = v.x; Bs[q * BS_STR + n4 + 1] = v.y;
        Bs[q * BS_STR + n4 + 2] = v.z; Bs[q * BS_STR + n4 + 3] = v.w;
        float4 u = *(const float4*)&g_xbc[(base_bl + q) * CDIM + DINNER + DSTATE + n4];
        Cs[q * BS_STR + n4 + 0] = u.x; Cs[q * BS_STR + n4 + 1] = u.y;
        Cs[q * BS_STR + n4 + 2] = u.z; Cs[q * BS_STR + n4 + 3] = u.w;
    }
    // load x chunk for this head (64 x 64), unscaled
    #pragma unroll
    for (int it = 0; it < 4; it++) {
        int i4 = tid + it * 256;               // 1024 float4s
        int q = i4 >> 4, p4 = (i4 & 15) * 4;
        float4 v = *(const float4*)&g_xbc[(base_bl + q) * CDIM + h * HDIM + p4];
        xs[q * XS_STR + p4 + 0] = v.x; xs[q * XS_STR + p4 + 1] = v.y;
        xs[q * XS_STR + p4 + 2] = v.z; xs[q * XS_STR + p4 + 3] = v.w;
    }
    if (tid < QC) dt_s[tid] = g_dt[(base_bl + tid) * NHEADS + h];
    __syncthreads();

    if (tid == 0) {
        float Ah = -__expf(A_log[h]);
        float s = 0.f;
        for (int q = 0; q < QC; q++) { s += dt_s[q] * Ah; Ac_s[q] = s; }
    }
    __syncthreads();

    if (tid < QC) {
        float last = Ac_s[QC - 1];
        ws[tid] = __expf(last - Ac_s[tid]) * dt_s[tid];   // decay_states * dt
        g_Acum[((long long)bc * NHEADS + h) * QC + tid] = Ac_s[tid];
        if (tid == 0) g_cdecay[(long long)bc * NHEADS + h] = __expf(last);
    }

    // ---- CBL[q][s] = (C_q . B_s) * exp(Acum_q - Acum_s) * dt_s   (s<=q else 0)
    {
        const int tq0 = (tid >> 4) * 4;
        const int ts0 = (tid & 15) * 4;
        float acc[4][4];
        #pragma unroll
        for (int i = 0; i < 4; i++)
            #pragma unroll
            for (int j = 0; j < 4; j++) acc[i][j] = 0.f;
        for (int n = 0; n < DSTATE; n++) {
            float cq[4], bs[4];
            #pragma unroll
            for (int i = 0; i < 4; i++) cq[i] = Cs[(tq0 + i) * BS_STR + n];
            #pragma unroll
            for (int j = 0; j < 4; j++) bs[j] = Bs[(ts0 + j) * BS_STR + n];
            #pragma unroll
            for (int i = 0; i < 4; i++)
                #pragma unroll
                for (int j = 0; j < 4; j++)
                    acc[i][j] = fmaf(cq[i], bs[j], acc[i][j]);
        }
        #pragma unroll
        for (int i = 0; i < 4; i++) {
            int q = tq0 + i;
            #pragma unroll
            for (int j = 0; j < 4; j++) {
                int s = ts0 + j;
                float val = 0.f;
                if (s <= q) val = acc[i][j] * __expf(Ac_s[q] - Ac_s[s]) * dt_s[s];
                CBL[q * XS_STR + s] = val;
            }
        }
    }
    __syncthreads();

    // ---- Yd[q][p] = sum_s CBL[q][s] * xs[s][p]  -> write to g_Y
    {
        const int tq0 = (tid >> 4) * 4;
        const int tp0 = (tid & 15) * 4;
        float acc[4][4];
        #pragma unroll
        for (int i = 0; i < 4; i++)
            #pragma unroll
            for (int j = 0; j < 4; j++) acc[i][j] = 0.f;
        for (int s = 0; s < QC; s++) {
            float cb[4], xv[4];
            #pragma unroll
            for (int i = 0; i < 4; i++) cb[i] = CBL[(tq0 + i) * XS_STR + s];
            #pragma unroll
            for (int j = 0; j < 4; j++) xv[j] = xs[s * XS_STR + tp0 + j];
            #pragma unroll
            for (int i = 0; i < 4; i++)
                #pragma unroll
                for (int j = 0; j < 4; j++)
                    acc[i][j] = fmaf(cb[i], xv[j], acc[i][j]);
        }
        #pragma unroll
        for (int i = 0; i < 4; i++) {
            int q = tq0 + i;
            *(float4*)&g_Y[(base_bl + q) * DINNER + h * HDIM + tp0] =
                make_float4(acc[i][0], acc[i][1], acc[i][2], acc[i][3]);
        }
    }

    // ---- states[p][n] = sum_q (B[q][n]*ws[q]) * xs[q][p]
    {
        const int tp0 = (tid >> 4) * 4;
        const int tn0 = (tid & 15) * 8;
        float acc[4][8];
        #pragma unroll
        for (int i = 0; i < 4; i++)
            #pragma unroll
            for (int j = 0; j < 8; j++) acc[i][j] = 0.f;
        for (int q = 0; q < QC; q++) {
            float wq = ws[q];
            float xv[4], bv[8];
            #pragma unroll
            for (int i = 0; i < 4; i++) xv[i] = xs[q * XS_STR + tp0 + i] * wq;
            #pragma unroll
            for (int j = 0; j < 8; j++) bv[j] = Bs[q * BS_STR + tn0 + j];
            #pragma unroll
            for (int i = 0; i < 4; i++)
                #pragma unroll
                for (int j = 0; j < 8; j++)
                    acc[i][j] = fmaf(xv[i], bv[j], acc[i][j]);
        }
        long long sbase = ((long long)bc * NHEADS + h) * HDIM * DSTATE;
        #pragma unroll
        for (int i = 0; i < 4; i++) {
            int p = tp0 + i;
            #pragma unroll
            for (int j = 0; j < 8; j += 4)
                *(float4*)&g_states[sbase + (long long)p * DSTATE + tn0 + j] =
                    make_float4(acc[i][j], acc[i][j+1], acc[i][j+2], acc[i][j+3]);
        }
    }
}

// ---------------- sequential inter-chunk scan ----------------
__global__ void k_scan() {
    int bh = blockIdx.x;                        // 0..BATCH*NHEADS-1
    int b = bh / NHEADS, h = bh % NHEADS;
    int tid = threadIdx.x;                      // 256
    float carry[32];
    #pragma unroll
    for (int i = 0; i < 32; i++) carry[i] = 0.f;
    for (int c = 0; c < NCH; c++) {
        float dec = g_cdecay[((long long)b * NCH + c) * NHEADS + h];
        long long base = (((long long)b * NCH + c) * NHEADS + h) * (HDIM * DSTATE);
        #pragma unroll
        for (int i = 0; i < 32; i++) {
            int idx = tid + i * 256;
            float st = g_states[base + idx];
            g_prevs[base + idx] = carry[i];
            carry[i] = fmaf(dec, carry[i], st);
        }
    }
}

// ---------------- Yo + D_skip*x, accumulate into g_Y ----------------
#define SMEM_YO_FLOATS (64*129 + 64*129 + 64)
__global__ void k_yo(const float* __restrict__ D_skip) {
    extern __shared__ float sm[];
    float* Cs = sm;
    float* Pv = Cs + 64 * BS_STR;               // prevs[p][n]
    float* eA = Pv + 64 * BS_STR;

    const int tid = threadIdx.x;
    const int bc = blockIdx.x;
    const int h  = blockIdx.y;
    const int b  = bc / NCH, cc = bc % NCH;
    const long long base_bl = (long long)b * SEQ + (long long)cc * QC;
    const long long pbase = ((long long)bc * NHEADS + h) * (HDIM * DSTATE);

    #pragma unroll
    for (int it = 0; it < 8; it++) {
        int i4 = tid + it * 256;
        int r = i4 >> 5, n4 = (i4 & 31) * 4;
        float4 u = *(const float4*)&g_xbc[(base_bl + r) * CDIM + DINNER + DSTATE + n4];
        Cs[r * BS_STR + n4 + 0] = u.x; Cs[r * BS_STR + n4 + 1] = u.y;
        Cs[r * BS_STR + n4 + 2] = u.z; Cs[r * BS_STR + n4 + 3] = u.w;
        float4 v = *(const float4*)&g_prevs[pbase + (long long)r * DSTATE + n4];
        Pv[r * BS_STR + n4 + 0] = v.x; Pv[r * BS_STR + n4 + 1] = v.y;
        Pv[r * BS_STR + n4 + 2] = v.z; Pv[r * BS_STR + n4 + 3] = v.w;
    }
    if (tid < QC) eA[tid] = __expf(g_Acum[((long long)bc * NHEADS + h) * QC + tid]);
    __syncthreads();

    const float dsk = D_skip[h];
    const int tq0 = (tid >> 4) * 4;
    const int tp0 = (tid & 15) * 4;
    float acc[4][4];
    #pragma unroll
    for (int i = 0; i < 4; i++)
        #pragma unroll
        for (int j = 0; j < 4; j++) acc[i][j] = 0.f;
    for (int n = 0; n < DSTATE; n++) {
        float cq[4], pv[4];
        #pragma unroll
        for (int i = 0; i < 4; i++) cq[i] = Cs[(tq0 + i) * BS_STR + n];
        #pragma unroll
        for (int j = 0; j < 4; j++) pv[j] = Pv[(tp0 + j) * BS_STR + n];
        #pragma unroll
        for (int i = 0; i < 4; i++)
            #pragma unroll
            for (int j = 0; j < 4; j++)
                acc[i][j] = fmaf(cq[i], pv[j], acc[i][j]);
    }
    #pragma unroll
    for (int i = 0; i < 4; i++) {
        int q = tq0 + i;
        long long row = base_bl + q;
        float4 yv = *(float4*)&g_Y[row * DINNER + h * HDIM + tp0];
        float4 xv = *(const float4*)&g_xbc[row * CDIM + h * HDIM + tp0];
        float e = eA[q];
        yv.x += e * acc[i][0] + dsk * xv.x;
        yv.y += e * acc[i][1] + dsk * xv.y;
        yv.z += e * acc[i][2] + dsk * xv.z;
        yv.w += e * acc[i][3] + dsk * xv.w;
        *(float4*)&g_Y[row * DINNER + h * HDIM + tp0] = yv;
    }
}

// ---------------- gate with silu(z) + RMSNorm over DINNER ----------------
__global__ void k_gate(const float* __restrict__ norm_w) {
    __shared__ float sv[DINNER];
    const long long row = blockIdx.x;
    float local = 0.f;
    for (int i = threadIdx.x; i < DINNER; i += blockDim.x) {
        float yv = g_Y[row * DINNER + i];
        float zv = g_zxbcdt[row * NIN + i];
        float v = yv * silu(zv);
        sv[i] = v;
        local += v * v;
    }
    float tot = block_sum(local);
    float scale = rsqrtf(tot / DINNER + 1e-5f);
    for (int i = threadIdx.x; i < DINNER; i += blockDim.x)
        g_Y[row * DINNER + i] = sv[i] * scale * norm_w[i];
}

// ---------------- final LayerNorm + residual ----------------
__global__ void k_ln(const float* __restrict__ x, const float* __restrict__ ln_w,
                     const float* __restrict__ ln_b, float* __restrict__ out) {
    const long long row = blockIdx.x;
    const int t = threadIdx.x;                  // 256 threads, one float4 each
    float4 o = ((const float4*)&g_out[row * DMODEL])[t];
    float s = o.x + o.y + o.z + o.w;
    float sq = o.x*o.x + o.y*o.y + o.z*o.z + o.w*o.w;
    float sum = block_sum(s);
    float sumsq = block_sum(sq);
    float mu = sum / DMODEL;
    float var = sumsq / DMODEL - mu * mu;
    float rs = rsqrtf(var + 1e-5f);
    float4 xr = ((const float4*)&x[row * DMODEL])[t];
    float4 w = ((const float4*)ln_w)[t];
    float4 bb = ((const float4*)ln_b)[t];
    float4 r;
    r.x = xr.x + (o.x - mu) * rs * w.x + bb.x;
    r.y = xr.y + (o.y - mu) * rs * w.y + bb.y;
    r.z = xr.z + (o.z - mu) * rs * w.z + bb.z;
    r.w = xr.w + (o.w - mu) * rs * w.w + bb.w;
    ((float4*)&out[row * DMODEL])[t] = r;
}

// ---------------- launch ----------------
extern "C" void kernel_launch(void* const* d_in, const int* in_sizes, int n_in,
                              void* d_out, int out_size) {
    const float* x          = (const float*)d_in[0];
    const float* in_proj_w  = (const float*)d_in[1];
    const float* conv_w     = (const float*)d_in[2];
    const float* conv_b     = (const float*)d_in[3];
    const float* dt_bias    = (const float*)d_in[4];
    const float* A_log      = (const float*)d_in[5];
    const float* D_skip     = (const float*)d_in[6];
    const float* norm_w     = (const float*)d_in[7];
    const float* out_proj_w = (const float*)d_in[8];
    const float* ln_w       = (const float*)d_in[9];
    const float* ln_b       = (const float*)d_in[10];
    float* out = (float*)d_out;

    (void)in_sizes; (void)n_in; (void)out_size;

    cudaFuncSetAttribute(k_chunk, cudaFuncAttributeMaxDynamicSharedMemorySize,
                         SMEM_CHUNK_FLOATS * (int)sizeof(float));
    cudaFuncSetAttribute(k_yo, cudaFuncAttributeMaxDynamicSharedMemorySize,
                         SMEM_YO_FLOATS * (int)sizeof(float));

    // 1) in_proj GEMM: [8192,1024] x [4384,1024]^T -> [8192,4384]
    k_gemm1<<<dim3((NIN + GBN - 1) / GBN, BL / GBM), 256>>>(x, in_proj_w);
    // 2) causal conv + SiLU
    k_conv<<<(int)(((long long)BL * CDIM + 255) / 256), 256>>>(conv_w, conv_b);
    // 3) dt
    k_dtk<<<(BL * NHEADS + 255) / 256, 256>>>(dt_bias);
    // 4) per-chunk intra work
    k_chunk<<<dim3(BATCH * NCH, NHEADS), 256,
              SMEM_CHUNK_FLOATS * sizeof(float)>>>(A_log);
    // 5) inter-chunk scan
    k_scan<<<BATCH * NHEADS, 256>>>();
    // 6) Yo + skip
    k_yo<<<dim3(BATCH * NCH, NHEADS), 256,
           SMEM_YO_FLOATS * sizeof(float)>>>(D_skip);
    // 7) gate + rmsnorm
    k_gate<<<BL, 256>>>(norm_w);
    // 8) out_proj GEMM: [8192,2048] x [1024,2048]^T -> [8192,1024]
    k_gemm2<<<dim3(DMODEL / GBN, BL / GBM), 256>>>(out_proj_w);
    // 9) LayerNorm + residual
    k_ln<<<BL, 256>>>(x, ln_w, ln_b, out);
}

// round 5
// speedup vs baseline: 1.7932x; 1.7932x over previous
#include <cuda_runtime.h>
#include <cuda_bf16.h>
#include <cstdint>

// ---------------- problem constants ----------------
#define BATCH  2
#define SEQ    4096
#define DMODEL 1024
#define DINNER 2048
#define DSTATE 128
#define NHEADS 32
#define HDIM   64
#define CDIM   2304        // DINNER + 2*DSTATE
#define NIN    4384        // 2*DINNER + 2*DSTATE + NHEADS
#define QC     64          // chunk length
#define NCH    64          // SEQ / QC
#define BL     8192        // BATCH * SEQ
#define DTMIN  0.001f
#define DTMAX  0.1f

// ---------------- scratch (device globals; no allocs allowed) ----------------
__device__ float g_zxbcdt[(size_t)BL * NIN];       // in_proj output
__device__ float g_xbc[(size_t)BL * CDIM];         // conv+silu output (x_ssm | B | C)
__device__ float g_dt[(size_t)BL * NHEADS];        // dt after sigmoid mapping
__device__ float g_Acum[(size_t)BATCH * NCH * NHEADS * QC];
__device__ float g_cdecay[(size_t)BATCH * NCH * NHEADS];
__device__ float g_states[(size_t)BATCH * NCH * NHEADS * HDIM * DSTATE];
__device__ float g_prevs [(size_t)BATCH * NCH * NHEADS * HDIM * DSTATE];
__device__ float g_Y[(size_t)BL * DINNER];         // Yd then += Yo + skip
__device__ float g_out[(size_t)BL * DMODEL];       // out_proj output (pre-LN)

// bf16 hi/lo splits for tensor-core GEMMs
__device__ __nv_bfloat16 g_x_hi[(size_t)BL * DMODEL];
__device__ __nv_bfloat16 g_x_lo[(size_t)BL * DMODEL];
__device__ __nv_bfloat16 g_w1_hi[(size_t)NIN * DMODEL];
__device__ __nv_bfloat16 g_w1_lo[(size_t)NIN * DMODEL];
__device__ __nv_bfloat16 g_y_hi[(size_t)BL * DINNER];
__device__ __nv_bfloat16 g_y_lo[(size_t)BL * DINNER];
__device__ __nv_bfloat16 g_w2_hi[(size_t)DMODEL * DINNER];
__device__ __nv_bfloat16 g_w2_lo[(size_t)DMODEL * DINNER];

// ---------------- helpers ----------------
__device__ __forceinline__ float block_sum(float v) {
    __shared__ float sh[32];
    __syncthreads();
    int lane = threadIdx.x & 31, wid = threadIdx.x >> 5;
    #pragma unroll
    for (int o = 16; o > 0; o >>= 1) v += __shfl_xor_sync(0xffffffffu, v, o);
    if (lane == 0) sh[wid] = v;
    __syncthreads();
    float r = (threadIdx.x < (blockDim.x >> 5)) ? sh[threadIdx.x] : 0.f;
    if (wid == 0) {
        #pragma unroll
        for (int o = 16; o > 0; o >>= 1) r += __shfl_xor_sync(0xffffffffu, r, o);
        if (lane == 0) sh[0] = r;
    }
    __syncthreads();
    return sh[0];
}

__device__ __forceinline__ float silu(float x) { return x / (1.f + __expf(-x)); }

__device__ __forceinline__ uint32_t smem_u32(const void* p) {
    uint32_t a;
    asm("{ .reg .u64 t; cvta.to.shared.u64 t, %1; cvt.u32.u64 %0, t; }" : "=r"(a) : "l"(p));
    return a;
}

// ---------------- portable async-copy / ldmatrix / mma wrappers (no 'a' features) ----
__device__ __forceinline__ void cp16(uint32_t dst, const void* src, bool pred) {
    int sz = pred ? 16 : 0;
    asm volatile("cp.async.cg.shared.global [%0], [%1], 16, %2;\n"
                 :: "r"(dst), "l"(src), "r"(sz) : "memory");
}
__device__ __forceinline__ void cp_commit() {
    asm volatile("cp.async.commit_group;" ::: "memory");
}
template <int N>
__device__ __forceinline__ void cp_wait() {
    asm volatile("cp.async.wait_group %0;" :: "n"(N) : "memory");
}
__device__ __forceinline__ void ldm_x4(uint32_t* r, uint32_t addr) {
    asm volatile("ldmatrix.sync.aligned.m8n8.x4.shared.b16 {%0,%1,%2,%3}, [%4];"
                 : "=r"(r[0]), "=r"(r[1]), "=r"(r[2]), "=r"(r[3]) : "r"(addr));
}
__device__ __forceinline__ void ldm_x2(uint32_t* r, uint32_t addr) {
    asm volatile("ldmatrix.sync.aligned.m8n8.x2.shared.b16 {%0,%1}, [%2];"
                 : "=r"(r[0]), "=r"(r[1]) : "r"(addr));
}
__device__ __forceinline__ void mma_bf16(float* d, const uint32_t* a, const uint32_t* b) {
    asm volatile("mma.sync.aligned.m16n8k16.row.col.f32.bf16.bf16.f32 "
                 "{%0,%1,%2,%3}, {%4,%5,%6,%7}, {%8,%9}, {%0,%1,%2,%3};"
                 : "+f"(d[0]), "+f"(d[1]), "+f"(d[2]), "+f"(d[3])
                 : "r"(a[0]), "r"(a[1]), "r"(a[2]), "r"(a[3]), "r"(b[0]), "r"(b[1]));
}

// ---------------- fp32 -> bf16 hi/lo split ----------------
__global__ void k_cvt(const float* __restrict__ in, __nv_bfloat16* __restrict__ hi,
                      __nv_bfloat16* __restrict__ lo, long long n4) {
    long long i = (long long)blockIdx.x * blockDim.x + threadIdx.x;
    if (i >= n4) return;
    float4 v = ((const float4*)in)[i];
    __nv_bfloat16 h0 = __float2bfloat16(v.x), h1 = __float2bfloat16(v.y);
    __nv_bfloat16 h2 = __float2bfloat16(v.z), h3 = __float2bfloat16(v.w);
    __nv_bfloat162 hp0, hp1, lp0, lp1;
    hp0.x = h0; hp0.y = h1; hp1.x = h2; hp1.y = h3;
    lp0.x = __float2bfloat16(v.x - __bfloat162float(h0));
    lp0.y = __float2bfloat16(v.y - __bfloat162float(h1));
    lp1.x = __float2bfloat16(v.z - __bfloat162float(h2));
    lp1.y = __float2bfloat16(v.w - __bfloat162float(h3));
    ((__nv_bfloat162*)hi)[i * 2 + 0] = hp0;
    ((__nv_bfloat162*)hi)[i * 2 + 1] = hp1;
    ((__nv_bfloat162*)lo)[i * 2 + 0] = lp0;
    ((__nv_bfloat162*)lo)[i * 2 + 1] = lp1;
}

// ---------------- HMMA GEMM: C[M,N] = A[M,K] * B[N,K]^T, 3-term bf16 split ----------------
// Block 128x128, BK=32, 256 threads (8 warps, 2x4 -> warp tile 64x32).
// smem per stage: Ah|Al|Bh|Bl, each 128 rows x 32 bf16 @ stride 40 (80B, conflict-free ldmatrix)
#define BKG   32
#define AS_STR 40
#define TILE_ELEMS (128 * AS_STR)          // 5120
#define OFF_AH 0
#define OFF_AL TILE_ELEMS
#define OFF_BH (2 * TILE_ELEMS)
#define OFF_BL (3 * TILE_ELEMS)
#define STAGE_ELEMS (4 * TILE_ELEMS)       // 20480
#define GEMM_SMEM_BYTES (2 * STAGE_ELEMS * 2)  // 81920

__device__ __forceinline__ void load_stage(
    const __nv_bfloat16* __restrict__ Ah, const __nv_bfloat16* __restrict__ Al,
    const __nv_bfloat16* __restrict__ Bh, const __nv_bfloat16* __restrict__ Bl,
    uint32_t smbase, int stage, int m0, int n0, int k0, int N, int K, int tid)
{
    uint32_t sb = smbase + (uint32_t)stage * (STAGE_ELEMS * 2);
    #pragma unroll
    for (int j = 0; j < 2; j++) {
        int c = tid + j * 256;             // 0..511
        int r = c >> 2, c16 = c & 3;
        uint32_t soff = (uint32_t)(r * AS_STR + c16 * 8) * 2;
        size_t gA = (size_t)(m0 + r) * K + k0 + c16 * 8;
        cp16(sb + OFF_AH * 2 + soff, Ah + gA, true);
        cp16(sb + OFF_AL * 2 + soff, Al + gA, true);
        bool ok = (n0 + r) < N;
        size_t gB = (size_t)(ok ? (n0 + r) : 0) * K + k0 + c16 * 8;
        cp16(sb + OFF_BH * 2 + soff, Bh + gB, ok);
        cp16(sb + OFF_BL * 2 + soff, Bl + gB, ok);
    }
}

__global__ void __launch_bounds__(256)
k_gemm_mma(const __nv_bfloat16* __restrict__ Ah, const __nv_bfloat16* __restrict__ Al,
           const __nv_bfloat16* __restrict__ Bh, const __nv_bfloat16* __restrict__ Bl,
           float* __restrict__ C, int M, int N, int K) {
    extern __shared__ __nv_bfloat16 smg[];
    const uint32_t smbase = smem_u32(smg);
    const int tid = threadIdx.x, wid = tid >> 5, lid = tid & 31;
    const int m0 = blockIdx.y * 128, n0 = blockIdx.x * 128;
    const int wm = (wid >> 2) * 64;        // warp m offset (0/64)
    const int wn = (wid & 3) * 32;         // warp n offset (0/32/64/96)
    const int l15 = lid & 15;

    float acc[4][4][4];
    #pragma unroll
    for (int mi = 0; mi < 4; mi++)
        #pragma unroll
        for (int ni = 0; ni < 4; ni++)
            #pragma unroll
            for (int k = 0; k < 4; k++) acc[mi][ni][k] = 0.f;

    // per-lane ldmatrix coordinates
    const int la_row = wm + (lid & 15);            // + mi*16
    const int la_col = (lid >> 4) * 8;             // + ks*16
    const int lb_row = wn + (l15 & 7);             // + ni*8
    const int lb_col = ((l15 >> 3) & 1) * 8;       // + ks*16

    const int NIT = K / BKG;
    load_stage(Ah, Al, Bh, Bl, smbase, 0, m0, n0, 0, N, K, tid);
    cp_commit();

    for (int it = 0; it < NIT; it++) {
        if (it + 1 < NIT) {
            load_stage(Ah, Al, Bh, Bl, smbase, (it + 1) & 1, m0, n0, (it + 1) * BKG, N, K, tid);
            cp_commit();
            cp_wait<1>();
        } else {
            cp_wait<0>();
        }
        __syncthreads();

        uint32_t sb = smbase + (uint32_t)(it & 1) * (STAGE_ELEMS * 2);
        #pragma unroll
        for (int ks = 0; ks < 2; ks++) {
            uint32_t af[4][4], bh4[4][2], bl4[4][2];
            #pragma unroll
            for (int mi = 0; mi < 4; mi++)
                ldm_x4(af[mi], sb + (uint32_t)(OFF_AH + (la_row + mi * 16) * AS_STR + ks * 16 + la_col) * 2);
            #pragma unroll
            for (int ni = 0; ni < 4; ni++) {
                uint32_t boff = (uint32_t)((lb_row + ni * 8) * AS_STR + ks * 16 + lb_col) * 2;
                ldm_x2(bh4[ni], sb + OFF_BH * 2 + boff);
                ldm_x2(bl4[ni], sb + OFF_BL * 2 + boff);
            }
            #pragma unroll
            for (int mi = 0; mi < 4; mi++)
                #pragma unroll
                for (int ni = 0; ni < 4; ni++)
                    mma_bf16(acc[mi][ni], af[mi], bh4[ni]);
            #pragma unroll
            for (int mi = 0; mi < 4; mi++)
                #pragma unroll
                for (int ni = 0; ni < 4; ni++)
                    mma_bf16(acc[mi][ni], af[mi], bl4[ni]);
            #pragma unroll
            for (int mi = 0; mi < 4; mi++)
                ldm_x4(af[mi], sb + (uint32_t)(OFF_AL + (la_row + mi * 16) * AS_STR + ks * 16 + la_col) * 2);
            #pragma unroll
            for (int mi = 0; mi < 4; mi++)
                #pragma unroll
                for (int ni = 0; ni < 4; ni++)
                    mma_bf16(acc[mi][ni], af[mi], bh4[ni]);
        }
        __syncthreads();
    }

    // epilogue: accum layout d0,d1 = (row g, col 2c, 2c+1); d2,d3 = (row g+8)
    const int r0 = m0 + wm + (lid >> 2);
    const int c0 = n0 + wn + (lid & 3) * 2;
    #pragma unroll
    for (int mi = 0; mi < 4; mi++) {
        #pragma unroll
        for (int ni = 0; ni < 4; ni++) {
            int col = c0 + ni * 8;
            if (col < N) {
                int row = r0 + mi * 16;
                *(float2*)&C[(size_t)row * N + col] = make_float2(acc[mi][ni][0], acc[mi][ni][1]);
                *(float2*)&C[(size_t)(row + 8) * N + col] = make_float2(acc[mi][ni][2], acc[mi][ni][3]);
            }
        }
    }
}

// ---------------- conv1d (K=4, causal) + bias + SiLU ----------------
__global__ void k_conv(const float* __restrict__ conv_w, const float* __restrict__ conv_b) {
    long long idx = (long long)blockIdx.x * blockDim.x + threadIdx.x;
    if (idx >= (long long)BL * CDIM) return;
    int ch = (int)(idx % CDIM);
    int bl = (int)(idx / CDIM);
    int l  = bl & (SEQ - 1);
    const float4 w = *(const float4*)&conv_w[ch * 4];
    float acc = conv_b[ch];
    float v0 = (l >= 3) ? g_zxbcdt[(long long)(bl - 3) * NIN + DINNER + ch] : 0.f;
    float v1 = (l >= 2) ? g_zxbcdt[(long long)(bl - 2) * NIN + DINNER + ch] : 0.f;
    float v2 = (l >= 1) ? g_zxbcdt[(long long)(bl - 1) * NIN + DINNER + ch] : 0.f;
    float v3 = g_zxbcdt[(long long)bl * NIN + DINNER + ch];
    acc += v0 * w.x + v1 * w.y + v2 * w.z + v3 * w.w;
    g_xbc[(long long)bl * CDIM + ch] = silu(acc);
}

// ---------------- dt ----------------
__global__ void k_dtk(const float* __restrict__ dt_bias) {
    int idx = blockIdx.x * blockDim.x + threadIdx.x;
    if (idx >= BL * NHEADS) return;
    int h = idx & (NHEADS - 1);
    int bl = idx / NHEADS;
    float raw = g_zxbcdt[(long long)bl * NIN + DINNER + CDIM + h] + dt_bias[h];
    float sg = 1.f / (1.f + __expf(-raw));
    g_dt[idx] = DTMIN + (DTMAX - DTMIN) * sg;
}

// ---------------- per-chunk: CB^T*Lmat, Yd, states, decay ----------------
#define BS_STR 129
#define XS_STR 65
#define SMEM_CHUNK_FLOATS (64*129 + 64*129 + 64*65 + 64*65 + 64 + 64 + 64)

__global__ void k_chunk(const float* __restrict__ A_log) {
    extern __shared__ float sm[];
    float* Bs   = sm;
    float* Cs   = Bs + 64 * BS_STR;
    float* xs   = Cs + 64 * BS_STR;
    float* CBL  = xs + 64 * XS_STR;
    float* dt_s = CBL + 64 * XS_STR;
    float* Ac_s = dt_s + 64;
    float* ws   = Ac_s + 64;

    const int tid = threadIdx.x;
    const int bc = blockIdx.x;
    const int h  = blockIdx.y;
    const int b  = bc / NCH, cc = bc % NCH;
    const long long base_bl = (long long)b * SEQ + (long long)cc * QC;

    #pragma unroll
    for (int it = 0; it < 8; it++) {
        int i4 = tid + it * 256;
        int q = i4 >> 5, n4 = (i4 & 31) * 4;
        float4 v = *(const float4*)&g_xbc[(base_bl + q) * CDIM + DINNER + n4];
        Bs[q * BS_STR + n4 + 0] = v.x; Bs[q * BS_STR + n4 + 1] = v.y;
        Bs[q * BS_STR + n4 + 2] = v.z; Bs[q * BS_STR + n4 + 3] = v.w;
        float4 u = *(const float4*)&g_xbc[(base_bl + q) * CDIM + DINNER + DSTATE + n4];
        Cs[q * BS_STR + n4 + 0] = u.x; Cs[q * BS_STR + n4 + 1] = u.y;
        Cs[q * BS_STR + n4 + 2] = u.z; Cs[q * BS_STR + n4 + 3] = u.w;
    }
    #pragma unroll
    for (int it = 0; it < 4; it++) {
        int i4 = tid + it * 256;
        int q = i4 >> 4, p4 = (i4 & 15) * 4;
        float4 v = *(const float4*)&g_xbc[(base_bl + q) * CDIM + h * HDIM + p4];
        xs[q * XS_STR + p4 + 0] = v.x; xs[q * XS_STR + p4 + 1] = v.y;
        xs[q * XS_STR + p4 + 2] = v.z; xs[q * XS_STR + p4 + 3] = v.w;
    }
    if (tid < QC) dt_s[tid] = g_dt[(base_bl + tid) * NHEADS + h];
    __syncthreads();

    if (tid == 0) {
        float Ah = -__expf(A_log[h]);
        float s = 0.f;
        for (int q = 0; q < QC; q++) { s += dt_s[q] * Ah; Ac_s[q] = s; }
    }
    __syncthreads();

    if (tid < QC) {
        float last = Ac_s[QC - 1];
        ws[tid] = __expf(last - Ac_s[tid]) * dt_s[tid];
        g_Acum[((long long)bc * NHEADS + h) * QC + tid] = Ac_s[tid];
        if (tid == 0) g_cdecay[(long long)bc * NHEADS + h] = __expf(last);
    }

    {
        const int tq0 = (tid >> 4) * 4;
        const int ts0 = (tid & 15) * 4;
        float acc[4][4];
        #pragma unroll
        for (int i = 0; i < 4; i++)
            #pragma unroll
            for (int j = 0; j < 4; j++) acc[i][j] = 0.f;
        for (int n = 0; n < DSTATE; n++) {
            float cq[4], bs[4];
            #pragma unroll
            for (int i = 0; i < 4; i++) cq[i] = Cs[(tq0 + i) * BS_STR + n];
            #pragma unroll
            for (int j = 0; j < 4; j++) bs[j] = Bs[(ts0 + j) * BS_STR + n];
            #pragma unroll
            for (int i = 0; i < 4; i++)
                #pragma unroll
                for (int j = 0; j < 4; j++)
                    acc[i][j] = fmaf(cq[i], bs[j], acc[i][j]);
        }
        #pragma unroll
        for (int i = 0; i < 4; i++) {
            int q = tq0 + i;
            #pragma unroll
            for (int j = 0; j < 4; j++) {
                int s = ts0 + j;
                float val = 0.f;
                if (s <= q) val = acc[i][j] * __expf(Ac_s[q] - Ac_s[s]) * dt_s[s];
                CBL[q * XS_STR + s] = val;
            }
        }
    }
    __syncthreads();

    {
        const int tq0 = (tid >> 4) * 4;
        const int tp0 = (tid & 15) * 4;
        float acc[4][4];
        #pragma unroll
        for (int i = 0; i < 4; i++)
            #pragma unroll
            for (int j = 0; j < 4; j++) acc[i][j] = 0.f;
        for (int s = 0; s < QC; s++) {
            float cb[4], xv[4];
            #pragma unroll
            for (int i = 0; i < 4; i++) cb[i] = CBL[(tq0 + i) * XS_STR + s];
            #pragma unroll
            for (int j = 0; j < 4; j++) xv[j] = xs[s * XS_STR + tp0 + j];
            #pragma unroll
            for (int i = 0; i < 4; i++)
                #pragma unroll
                for (int j = 0; j < 4; j++)
                    acc[i][j] = fmaf(cb[i], xv[j], acc[i][j]);
        }
        #pragma unroll
        for (int i = 0; i < 4; i++) {
            int q = tq0 + i;
            *(float4*)&g_Y[(base_bl + q) * DINNER + h * HDIM + tp0] =
                make_float4(acc[i][0], acc[i][1], acc[i][2], acc[i][3]);
        }
    }

    {
        const int tp0 = (tid >> 4) * 4;
        const int tn0 = (tid & 15) * 8;
        float acc[4][8];
        #pragma unroll
        for (int i = 0; i < 4; i++)
            #pragma unroll
            for (int j = 0; j < 8; j++) acc[i][j] = 0.f;
        for (int q = 0; q < QC; q++) {
            float wq = ws[q];
            float xv[4], bv[8];
            #pragma unroll
            for (int i = 0; i < 4; i++) xv[i] = xs[q * XS_STR + tp0 + i] * wq;
            #pragma unroll
            for (int j = 0; j < 8; j++) bv[j] = Bs[q * BS_STR + tn0 + j];
            #pragma unroll
            for (int i = 0; i < 4; i++)
                #pragma unroll
                for (int j = 0; j < 8; j++)
                    acc[i][j] = fmaf(xv[i], bv[j], acc[i][j]);
        }
        long long sbase = ((long long)bc * NHEADS + h) * HDIM * DSTATE;
        #pragma unroll
        for (int i = 0; i < 4; i++) {
            int p = tp0 + i;
            #pragma unroll
            for (int j = 0; j < 8; j += 4)
                *(float4*)&g_states[sbase + (long long)p * DSTATE + tn0 + j] =
                    make_float4(acc[i][j], acc[i][j+1], acc[i][j+2], acc[i][j+3]);
        }
    }
}

// ---------------- sequential inter-chunk scan ----------------
__global__ void k_scan() {
    int bh = blockIdx.x;
    int b = bh / NHEADS, h = bh % NHEADS;
    int tid = threadIdx.x;
    float carry[32];
    #pragma unroll
    for (int i = 0; i < 32; i++) carry[i] = 0.f;
    for (int c = 0; c < NCH; c++) {
        float dec = g_cdecay[((long long)b * NCH + c) * NHEADS + h];
        long long base = (((long long)b * NCH + c) * NHEADS + h) * (HDIM * DSTATE);
        #pragma unroll
        for (int i = 0; i < 32; i++) {
            int idx = tid + i * 256;
            float st = g_states[base + idx];
            g_prevs[base + idx] = carry[i];
            carry[i] = fmaf(dec, carry[i], st);
        }
    }
}

// ---------------- Yo + D_skip*x, accumulate into g_Y ----------------
#define SMEM_YO_FLOATS (64*129 + 64*129 + 64)
__global__ void k_yo(const float* __restrict__ D_skip) {
    extern __shared__ float sm[];
    float* Cs = sm;
    float* Pv = Cs + 64 * BS_STR;
    float* eA = Pv + 64 * BS_STR;

    const int tid = threadIdx.x;
    const int bc = blockIdx.x;
    const int h  = blockIdx.y;
    const int b  = bc / NCH, cc = bc % NCH;
    const long long base_bl = (long long)b * SEQ + (long long)cc * QC;
    const long long pbase = ((long long)bc * NHEADS + h) * (HDIM * DSTATE);

    #pragma unroll
    for (int it = 0; it < 8; it++) {
        int i4 = tid + it * 256;
        int r = i4 >> 5, n4 = (i4 & 31) * 4;
        float4 u = *(const float4*)&g_xbc[(base_bl + r) * CDIM + DINNER + DSTATE + n4];
        Cs[r * BS_STR + n4 + 0] = u.x; Cs[r * BS_STR + n4 + 1] = u.y;
        Cs[r * BS_STR + n4 + 2] = u.z; Cs[r * BS_STR + n4 + 3] = u.w;
        float4 v = *(const float4*)&g_prevs[pbase + (long long)r * DSTATE + n4];
        Pv[r * BS_STR + n4 + 0] = v.x; Pv[r * BS_STR + n4 + 1] = v.y;
        Pv[r * BS_STR + n4 + 2] = v.z; Pv[r * BS_STR + n4 + 3] = v.w;
    }
    if (tid < QC) eA[tid] = __expf(g_Acum[((long long)bc * NHEADS + h) * QC + tid]);
    __syncthreads();

    const float dsk = D_skip[h];
    const int tq0 = (tid >> 4) * 4;
    const int tp0 = (tid & 15) * 4;
    float acc[4][4];
    #pragma unroll
    for (int i = 0; i < 4; i++)
        #pragma unroll
        for (int j = 0; j < 4; j++) acc[i][j] = 0.f;
    for (int n = 0; n < DSTATE; n++) {
        float cq[4], pv[4];
        #pragma unroll
        for (int i = 0; i < 4; i++) cq[i] = Cs[(tq0 + i) * BS_STR + n];
        #pragma unroll
        for (int j = 0; j < 4; j++) pv[j] = Pv[(tp0 + j) * BS_STR + n];
        #pragma unroll
        for (int i = 0; i < 4; i++)
            #pragma unroll
            for (int j = 0; j < 4; j++)
                acc[i][j] = fmaf(cq[i], pv[j], acc[i][j]);
    }
    #pragma unroll
    for (int i = 0; i < 4; i++) {
        int q = tq0 + i;
        long long row = base_bl + q;
        float4 yv = *(float4*)&g_Y[row * DINNER + h * HDIM + tp0];
        float4 xv = *(const float4*)&g_xbc[row * CDIM + h * HDIM + tp0];
        float e = eA[q];
        yv.x += e * acc[i][0] + dsk * xv.x;
        yv.y += e * acc[i][1] + dsk * xv.y;
        yv.z += e * acc[i][2] + dsk * xv.z;
        yv.w += e * acc[i][3] + dsk * xv.w;
        *(float4*)&g_Y[row * DINNER + h * HDIM + tp0] = yv;
    }
}

// ---------------- gate with silu(z) + RMSNorm, emit bf16 hi/lo for gemm2 ----------------
__global__ void k_gate(const float* __restrict__ norm_w) {
    __shared__ float sv[DINNER];
    const long long row = blockIdx.x;
    float local = 0.f;
    for (int i = threadIdx.x; i < DINNER; i += blockDim.x) {
        float yv = g_Y[row * DINNER + i];
        float zv = g_zxbcdt[row * NIN + i];
        float v = yv * silu(zv);
        sv[i] = v;
        local += v * v;
    }
    float tot = block_sum(local);
    float scale = rsqrtf(tot / DINNER + 1e-5f);
    for (int i = threadIdx.x; i < DINNER; i += blockDim.x) {
        float v = sv[i] * scale * norm_w[i];
        __nv_bfloat16 h = __float2bfloat16(v);
        g_y_hi[row * DINNER + i] = h;
        g_y_lo[row * DINNER + i] = __float2bfloat16(v - __bfloat162float(h));
    }
}

// ---------------- final LayerNorm + residual ----------------
__global__ void k_ln(const float* __restrict__ x, const float* __restrict__ ln_w,
                     const float* __restrict__ ln_b, float* __restrict__ out) {
    const long long row = blockIdx.x;
    const int t = threadIdx.x;
    float4 o = ((const float4*)&g_out[row * DMODEL])[t];
    float s = o.x + o.y + o.z + o.w;
    float sq = o.x*o.x + o.y*o.y + o.z*o.z + o.w*o.w;
    float sum = block_sum(s);
    float sumsq = block_sum(sq);
    float mu = sum / DMODEL;
    float var = sumsq / DMODEL - mu * mu;
    float rs = rsqrtf(var + 1e-5f);
    float4 xr = ((const float4*)&x[row * DMODEL])[t];
    float4 w = ((const float4*)ln_w)[t];
    float4 bb = ((const float4*)ln_b)[t];
    float4 r;
    r.x = xr.x + (o.x - mu) * rs * w.x + bb.x;
    r.y = xr.y + (o.y - mu) * rs * w.y + bb.y;
    r.z = xr.z + (o.z - mu) * rs * w.z + bb.z;
    r.w = xr.w + (o.w - mu) * rs * w.w + bb.w;
    ((float4*)&out[row * DMODEL])[t] = r;
}

// ---------------- launch ----------------
extern "C" void kernel_launch(void* const* d_in, const int* in_sizes, int n_in,
                              void* d_out, int out_size) {
    const float* x          = (const float*)d_in[0];
    const float* in_proj_w  = (const float*)d_in[1];
    const float* conv_w     = (const float*)d_in[2];
    const float* conv_b     = (const float*)d_in[3];
    const float* dt_bias    = (const float*)d_in[4];
    const float* A_log      = (const float*)d_in[5];
    const float* D_skip     = (const float*)d_in[6];
    const float* norm_w     = (const float*)d_in[7];
    const float* out_proj_w = (const float*)d_in[8];
    const float* ln_w       = (const float*)d_in[9];
    const float* ln_b       = (const float*)d_in[10];
    float* out = (float*)d_out;
    (void)in_sizes; (void)n_in; (void)out_size;

    cudaFuncSetAttribute(k_chunk, cudaFuncAttributeMaxDynamicSharedMemorySize,
                         SMEM_CHUNK_FLOATS * (int)sizeof(float));
    cudaFuncSetAttribute(k_yo, cudaFuncAttributeMaxDynamicSharedMemorySize,
                         SMEM_YO_FLOATS * (int)sizeof(float));
    cudaFuncSetAttribute(k_gemm_mma, cudaFuncAttributeMaxDynamicSharedMemorySize,
                         GEMM_SMEM_BYTES);

    __nv_bfloat16 *xh, *xl, *w1h, *w1l, *yh, *yl, *w2h, *w2l;
    float *zx, *go;
    cudaGetSymbolAddress((void**)&xh,  g_x_hi);  cudaGetSymbolAddress((void**)&xl,  g_x_lo);
    cudaGetSymbolAddress((void**)&w1h, g_w1_hi); cudaGetSymbolAddress((void**)&w1l, g_w1_lo);
    cudaGetSymbolAddress((void**)&yh,  g_y_hi);  cudaGetSymbolAddress((void**)&yl,  g_y_lo);
    cudaGetSymbolAddress((void**)&w2h, g_w2_hi); cudaGetSymbolAddress((void**)&w2l, g_w2_lo);
    cudaGetSymbolAddress((void**)&zx,  g_zxbcdt); cudaGetSymbolAddress((void**)&go, g_out);

    // 0) bf16 hi/lo conversions
    k_cvt<<<(int)(((long long)BL * DMODEL / 4 + 255) / 256), 256>>>(x, xh, xl, (long long)BL * DMODEL / 4);
    k_cvt<<<(int)(((long long)NIN * DMODEL / 4 + 255) / 256), 256>>>(in_proj_w, w1h, w1l, (long long)NIN * DMODEL / 4);
    k_cvt<<<(int)(((long long)DMODEL * DINNER / 4 + 255) / 256), 256>>>(out_proj_w, w2h, w2l, (long long)DMODEL * DINNER / 4);

    // 1) in_proj GEMM (HMMA): [8192,1024] x [4384,1024]^T
    k_gemm_mma<<<dim3((NIN + 127) / 128, BL / 128), 256, GEMM_SMEM_BYTES>>>(
        xh, xl, w1h, w1l, zx, BL, NIN, DMODEL);
    // 2) causal conv + SiLU
    k_conv<<<(int)(((long long)BL * CDIM + 255) / 256), 256>>>(conv_w, conv_b);
    // 3) dt
    k_dtk<<<(BL * NHEADS + 255) / 256, 256>>>(dt_bias);
    // 4) per-chunk intra work
    k_chunk<<<dim3(BATCH * NCH, NHEADS), 256, SMEM_CHUNK_FLOATS * sizeof(float)>>>(A_log);
    // 5) inter-chunk scan
    k_scan<<<BATCH * NHEADS, 256>>>();
    // 6) Yo + skip
    k_yo<<<dim3(BATCH * NCH, NHEADS), 256, SMEM_YO_FLOATS * sizeof(float)>>>(D_skip);
    // 7) gate + rmsnorm (emits bf16 hi/lo)
    k_gate<<<BL, 256>>>(norm_w);
    // 8) out_proj GEMM (HMMA): [8192,2048] x [1024,2048]^T
    k_gemm_mma<<<dim3(DMODEL / 128, BL / 128), 256, GEMM_SMEM_BYTES>>>(
        yh, yl, w2h, w2l, go, BL, DMODEL, DINNER);
    // 9) LayerNorm + residual
    k_ln<<<BL, 256>>>(x, ln_w, ln_b, out);
}

// round 8
// speedup vs baseline: 1.8001x; 1.0038x over previous
#include <cuda_runtime.h>
#include <cuda_bf16.h>
#include <cstdint>

// ---------------- problem constants ----------------
#define BATCH  2
#define SEQ    4096
#define DMODEL 1024
#define DINNER 2048
#define DSTATE 128
#define NHEADS 32
#define HDIM   64
#define CDIM   2304        // DINNER + 2*DSTATE
#define NIN    4384        // 2*DINNER + 2*DSTATE + NHEADS
#define QC     64          // chunk length
#define NCH    64          // SEQ / QC
#define BL     8192        // BATCH * SEQ
#define DTMIN  0.001f
#define DTMAX  0.1f

// ---------------- scratch (device globals; no allocs allowed) ----------------
__device__ float g_zxbcdt[(size_t)BL * NIN];       // in_proj output
__device__ float g_xbc[(size_t)BL * CDIM];         // conv+silu output (x_ssm | B | C)
__device__ float g_dt[(size_t)BL * NHEADS];        // dt after sigmoid mapping
__device__ float g_Acum[(size_t)BATCH * NCH * NHEADS * QC];
__device__ float g_cdecay[(size_t)BATCH * NCH * NHEADS];
__device__ float g_states[(size_t)BATCH * NCH * NHEADS * HDIM * DSTATE];
__device__ float g_prevs [(size_t)BATCH * NCH * NHEADS * HDIM * DSTATE];
__device__ float g_Y[(size_t)BL * DINNER];         // Yd then += Yo + skip
__device__ float g_out[(size_t)BL * DMODEL];       // out_proj output (pre-LN)

// bf16 hi/lo splits for tensor-core GEMMs
__device__ __nv_bfloat16 g_x_hi[(size_t)BL * DMODEL];
__device__ __nv_bfloat16 g_x_lo[(size_t)BL * DMODEL];
__device__ __nv_bfloat16 g_w1_hi[(size_t)NIN * DMODEL];
__device__ __nv_bfloat16 g_w1_lo[(size_t)NIN * DMODEL];
__device__ __nv_bfloat16 g_y_hi[(size_t)BL * DINNER];
__device__ __nv_bfloat16 g_y_lo[(size_t)BL * DINNER];
__device__ __nv_bfloat16 g_w2_hi[(size_t)DMODEL * DINNER];
__device__ __nv_bfloat16 g_w2_lo[(size_t)DMODEL * DINNER];

// ---------------- helpers ----------------
__device__ __forceinline__ float block_sum(float v) {
    __shared__ float sh[32];
    __syncthreads();
    int lane = threadIdx.x & 31, wid = threadIdx.x >> 5;
    #pragma unroll
    for (int o = 16; o > 0; o >>= 1) v += __shfl_xor_sync(0xffffffffu, v, o);
    if (lane == 0) sh[wid] = v;
    __syncthreads();
    float r = (threadIdx.x < (blockDim.x >> 5)) ? sh[threadIdx.x] : 0.f;
    if (wid == 0) {
        #pragma unroll
        for (int o = 16; o > 0; o >>= 1) r += __shfl_xor_sync(0xffffffffu, r, o);
        if (lane == 0) sh[0] = r;
    }
    __syncthreads();
    return sh[0];
}

__device__ __forceinline__ float silu(float x) { return x / (1.f + __expf(-x)); }

__device__ __forceinline__ uint32_t smem_u32(const void* p) {
    uint32_t a;
    asm("{ .reg .u64 t; cvta.to.shared.u64 t, %1; cvt.u32.u64 %0, t; }" : "=r"(a) : "l"(p));
    return a;
}

// ---------------- portable async-copy / ldmatrix / mma wrappers ----------------
__device__ __forceinline__ void cp16(uint32_t dst, const void* src, bool pred) {
    int sz = pred ? 16 : 0;
    asm volatile("cp.async.cg.shared.global [%0], [%1], 16, %2;\n"
                 :: "r"(dst), "l"(src), "r"(sz) : "memory");
}
__device__ __forceinline__ void cp_commit() {
    asm volatile("cp.async.commit_group;" ::: "memory");
}
template <int N>
__device__ __forceinline__ void cp_wait() {
    asm volatile("cp.async.wait_group %0;" :: "n"(N) : "memory");
}
__device__ __forceinline__ void ldm_x4(uint32_t* r, uint32_t addr) {
    asm volatile("ldmatrix.sync.aligned.m8n8.x4.shared.b16 {%0,%1,%2,%3}, [%4];"
                 : "=r"(r[0]), "=r"(r[1]), "=r"(r[2]), "=r"(r[3]) : "r"(addr));
}
__device__ __forceinline__ void ldm_x2(uint32_t* r, uint32_t addr) {
    asm volatile("ldmatrix.sync.aligned.m8n8.x2.shared.b16 {%0,%1}, [%2];"
                 : "=r"(r[0]), "=r"(r[1]) : "r"(addr));
}
__device__ __forceinline__ void mma_bf16(float* d, const uint32_t* a, const uint32_t* b) {
    asm volatile("mma.sync.aligned.m16n8k16.row.col.f32.bf16.bf16.f32 "
                 "{%0,%1,%2,%3}, {%4,%5,%6,%7}, {%8,%9}, {%0,%1,%2,%3};"
                 : "+f"(d[0]), "+f"(d[1]), "+f"(d[2]), "+f"(d[3])
                 : "r"(a[0]), "r"(a[1]), "r"(a[2]), "r"(a[3]), "r"(b[0]), "r"(b[1]));
}

// ---------------- fp32 -> bf16 hi/lo split ----------------
__global__ void k_cvt(const float* __restrict__ in, __nv_bfloat16* __restrict__ hi,
                      __nv_bfloat16* __restrict__ lo, long long n4) {
    long long i = (long long)blockIdx.x * blockDim.x + threadIdx.x;
    if (i >= n4) return;
    float4 v = ((const float4*)in)[i];
    __nv_bfloat16 h0 = __float2bfloat16(v.x), h1 = __float2bfloat16(v.y);
    __nv_bfloat16 h2 = __float2bfloat16(v.z), h3 = __float2bfloat16(v.w);
    __nv_bfloat162 hp0, hp1, lp0, lp1;
    hp0.x = h0; hp0.y = h1; hp1.x = h2; hp1.y = h3;
    lp0.x = __float2bfloat16(v.x - __bfloat162float(h0));
    lp0.y = __float2bfloat16(v.y - __bfloat162float(h1));
    lp1.x = __float2bfloat16(v.z - __bfloat162float(h2));
    lp1.y = __float2bfloat16(v.w - __bfloat162float(h3));
    ((__nv_bfloat162*)hi)[i * 2 + 0] = hp0;
    ((__nv_bfloat162*)hi)[i * 2 + 1] = hp1;
    ((__nv_bfloat162*)lo)[i * 2 + 0] = lp0;
    ((__nv_bfloat162*)lo)[i * 2 + 1] = lp1;
}

// ---------------- HMMA GEMM: C[M,N] = A[M,K] * B[N,K]^T, 3-term bf16 split ----------------
#define BKG   32
#define AS_STR 40
#define TILE_ELEMS (128 * AS_STR)          // 5120
#define OFF_AH 0
#define OFF_AL TILE_ELEMS
#define OFF_BH (2 * TILE_ELEMS)
#define OFF_BL (3 * TILE_ELEMS)
#define STAGE_ELEMS (4 * TILE_ELEMS)       // 20480
#define GEMM_SMEM_BYTES (2 * STAGE_ELEMS * 2)  // 81920

__device__ __forceinline__ void load_stage(
    const __nv_bfloat16* __restrict__ Ah, const __nv_bfloat16* __restrict__ Al,
    const __nv_bfloat16* __restrict__ Bh, const __nv_bfloat16* __restrict__ Bl,
    uint32_t smbase, int stage, int m0, int n0, int k0, int N, int K, int tid)
{
    uint32_t sb = smbase + (uint32_t)stage * (STAGE_ELEMS * 2);
    #pragma unroll
    for (int j = 0; j < 2; j++) {
        int c = tid + j * 256;             // 0..511
        int r = c >> 2, c16 = c & 3;
        uint32_t soff = (uint32_t)(r * AS_STR + c16 * 8) * 2;
        size_t gA = (size_t)(m0 + r) * K + k0 + c16 * 8;
        cp16(sb + OFF_AH * 2 + soff, Ah + gA, true);
        cp16(sb + OFF_AL * 2 + soff, Al + gA, true);
        bool ok = (n0 + r) < N;
        size_t gB = (size_t)(ok ? (n0 + r) : 0) * K + k0 + c16 * 8;
        cp16(sb + OFF_BH * 2 + soff, Bh + gB, ok);
        cp16(sb + OFF_BL * 2 + soff, Bl + gB, ok);
    }
}

__global__ void __launch_bounds__(256, 2)
k_gemm_mma(const __nv_bfloat16* __restrict__ Ah, const __nv_bfloat16* __restrict__ Al,
           const __nv_bfloat16* __restrict__ Bh, const __nv_bfloat16* __restrict__ Bl,
           float* __restrict__ C, int M, int N, int K) {
    extern __shared__ __nv_bfloat16 smg[];
    const uint32_t smbase = smem_u32(smg);
    const int tid = threadIdx.x, wid = tid >> 5, lid = tid & 31;
    const int m0 = blockIdx.y * 128, n0 = blockIdx.x * 128;
    const int wm = (wid >> 2) * 64;        // warp m offset (0/64)
    const int wn = (wid & 3) * 32;         // warp n offset (0/32/64/96)
    const int l15 = lid & 15;

    float acc[4][4][4];
    #pragma unroll
    for (int mi = 0; mi < 4; mi++)
        #pragma unroll
        for (int ni = 0; ni < 4; ni++)
            #pragma unroll
            for (int k = 0; k < 4; k++) acc[mi][ni][k] = 0.f;

    const int la_row = wm + (lid & 15);
    const int la_col = (lid >> 4) * 8;
    const int lb_row = wn + (l15 & 7);
    const int lb_col = ((l15 >> 3) & 1) * 8;

    const int NIT = K / BKG;
    load_stage(Ah, Al, Bh, Bl, smbase, 0, m0, n0, 0, N, K, tid);
    cp_commit();

    for (int it = 0; it < NIT; it++) {
        if (it + 1 < NIT) {
            load_stage(Ah, Al, Bh, Bl, smbase, (it + 1) & 1, m0, n0, (it + 1) * BKG, N, K, tid);
            cp_commit();
            cp_wait<1>();
        } else {
            cp_wait<0>();
        }
        __syncthreads();

        uint32_t sb = smbase + (uint32_t)(it & 1) * (STAGE_ELEMS * 2);
        #pragma unroll
        for (int ks = 0; ks < 2; ks++) {
            uint32_t af[4][4], bh4[4][2], bl4[4][2];
            #pragma unroll
            for (int mi = 0; mi < 4; mi++)
                ldm_x4(af[mi], sb + (uint32_t)(OFF_AH + (la_row + mi * 16) * AS_STR + ks * 16 + la_col) * 2);
            #pragma unroll
            for (int ni = 0; ni < 4; ni++) {
                uint32_t boff = (uint32_t)((lb_row + ni * 8) * AS_STR + ks * 16 + lb_col) * 2;
                ldm_x2(bh4[ni], sb + OFF_BH * 2 + boff);
                ldm_x2(bl4[ni], sb + OFF_BL * 2 + boff);
            }
            #pragma unroll
            for (int mi = 0; mi < 4; mi++)
                #pragma unroll
                for (int ni = 0; ni < 4; ni++)
                    mma_bf16(acc[mi][ni], af[mi], bh4[ni]);
            #pragma unroll
            for (int mi = 0; mi < 4; mi++)
                #pragma unroll
                for (int ni = 0; ni < 4; ni++)
                    mma_bf16(acc[mi][ni], af[mi], bl4[ni]);
            #pragma unroll
            for (int mi = 0; mi < 4; mi++)
                ldm_x4(af[mi], sb + (uint32_t)(OFF_AL + (la_row + mi * 16) * AS_STR + ks * 16 + la_col) * 2);
            #pragma unroll
            for (int mi = 0; mi < 4; mi++)
                #pragma unroll
                for (int ni = 0; ni < 4; ni++)
                    mma_bf16(acc[mi][ni], af[mi], bh4[ni]);
        }
        __syncthreads();
    }

    const int r0 = m0 + wm + (lid >> 2);
    const int c0 = n0 + wn + (lid & 3) * 2;
    #pragma unroll
    for (int mi = 0; mi < 4; mi++) {
        #pragma unroll
        for (int ni = 0; ni < 4; ni++) {
            int col = c0 + ni * 8;
            if (col < N) {
                int row = r0 + mi * 16;
                *(float2*)&C[(size_t)row * N + col] = make_float2(acc[mi][ni][0], acc[mi][ni][1]);
                *(float2*)&C[(size_t)(row + 8) * N + col] = make_float2(acc[mi][ni][2], acc[mi][ni][3]);
            }
        }
    }
}

// ---------------- conv1d (K=4, causal) + bias + SiLU ----------------
__global__ void k_conv(const float* __restrict__ conv_w, const float* __restrict__ conv_b) {
    long long idx = (long long)blockIdx.x * blockDim.x + threadIdx.x;
    if (idx >= (long long)BL * CDIM) return;
    int ch = (int)(idx % CDIM);
    int bl = (int)(idx / CDIM);
    int l  = bl & (SEQ - 1);
    const float4 w = *(const float4*)&conv_w[ch * 4];
    float acc = conv_b[ch];
    float v0 = (l >= 3) ? g_zxbcdt[(long long)(bl - 3) * NIN + DINNER + ch] : 0.f;
    float v1 = (l >= 2) ? g_zxbcdt[(long long)(bl - 2) * NIN + DINNER + ch] : 0.f;
    float v2 = (l >= 1) ? g_zxbcdt[(long long)(bl - 1) * NIN + DINNER + ch] : 0.f;
    float v3 = g_zxbcdt[(long long)bl * NIN + DINNER + ch];
    acc += v0 * w.x + v1 * w.y + v2 * w.z + v3 * w.w;
    g_xbc[(long long)bl * CDIM + ch] = silu(acc);
}

// ---------------- dt ----------------
__global__ void k_dtk(const float* __restrict__ dt_bias) {
    int idx = blockIdx.x * blockDim.x + threadIdx.x;
    if (idx >= BL * NHEADS) return;
    int h = idx & (NHEADS - 1);
    int bl = idx / NHEADS;
    float raw = g_zxbcdt[(long long)bl * NIN + DINNER + CDIM + h] + dt_bias[h];
    float sg = 1.f / (1.f + __expf(-raw));
    g_dt[idx] = DTMIN + (DTMAX - DTMIN) * sg;
}

// ---------------- per-chunk: CB^T*Lmat, Yd, states, decay ----------------
// padded strides, multiples of 4 for float4 LDS
#define BS_STR 132
#define XS_STR 68
#define SMEM_CHUNK_FLOATS (64*BS_STR*2 + 64*XS_STR*2 + 64*3)

__global__ void k_chunk(const float* __restrict__ A_log) {
    extern __shared__ float sm[];
    float* Bs   = sm;
    float* Cs   = Bs + 64 * BS_STR;
    float* xs   = Cs + 64 * BS_STR;
    float* CBL  = xs + 64 * XS_STR;
    float* dt_s = CBL + 64 * XS_STR;
    float* Ac_s = dt_s + 64;
    float* ws   = Ac_s + 64;

    const int tid = threadIdx.x;
    const int bc = blockIdx.x;
    const int h  = blockIdx.y;
    const int b  = bc / NCH, cc = bc % NCH;
    const long long base_bl = (long long)b * SEQ + (long long)cc * QC;

    #pragma unroll
    for (int it = 0; it < 8; it++) {
        int i4 = tid + it * 256;
        int q = i4 >> 5, n4 = (i4 & 31) * 4;
        *(float4*)&Bs[q * BS_STR + n4] = *(const float4*)&g_xbc[(base_bl + q) * CDIM + DINNER + n4];
        *(float4*)&Cs[q * BS_STR + n4] = *(const float4*)&g_xbc[(base_bl + q) * CDIM + DINNER + DSTATE + n4];
    }
    #pragma unroll
    for (int it = 0; it < 4; it++) {
        int i4 = tid + it * 256;
        int q = i4 >> 4, p4 = (i4 & 15) * 4;
        *(float4*)&xs[q * XS_STR + p4] = *(const float4*)&g_xbc[(base_bl + q) * CDIM + h * HDIM + p4];
    }
    if (tid < QC) dt_s[tid] = g_dt[(base_bl + tid) * NHEADS + h];
    __syncthreads();

    if (tid == 0) {
        float Ah = -__expf(A_log[h]);
        float s = 0.f;
        for (int q = 0; q < QC; q++) { s += dt_s[q] * Ah; Ac_s[q] = s; }
    }
    __syncthreads();

    if (tid < QC) {
        float last = Ac_s[QC - 1];
        ws[tid] = __expf(last - Ac_s[tid]) * dt_s[tid];
        g_Acum[((long long)bc * NHEADS + h) * QC + tid] = Ac_s[tid];
        if (tid == 0) g_cdecay[(long long)bc * NHEADS + h] = __expf(last);
    }

    // ---- CBL[q][s] = (C_q . B_s) * exp(Acum_q - Acum_s) * dt_s   (s<=q else 0)
    {
        const int tq0 = (tid >> 4) * 4;
        const int ts0 = (tid & 15) * 4;
        float acc[4][4];
        #pragma unroll
        for (int i = 0; i < 4; i++)
            #pragma unroll
            for (int j = 0; j < 4; j++) acc[i][j] = 0.f;
        #pragma unroll 4
        for (int n = 0; n < DSTATE; n += 4) {
            float4 cq[4], bs[4];
            #pragma unroll
            for (int i = 0; i < 4; i++) cq[i] = *(const float4*)&Cs[(tq0 + i) * BS_STR + n];
            #pragma unroll
            for (int j = 0; j < 4; j++) bs[j] = *(const float4*)&Bs[(ts0 + j) * BS_STR + n];
            #pragma unroll
            for (int i = 0; i < 4; i++)
                #pragma unroll
                for (int j = 0; j < 4; j++) {
                    acc[i][j] = fmaf(cq[i].x, bs[j].x, acc[i][j]);
                    acc[i][j] = fmaf(cq[i].y, bs[j].y, acc[i][j]);
                    acc[i][j] = fmaf(cq[i].z, bs[j].z, acc[i][j]);
                    acc[i][j] = fmaf(cq[i].w, bs[j].w, acc[i][j]);
                }
        }
        #pragma unroll
        for (int i = 0; i < 4; i++) {
            int q = tq0 + i;
            #pragma unroll
            for (int j = 0; j < 4; j++) {
                int s = ts0 + j;
                float val = 0.f;
                if (s <= q) val = acc[i][j] * __expf(Ac_s[q] - Ac_s[s]) * dt_s[s];
                CBL[q * XS_STR + s] = val;
            }
        }
    }
    __syncthreads();

    // ---- Yd[q][p] = sum_s CBL[q][s] * xs[s][p]
    {
        const int tq0 = (tid >> 4) * 4;
        const int tp0 = (tid & 15) * 4;
        float acc[4][4];
        #pragma unroll
        for (int i = 0; i < 4; i++)
            #pragma unroll
            for (int j = 0; j < 4; j++) acc[i][j] = 0.f;
        #pragma unroll 4
        for (int s = 0; s < QC; s += 4) {
            float4 cb[4];
            float4 xv[4];
            #pragma unroll
            for (int i = 0; i < 4; i++) cb[i] = *(const float4*)&CBL[(tq0 + i) * XS_STR + s];
            #pragma unroll
            for (int ss = 0; ss < 4; ss++) xv[ss] = *(const float4*)&xs[(s + ss) * XS_STR + tp0];
            #pragma unroll
            for (int i = 0; i < 4; i++) {
                acc[i][0] = fmaf(cb[i].x, xv[0].x, acc[i][0]);
                acc[i][1] = fmaf(cb[i].x, xv[0].y, acc[i][1]);
                acc[i][2] = fmaf(cb[i].x, xv[0].z, acc[i][2]);
                acc[i][3] = fmaf(cb[i].x, xv[0].w, acc[i][3]);
                acc[i][0] = fmaf(cb[i].y, xv[1].x, acc[i][0]);
                acc[i][1] = fmaf(cb[i].y, xv[1].y, acc[i][1]);
                acc[i][2] = fmaf(cb[i].y, xv[1].z, acc[i][2]);
                acc[i][3] = fmaf(cb[i].y, xv[1].w, acc[i][3]);
                acc[i][0] = fmaf(cb[i].z, xv[2].x, acc[i][0]);
                acc[i][1] = fmaf(cb[i].z, xv[2].y, acc[i][1]);
                acc[i][2] = fmaf(cb[i].z, xv[2].z, acc[i][2]);
                acc[i][3] = fmaf(cb[i].z, xv[2].w, acc[i][3]);
                acc[i][0] = fmaf(cb[i].w, xv[3].x, acc[i][0]);
                acc[i][1] = fmaf(cb[i].w, xv[3].y, acc[i][1]);
                acc[i][2] = fmaf(cb[i].w, xv[3].z, acc[i][2]);
                acc[i][3] = fmaf(cb[i].w, xv[3].w, acc[i][3]);
            }
        }
        #pragma unroll
        for (int i = 0; i < 4; i++) {
            int q = tq0 + i;
            *(float4*)&g_Y[(base_bl + q) * DINNER + h * HDIM + tp0] =
                make_float4(acc[i][0], acc[i][1], acc[i][2], acc[i][3]);
        }
    }

    // ---- states[p][n] = sum_q (B[q][n]*ws[q]) * xs[q][p]
    {
        const int tp0 = (tid >> 4) * 4;
        const int tn0 = (tid & 15) * 8;
        float acc[4][8];
        #pragma unroll
        for (int i = 0; i < 4; i++)
            #pragma unroll
            for (int j = 0; j < 8; j++) acc[i][j] = 0.f;
        #pragma unroll 4
        for (int q = 0; q < QC; q++) {
            float wq = ws[q];
            float4 xv = *(const float4*)&xs[q * XS_STR + tp0];
            float4 bv0 = *(const float4*)&Bs[q * BS_STR + tn0];
            float4 bv1 = *(const float4*)&Bs[q * BS_STR + tn0 + 4];
            float xw[4] = { xv.x * wq, xv.y * wq, xv.z * wq, xv.w * wq };
            float bb[8] = { bv0.x, bv0.y, bv0.z, bv0.w, bv1.x, bv1.y, bv1.z, bv1.w };
            #pragma unroll
            for (int i = 0; i < 4; i++)
                #pragma unroll
                for (int j = 0; j < 8; j++)
                    acc[i][j] = fmaf(xw[i], bb[j], acc[i][j]);
        }
        long long sbase = ((long long)bc * NHEADS + h) * HDIM * DSTATE;
        #pragma unroll
        for (int i = 0; i < 4; i++) {
            int p = tp0 + i;
            #pragma unroll
            for (int j = 0; j < 8; j += 4)
                *(float4*)&g_states[sbase + (long long)p * DSTATE + tn0 + j] =
                    make_float4(acc[i][j], acc[i][j+1], acc[i][j+2], acc[i][j+3]);
        }
    }
}

// ---------------- sequential inter-chunk scan ----------------
__global__ void k_scan() {
    int bh = blockIdx.x;
    int b = bh / NHEADS, h = bh % NHEADS;
    int tid = threadIdx.x;
    float carry[32];
    #pragma unroll
    for (int i = 0; i < 32; i++) carry[i] = 0.f;
    for (int c = 0; c < NCH; c++) {
        float dec = g_cdecay[((long long)b * NCH + c) * NHEADS + h];
        long long base = (((long long)b * NCH + c) * NHEADS + h) * (HDIM * DSTATE);
        #pragma unroll
        for (int i = 0; i < 32; i++) {
            int idx = tid + i * 256;
            float st = g_states[base + idx];
            g_prevs[base + idx] = carry[i];
            carry[i] = fmaf(dec, carry[i], st);
        }
    }
}

// ---------------- Yo + D_skip*x, accumulate into g_Y ----------------
#define SMEM_YO_FLOATS (64*BS_STR*2 + 64)
__global__ void k_yo(const float* __restrict__ D_skip) {
    extern __shared__ float sm[];
    float* Cs = sm;
    float* Pv = Cs + 64 * BS_STR;
    float* eA = Pv + 64 * BS_STR;

    const int tid = threadIdx.x;
    const int bc = blockIdx.x;
    const int h  = blockIdx.y;
    const int b  = bc / NCH, cc = bc % NCH;
    const long long base_bl = (long long)b * SEQ + (long long)cc * QC;
    const long long pbase = ((long long)bc * NHEADS + h) * (HDIM * DSTATE);

    #pragma unroll
    for (int it = 0; it < 8; it++) {
        int i4 = tid + it * 256;
        int r = i4 >> 5, n4 = (i4 & 31) * 4;
        *(float4*)&Cs[r * BS_STR + n4] = *(const float4*)&g_xbc[(base_bl + r) * CDIM + DINNER + DSTATE + n4];
        *(float4*)&Pv[r * BS_STR + n4] = *(const float4*)&g_prevs[pbase + (long long)r * DSTATE + n4];
    }
    if (tid < QC) eA[tid] = __expf(g_Acum[((long long)bc * NHEADS + h) * QC + tid]);
    __syncthreads();

    const float dsk = D_skip[h];
    const int tq0 = (tid >> 4) * 4;
    const int tp0 = (tid & 15) * 4;
    float acc[4][4];
    #pragma unroll
    for (int i = 0; i < 4; i++)
        #pragma unroll
        for (int j = 0; j < 4; j++) acc[i][j] = 0.f;
    #pragma unroll 4
    for (int n = 0; n < DSTATE; n += 4) {
        float4 cq[4], pv[4];
        #pragma unroll
        for (int i = 0; i < 4; i++) cq[i] = *(const float4*)&Cs[(tq0 + i) * BS_STR + n];
        #pragma unroll
        for (int j = 0; j < 4; j++) pv[j] = *(const float4*)&Pv[(tp0 + j) * BS_STR + n];
        #pragma unroll
        for (int i = 0; i < 4; i++)
            #pragma unroll
            for (int j = 0; j < 4; j++) {
                acc[i][j] = fmaf(cq[i].x, pv[j].x, acc[i][j]);
                acc[i][j] = fmaf(cq[i].y, pv[j].y, acc[i][j]);
                acc[i][j] = fmaf(cq[i].z, pv[j].z, acc[i][j]);
                acc[i][j] = fmaf(cq[i].w, pv[j].w, acc[i][j]);
            }
    }
    #pragma unroll
    for (int i = 0; i < 4; i++) {
        int q = tq0 + i;
        long long row = base_bl + q;
        float4 yv = *(float4*)&g_Y[row * DINNER + h * HDIM + tp0];
        float4 xv = *(const float4*)&g_xbc[row * CDIM + h * HDIM + tp0];
        float e = eA[q];
        yv.x += e * acc[i][0] + dsk * xv.x;
        yv.y += e * acc[i][1] + dsk * xv.y;
        yv.z += e * acc[i][2] + dsk * xv.z;
        yv.w += e * acc[i][3] + dsk * xv.w;
        *(float4*)&g_Y[row * DINNER + h * HDIM + tp0] = yv;
    }
}

// ---------------- gate with silu(z) + RMSNorm, emit bf16 hi/lo for gemm2 ----------------
__global__ void k_gate(const float* __restrict__ norm_w) {
    __shared__ float sv[DINNER];
    const long long row = blockIdx.x;
    float local = 0.f;
    for (int i = threadIdx.x; i < DINNER; i += blockDim.x) {
        float yv = g_Y[row * DINNER + i];
        float zv = g_zxbcdt[row * NIN + i];
        float v = yv * silu(zv);
        sv[i] = v;
        local += v * v;
    }
    float tot = block_sum(local);
    float scale = rsqrtf(tot / DINNER + 1e-5f);
    for (int i = threadIdx.x; i < DINNER; i += blockDim.x) {
        float v = sv[i] * scale * norm_w[i];
        __nv_bfloat16 h = __float2bfloat16(v);
        g_y_hi[row * DINNER + i] = h;
        g_y_lo[row * DINNER + i] = __float2bfloat16(v - __bfloat162float(h));
    }
}

// ---------------- final LayerNorm + residual ----------------
__global__ void k_ln(const float* __restrict__ x, const float* __restrict__ ln_w,
                     const float* __restrict__ ln_b, float* __restrict__ out) {
    const long long row = blockIdx.x;
    const int t = threadIdx.x;
    float4 o = ((const float4*)&g_out[row * DMODEL])[t];
    float s = o.x + o.y + o.z + o.w;
    float sq = o.x*o.x + o.y*o.y + o.z*o.z + o.w*o.w;
    float sum = block_sum(s);
    float sumsq = block_sum(sq);
    float mu = sum / DMODEL;
    float var = sumsq / DMODEL - mu * mu;
    float rs = rsqrtf(var + 1e-5f);
    float4 xr = ((const float4*)&x[row * DMODEL])[t];
    float4 w = ((const float4*)ln_w)[t];
    float4 bb = ((const float4*)ln_b)[t];
    float4 r;
    r.x = xr.x + (o.x - mu) * rs * w.x + bb.x;
    r.y = xr.y + (o.y - mu) * rs * w.y + bb.y;
    r.z = xr.z + (o.z - mu) * rs * w.z + bb.z;
    r.w = xr.w + (o.w - mu) * rs * w.w + bb.w;
    ((float4*)&out[row * DMODEL])[t] = r;
}

// ---------------- launch ----------------
extern "C" void kernel_launch(void* const* d_in, const int* in_sizes, int n_in,
                              void* d_out, int out_size) {
    const float* x          = (const float*)d_in[0];
    const float* in_proj_w  = (const float*)d_in[1];
    const float* conv_w     = (const float*)d_in[2];
    const float* conv_b     = (const float*)d_in[3];
    const float* dt_bias    = (const float*)d_in[4];
    const float* A_log      = (const float*)d_in[5];
    const float* D_skip     = (const float*)d_in[6];
    const float* norm_w     = (const float*)d_in[7];
    const float* out_proj_w = (const float*)d_in[8];
    const float* ln_w       = (const float*)d_in[9];
    const float* ln_b       = (const float*)d_in[10];
    float* out = (float*)d_out;
    (void)in_sizes; (void)n_in; (void)out_size;

    cudaFuncSetAttribute(k_chunk, cudaFuncAttributeMaxDynamicSharedMemorySize,
                         SMEM_CHUNK_FLOATS * (int)sizeof(float));
    cudaFuncSetAttribute(k_yo, cudaFuncAttributeMaxDynamicSharedMemorySize,
                         SMEM_YO_FLOATS * (int)sizeof(float));
    cudaFuncSetAttribute(k_gemm_mma, cudaFuncAttributeMaxDynamicSharedMemorySize,
                         GEMM_SMEM_BYTES);

    __nv_bfloat16 *xh, *xl, *w1h, *w1l, *yh, *yl, *w2h, *w2l;
    float *zx, *go;
    cudaGetSymbolAddress((void**)&xh,  g_x_hi);  cudaGetSymbolAddress((void**)&xl,  g_x_lo);
    cudaGetSymbolAddress((void**)&w1h, g_w1_hi); cudaGetSymbolAddress((void**)&w1l, g_w1_lo);
    cudaGetSymbolAddress((void**)&yh,  g_y_hi);  cudaGetSymbolAddress((void**)&yl,  g_y_lo);
    cudaGetSymbolAddress((void**)&w2h, g_w2_hi); cudaGetSymbolAddress((void**)&w2l, g_w2_lo);
    cudaGetSymbolAddress((void**)&zx,  g_zxbcdt); cudaGetSymbolAddress((void**)&go, g_out);

    // 0) bf16 hi/lo conversions
    k_cvt<<<(int)(((long long)BL * DMODEL / 4 + 255) / 256), 256>>>(x, xh, xl, (long long)BL * DMODEL / 4);
    k_cvt<<<(int)(((long long)NIN * DMODEL / 4 + 255) / 256), 256>>>(in_proj_w, w1h, w1l, (long long)NIN * DMODEL / 4);
    k_cvt<<<(int)(((long long)DMODEL * DINNER / 4 + 255) / 256), 256>>>(out_proj_w, w2h, w2l, (long long)DMODEL * DINNER / 4);

    // 1) in_proj GEMM (HMMA): [8192,1024] x [4384,1024]^T
    k_gemm_mma<<<dim3((NIN + 127) / 128, BL / 128), 256, GEMM_SMEM_BYTES>>>(
        xh, xl, w1h, w1l, zx, BL, NIN, DMODEL);
    // 2) causal conv + SiLU
    k_conv<<<(int)(((long long)BL * CDIM + 255) / 256), 256>>>(conv_w, conv_b);
    // 3) dt
    k_dtk<<<(BL * NHEADS + 255) / 256, 256>>>(dt_bias);
    // 4) per-chunk intra work
    k_chunk<<<dim3(BATCH * NCH, NHEADS), 256, SMEM_CHUNK_FLOATS * sizeof(float)>>>(A_log);
    // 5) inter-chunk scan
    k_scan<<<BATCH * NHEADS, 256>>>();
    // 6) Yo + skip
    k_yo<<<dim3(BATCH * NCH, NHEADS), 256, SMEM_YO_FLOATS * sizeof(float)>>>(D_skip);
    // 7) gate + rmsnorm (emits bf16 hi/lo)
    k_gate<<<BL, 256>>>(norm_w);
    // 8) out_proj GEMM (HMMA): [8192,2048] x [1024,2048]^T
    k_gemm_mma<<<dim3(DMODEL / 128, BL / 128), 256, GEMM_SMEM_BYTES>>>(
        yh, yl, w2h, w2l, go, BL, DMODEL, DINNER);
    // 9) LayerNorm + residual
    k_ln<<<BL, 256>>>(x, ln_w, ln_b, out);
}

// round 9
// speedup vs baseline: 2.7486x; 1.5270x over previous
#include <cuda_runtime.h>
#include <cuda_bf16.h>
#include <cuda_fp16.h>
#include <cstdint>

// ---------------- problem constants ----------------
#define BATCH  2
#define SEQ    4096
#define DMODEL 1024
#define DINNER 2048
#define DSTATE 128
#define NHEADS 32
#define HDIM   64
#define CDIM   2304        // DINNER + 2*DSTATE
#define NIN    4384        // 2*DINNER + 2*DSTATE + NHEADS
#define QC     64          // chunk length
#define NCH    64          // SEQ / QC
#define BL     8192        // BATCH * SEQ
#define DTMIN  0.001f
#define DTMAX  0.1f

// ---------------- scratch (device globals; no allocs allowed) ----------------
__device__ float g_zxbcdt[(size_t)BL * NIN];       // in_proj output
__device__ float g_xbc[(size_t)BL * CDIM];         // conv+silu output (x_ssm | B | C)
__device__ float g_dt[(size_t)BL * NHEADS];        // dt after sigmoid mapping (fp32-exact)
__device__ float g_Acum[(size_t)BATCH * NCH * NHEADS * QC];
__device__ float g_cdecay[(size_t)BATCH * NCH * NHEADS];
__device__ float g_states[(size_t)BATCH * NCH * NHEADS * HDIM * DSTATE];
__device__ float g_prevs [(size_t)BATCH * NCH * NHEADS * HDIM * DSTATE];
__device__ float g_Y[(size_t)BL * DINNER];         // Yd then += Yo + skip
__device__ float g_out[(size_t)BL * DMODEL];       // out_proj output (pre-LN)

// fp16 operands for tensor-core GEMMs
__device__ __half g_x_h [(size_t)BL * DMODEL];
__device__ __half g_w1_h[(size_t)NIN * DMODEL];
__device__ __half g_y_h [(size_t)BL * DINNER];
__device__ __half g_w2_h[(size_t)DMODEL * DINNER];

// ---------------- helpers ----------------
__device__ __forceinline__ float block_sum(float v) {
    __shared__ float sh[32];
    __syncthreads();
    int lane = threadIdx.x & 31, wid = threadIdx.x >> 5;
    #pragma unroll
    for (int o = 16; o > 0; o >>= 1) v += __shfl_xor_sync(0xffffffffu, v, o);
    if (lane == 0) sh[wid] = v;
    __syncthreads();
    float r = (threadIdx.x < (blockDim.x >> 5)) ? sh[threadIdx.x] : 0.f;
    if (wid == 0) {
        #pragma unroll
        for (int o = 16; o > 0; o >>= 1) r += __shfl_xor_sync(0xffffffffu, r, o);
        if (lane == 0) sh[0] = r;
    }
    __syncthreads();
    return sh[0];
}

__device__ __forceinline__ float silu(float x) { return x / (1.f + __expf(-x)); }

__device__ __forceinline__ uint32_t smem_u32(const void* p) {
    uint32_t a;
    asm("{ .reg .u64 t; cvta.to.shared.u64 t, %1; cvt.u32.u64 %0, t; }" : "=r"(a) : "l"(p));
    return a;
}

// ---------------- portable async-copy / ldmatrix / mma wrappers ----------------
__device__ __forceinline__ void cp16(uint32_t dst, const void* src, bool pred) {
    int sz = pred ? 16 : 0;
    asm volatile("cp.async.cg.shared.global [%0], [%1], 16, %2;\n"
                 :: "r"(dst), "l"(src), "r"(sz) : "memory");
}
__device__ __forceinline__ void cp_commit() {
    asm volatile("cp.async.commit_group;" ::: "memory");
}
template <int N>
__device__ __forceinline__ void cp_wait() {
    asm volatile("cp.async.wait_group %0;" :: "n"(N) : "memory");
}
__device__ __forceinline__ void ldm_x4(uint32_t* r, uint32_t addr) {
    asm volatile("ldmatrix.sync.aligned.m8n8.x4.shared.b16 {%0,%1,%2,%3}, [%4];"
                 : "=r"(r[0]), "=r"(r[1]), "=r"(r[2]), "=r"(r[3]) : "r"(addr));
}
__device__ __forceinline__ void ldm_x2(uint32_t* r, uint32_t addr) {
    asm volatile("ldmatrix.sync.aligned.m8n8.x2.shared.b16 {%0,%1}, [%2];"
                 : "=r"(r[0]), "=r"(r[1]) : "r"(addr));
}
__device__ __forceinline__ void mma_f16(float* d, const uint32_t* a, const uint32_t* b) {
    asm volatile("mma.sync.aligned.m16n8k16.row.col.f32.f16.f16.f32 "
                 "{%0,%1,%2,%3}, {%4,%5,%6,%7}, {%8,%9}, {%0,%1,%2,%3};"
                 : "+f"(d[0]), "+f"(d[1]), "+f"(d[2]), "+f"(d[3])
                 : "r"(a[0]), "r"(a[1]), "r"(a[2]), "r"(a[3]), "r"(b[0]), "r"(b[1]));
}

// ---------------- fp32 -> fp16 convert ----------------
__global__ void k_cvt_h(const float* __restrict__ in, __half* __restrict__ out, long long n4) {
    long long i = (long long)blockIdx.x * blockDim.x + threadIdx.x;
    if (i >= n4) return;
    float4 v = ((const float4*)in)[i];
    __half2 a = __floats2half2_rn(v.x, v.y);
    __half2 b = __floats2half2_rn(v.z, v.w);
    ((__half2*)out)[i * 2 + 0] = a;
    ((__half2*)out)[i * 2 + 1] = b;
}

// ---------------- fp16 HMMA GEMM: C[M,N] = A[M,K] * B[N,K]^T ----------------
// Block 128x128, BK=64, 256 threads (8 warps, 2x4 -> warp tile 64x32), double-buffered.
#define BKH    64
#define HS_STR 72
#define H_TILE (128 * HS_STR)              // elems per tile
#define OFF_B  H_TILE
#define H_STAGE (2 * H_TILE)               // elems per stage
#define GEMMH_SMEM_BYTES (2 * H_STAGE * 2) // 73728

__device__ __forceinline__ void load_stage_h(
    const __half* __restrict__ A, const __half* __restrict__ B,
    uint32_t smbase, int stage, int m0, int n0, int k0, int N, int K, int tid)
{
    uint32_t sb = smbase + (uint32_t)stage * (H_STAGE * 2);
    #pragma unroll
    for (int j = 0; j < 4; j++) {
        int c = tid + j * 256;             // 0..1023
        int r = c >> 3, c8 = (c & 7) * 8;  // row 0..127, col 0..56
        uint32_t soff = (uint32_t)(r * HS_STR + c8) * 2;
        cp16(sb + soff, A + (size_t)(m0 + r) * K + k0 + c8, true);
        bool ok = (n0 + r) < N;
        cp16(sb + OFF_B * 2 + soff, B + (size_t)(ok ? (n0 + r) : 0) * K + k0 + c8, ok);
    }
}

__global__ void __launch_bounds__(256, 2)
k_gemm_h(const __half* __restrict__ A, const __half* __restrict__ B,
         float* __restrict__ C, int M, int N, int K) {
    extern __shared__ __half smg[];
    const uint32_t smbase = smem_u32(smg);
    const int tid = threadIdx.x, wid = tid >> 5, lid = tid & 31;
    const int m0 = blockIdx.y * 128, n0 = blockIdx.x * 128;
    const int wm = (wid >> 2) * 64;        // warp m offset (0/64)
    const int wn = (wid & 3) * 32;         // warp n offset (0/32/64/96)
    const int l15 = lid & 15;

    float acc[4][4][4];
    #pragma unroll
    for (int mi = 0; mi < 4; mi++)
        #pragma unroll
        for (int ni = 0; ni < 4; ni++)
            #pragma unroll
            for (int k = 0; k < 4; k++) acc[mi][ni][k] = 0.f;

    const int la_row = wm + (lid & 15);
    const int la_col = (lid >> 4) * 8;
    const int lb_row = wn + (l15 & 7);
    const int lb_col = ((l15 >> 3) & 1) * 8;

    const int NIT = K / BKH;
    load_stage_h(A, B, smbase, 0, m0, n0, 0, N, K, tid);
    cp_commit();

    for (int it = 0; it < NIT; it++) {
        if (it + 1 < NIT) {
            load_stage_h(A, B, smbase, (it + 1) & 1, m0, n0, (it + 1) * BKH, N, K, tid);
            cp_commit();
            cp_wait<1>();
        } else {
            cp_wait<0>();
        }
        __syncthreads();

        uint32_t sb = smbase + (uint32_t)(it & 1) * (H_STAGE * 2);
        #pragma unroll
        for (int ks = 0; ks < 4; ks++) {
            uint32_t af[4][4], bb[4][2];
            #pragma unroll
            for (int mi = 0; mi < 4; mi++)
                ldm_x4(af[mi], sb + (uint32_t)((la_row + mi * 16) * HS_STR + ks * 16 + la_col) * 2);
            #pragma unroll
            for (int ni = 0; ni < 4; ni++)
                ldm_x2(bb[ni], sb + (uint32_t)(OFF_B + (lb_row + ni * 8) * HS_STR + ks * 16 + lb_col) * 2);
            #pragma unroll
            for (int mi = 0; mi < 4; mi++)
                #pragma unroll
                for (int ni = 0; ni < 4; ni++)
                    mma_f16(acc[mi][ni], af[mi], bb[ni]);
        }
        __syncthreads();
    }

    const int r0 = m0 + wm + (lid >> 2);
    const int c0 = n0 + wn + (lid & 3) * 2;
    #pragma unroll
    for (int mi = 0; mi < 4; mi++) {
        #pragma unroll
        for (int ni = 0; ni < 4; ni++) {
            int col = c0 + ni * 8;
            if (col < N) {
                int row = r0 + mi * 16;
                *(float2*)&C[(size_t)row * N + col] = make_float2(acc[mi][ni][0], acc[mi][ni][1]);
                *(float2*)&C[(size_t)(row + 8) * N + col] = make_float2(acc[mi][ni][2], acc[mi][ni][3]);
            }
        }
    }
}

// ---------------- fp32-exact dt: dt_raw = x . w_dt, then sigmoid mapping ----------------
// grid = BL/64 blocks, 256 threads. Each block: 64 rows x 32 heads.
__global__ void k_dtfix(const float* __restrict__ x, const float* __restrict__ in_proj_w,
                        const float* __restrict__ dt_bias) {
    __shared__ float xs[64 * 64];
    __shared__ float ws[32 * 65];
    const int tid = threadIdx.x;
    const int h = tid & 31, rg = tid >> 5;              // head, row-group (8 rows each)
    const int bl0 = blockIdx.x * 64;
    const float* wdt = in_proj_w + (size_t)(DINNER + CDIM) * DMODEL;

    float acc[8];
    #pragma unroll
    for (int i = 0; i < 8; i++) acc[i] = 0.f;

    for (int k0 = 0; k0 < DMODEL; k0 += 64) {
        __syncthreads();
        #pragma unroll
        for (int it = 0; it < 4; it++) {
            int i4 = tid + it * 256;                    // 1024 float4s
            int r = i4 >> 4, c4 = (i4 & 15) * 4;
            *(float4*)&xs[r * 64 + c4] = *(const float4*)&x[(size_t)(bl0 + r) * DMODEL + k0 + c4];
        }
        #pragma unroll
        for (int it = 0; it < 2; it++) {
            int i4 = tid + it * 256;                    // 512 float4s
            int r = i4 >> 4, c4 = (i4 & 15) * 4;
            float4 v = *(const float4*)&wdt[(size_t)r * DMODEL + k0 + c4];
            ws[r * 65 + c4 + 0] = v.x; ws[r * 65 + c4 + 1] = v.y;
            ws[r * 65 + c4 + 2] = v.z; ws[r * 65 + c4 + 3] = v.w;
        }
        __syncthreads();
        #pragma unroll 8
        for (int k = 0; k < 64; k++) {
            float w = ws[h * 65 + k];
            #pragma unroll
            for (int i = 0; i < 8; i++)
                acc[i] = fmaf(xs[(rg * 8 + i) * 64 + k], w, acc[i]);
        }
    }
    float bias = dt_bias[h];
    #pragma unroll
    for (int i = 0; i < 8; i++) {
        float raw = acc[i] + bias;
        float sg = 1.f / (1.f + __expf(-raw));
        g_dt[(size_t)(bl0 + rg * 8 + i) * NHEADS + h] = DTMIN + (DTMAX - DTMIN) * sg;
    }
}

// ---------------- conv1d (K=4, causal) + bias + SiLU ----------------
__global__ void k_conv(const float* __restrict__ conv_w, const float* __restrict__ conv_b) {
    long long idx = (long long)blockIdx.x * blockDim.x + threadIdx.x;
    if (idx >= (long long)BL * CDIM) return;
    int ch = (int)(idx % CDIM);
    int bl = (int)(idx / CDIM);
    int l  = bl & (SEQ - 1);
    const float4 w = *(const float4*)&conv_w[ch * 4];
    float acc = conv_b[ch];
    float v0 = (l >= 3) ? g_zxbcdt[(long long)(bl - 3) * NIN + DINNER + ch] : 0.f;
    float v1 = (l >= 2) ? g_zxbcdt[(long long)(bl - 2) * NIN + DINNER + ch] : 0.f;
    float v2 = (l >= 1) ? g_zxbcdt[(long long)(bl - 1) * NIN + DINNER + ch] : 0.f;
    float v3 = g_zxbcdt[(long long)bl * NIN + DINNER + ch];
    acc += v0 * w.x + v1 * w.y + v2 * w.z + v3 * w.w;
    g_xbc[(long long)bl * CDIM + ch] = silu(acc);
}

// ---------------- per-chunk: CB^T*Lmat, Yd, states, decay ----------------
#define BS_STR 132
#define XS_STR 68
#define SMEM_CHUNK_FLOATS (64*BS_STR*2 + 64*XS_STR*2 + 64*3)

__global__ void k_chunk(const float* __restrict__ A_log) {
    extern __shared__ float sm[];
    float* Bs   = sm;
    float* Cs   = Bs + 64 * BS_STR;
    float* xs   = Cs + 64 * BS_STR;
    float* CBL  = xs + 64 * XS_STR;
    float* dt_s = CBL + 64 * XS_STR;
    float* Ac_s = dt_s + 64;
    float* ws   = Ac_s + 64;

    const int tid = threadIdx.x;
    const int bc = blockIdx.x;
    const int h  = blockIdx.y;
    const int b  = bc / NCH, cc = bc % NCH;
    const long long base_bl = (long long)b * SEQ + (long long)cc * QC;

    #pragma unroll
    for (int it = 0; it < 8; it++) {
        int i4 = tid + it * 256;
        int q = i4 >> 5, n4 = (i4 & 31) * 4;
        *(float4*)&Bs[q * BS_STR + n4] = *(const float4*)&g_xbc[(base_bl + q) * CDIM + DINNER + n4];
        *(float4*)&Cs[q * BS_STR + n4] = *(const float4*)&g_xbc[(base_bl + q) * CDIM + DINNER + DSTATE + n4];
    }
    #pragma unroll
    for (int it = 0; it < 4; it++) {
        int i4 = tid + it * 256;
        int q = i4 >> 4, p4 = (i4 & 15) * 4;
        *(float4*)&xs[q * XS_STR + p4] = *(const float4*)&g_xbc[(base_bl + q) * CDIM + h * HDIM + p4];
    }
    if (tid < QC) dt_s[tid] = g_dt[(base_bl + tid) * NHEADS + h];
    __syncthreads();

    if (tid == 0) {
        float Ah = -__expf(A_log[h]);
        float s = 0.f;
        for (int q = 0; q < QC; q++) { s += dt_s[q] * Ah; Ac_s[q] = s; }
    }
    __syncthreads();

    if (tid < QC) {
        float last = Ac_s[QC - 1];
        ws[tid] = __expf(last - Ac_s[tid]) * dt_s[tid];
        g_Acum[((long long)bc * NHEADS + h) * QC + tid] = Ac_s[tid];
        if (tid == 0) g_cdecay[(long long)bc * NHEADS + h] = __expf(last);
    }

    // ---- CBL[q][s] = (C_q . B_s) * exp(Acum_q - Acum_s) * dt_s   (s<=q else 0)
    {
        const int tq0 = (tid >> 4) * 4;
        const int ts0 = (tid & 15) * 4;
        float acc[4][4];
        #pragma unroll
        for (int i = 0; i < 4; i++)
            #pragma unroll
            for (int j = 0; j < 4; j++) acc[i][j] = 0.f;
        #pragma unroll 4
        for (int n = 0; n < DSTATE; n += 4) {
            float4 cq[4], bs[4];
            #pragma unroll
            for (int i = 0; i < 4; i++) cq[i] = *(const float4*)&Cs[(tq0 + i) * BS_STR + n];
            #pragma unroll
            for (int j = 0; j < 4; j++) bs[j] = *(const float4*)&Bs[(ts0 + j) * BS_STR + n];
            #pragma unroll
            for (int i = 0; i < 4; i++)
                #pragma unroll
                for (int j = 0; j < 4; j++) {
                    acc[i][j] = fmaf(cq[i].x, bs[j].x, acc[i][j]);
                    acc[i][j] = fmaf(cq[i].y, bs[j].y, acc[i][j]);
                    acc[i][j] = fmaf(cq[i].z, bs[j].z, acc[i][j]);
                    acc[i][j] = fmaf(cq[i].w, bs[j].w, acc[i][j]);
                }
        }
        #pragma unroll
        for (int i = 0; i < 4; i++) {
            int q = tq0 + i;
            #pragma unroll
            for (int j = 0; j < 4; j++) {
                int s = ts0 + j;
                float val = 0.f;
                if (s <= q) val = acc[i][j] * __expf(Ac_s[q] - Ac_s[s]) * dt_s[s];
                CBL[q * XS_STR + s] = val;
            }
        }
    }
    __syncthreads();

    // ---- Yd[q][p] = sum_s CBL[q][s] * xs[s][p]
    {
        const int tq0 = (tid >> 4) * 4;
        const int tp0 = (tid & 15) * 4;
        float acc[4][4];
        #pragma unroll
        for (int i = 0; i < 4; i++)
            #pragma unroll
            for (int j = 0; j < 4; j++) acc[i][j] = 0.f;
        #pragma unroll 4
        for (int s = 0; s < QC; s += 4) {
            float4 cb[4];
            float4 xv[4];
            #pragma unroll
            for (int i = 0; i < 4; i++) cb[i] = *(const float4*)&CBL[(tq0 + i) * XS_STR + s];
            #pragma unroll
            for (int ss = 0; ss < 4; ss++) xv[ss] = *(const float4*)&xs[(s + ss) * XS_STR + tp0];
            #pragma unroll
            for (int i = 0; i < 4; i++) {
                acc[i][0] = fmaf(cb[i].x, xv[0].x, acc[i][0]);
                acc[i][1] = fmaf(cb[i].x, xv[0].y, acc[i][1]);
                acc[i][2] = fmaf(cb[i].x, xv[0].z, acc[i][2]);
                acc[i][3] = fmaf(cb[i].x, xv[0].w, acc[i][3]);
                acc[i][0] = fmaf(cb[i].y, xv[1].x, acc[i][0]);
                acc[i][1] = fmaf(cb[i].y, xv[1].y, acc[i][1]);
                acc[i][2] = fmaf(cb[i].y, xv[1].z, acc[i][2]);
                acc[i][3] = fmaf(cb[i].y, xv[1].w, acc[i][3]);
                acc[i][0] = fmaf(cb[i].z, xv[2].x, acc[i][0]);
                acc[i][1] = fmaf(cb[i].z, xv[2].y, acc[i][1]);
                acc[i][2] = fmaf(cb[i].z, xv[2].z, acc[i][2]);
                acc[i][3] = fmaf(cb[i].z, xv[2].w, acc[i][3]);
                acc[i][0] = fmaf(cb[i].w, xv[3].x, acc[i][0]);
                acc[i][1] = fmaf(cb[i].w, xv[3].y, acc[i][1]);
                acc[i][2] = fmaf(cb[i].w, xv[3].z, acc[i][2]);
                acc[i][3] = fmaf(cb[i].w, xv[3].w, acc[i][3]);
            }
        }
        #pragma unroll
        for (int i = 0; i < 4; i++) {
            int q = tq0 + i;
            *(float4*)&g_Y[(base_bl + q) * DINNER + h * HDIM + tp0] =
                make_float4(acc[i][0], acc[i][1], acc[i][2], acc[i][3]);
        }
    }

    // ---- states[p][n] = sum_q (B[q][n]*ws[q]) * xs[q][p]
    {
        const int tp0 = (tid >> 4) * 4;
        const int tn0 = (tid & 15) * 8;
        float acc[4][8];
        #pragma unroll
        for (int i = 0; i < 4; i++)
            #pragma unroll
            for (int j = 0; j < 8; j++) acc[i][j] = 0.f;
        #pragma unroll 4
        for (int q = 0; q < QC; q++) {
            float wq = ws[q];
            float4 xv = *(const float4*)&xs[q * XS_STR + tp0];
            float4 bv0 = *(const float4*)&Bs[q * BS_STR + tn0];
            float4 bv1 = *(const float4*)&Bs[q * BS_STR + tn0 + 4];
            float xw[4] = { xv.x * wq, xv.y * wq, xv.z * wq, xv.w * wq };
            float bb[8] = { bv0.x, bv0.y, bv0.z, bv0.w, bv1.x, bv1.y, bv1.z, bv1.w };
            #pragma unroll
            for (int i = 0; i < 4; i++)
                #pragma unroll
                for (int j = 0; j < 8; j++)
                    acc[i][j] = fmaf(xw[i], bb[j], acc[i][j]);
        }
        long long sbase = ((long long)bc * NHEADS + h) * HDIM * DSTATE;
        #pragma unroll
        for (int i = 0; i < 4; i++) {
            int p = tp0 + i;
            #pragma unroll
            for (int j = 0; j < 8; j += 4)
                *(float4*)&g_states[sbase + (long long)p * DSTATE + tn0 + j] =
                    make_float4(acc[i][j], acc[i][j+1], acc[i][j+2], acc[i][j+3]);
        }
    }
}

// ---------------- parallel inter-chunk scan (one element per thread) ----------------
__global__ void k_scan() {
    int el = blockIdx.x * 256 + threadIdx.x;           // 0 .. BATCH*NHEADS*8192-1
    int bh = el >> 13;                                 // (b*NHEADS + h)
    int idx = el & 8191;
    int b = bh >> 5, h = bh & 31;
    float carry = 0.f;
    for (int c = 0; c < NCH; c++) {
        long long bcn = ((long long)b * NCH + c) * NHEADS + h;
        float dec = g_cdecay[bcn];
        long long base = bcn * (HDIM * DSTATE) + idx;
        float st = g_states[base];
        g_prevs[base] = carry;
        carry = fmaf(dec, carry, st);
    }
}

// ---------------- Yo + D_skip*x, accumulate into g_Y ----------------
#define SMEM_YO_FLOATS (64*BS_STR*2 + 64)
__global__ void k_yo(const float* __restrict__ D_skip) {
    extern __shared__ float sm[];
    float* Cs = sm;
    float* Pv = Cs + 64 * BS_STR;
    float* eA = Pv + 64 * BS_STR;

    const int tid = threadIdx.x;
    const int bc = blockIdx.x;
    const int h  = blockIdx.y;
    const int b  = bc / NCH, cc = bc % NCH;
    const long long base_bl = (long long)b * SEQ + (long long)cc * QC;
    const long long pbase = ((long long)bc * NHEADS + h) * (HDIM * DSTATE);

    #pragma unroll
    for (int it = 0; it < 8; it++) {
        int i4 = tid + it * 256;
        int r = i4 >> 5, n4 = (i4 & 31) * 4;
        *(float4*)&Cs[r * BS_STR + n4] = *(const float4*)&g_xbc[(base_bl + r) * CDIM + DINNER + DSTATE + n4];
        *(float4*)&Pv[r * BS_STR + n4] = *(const float4*)&g_prevs[pbase + (long long)r * DSTATE + n4];
    }
    if (tid < QC) eA[tid] = __expf(g_Acum[((long long)bc * NHEADS + h) * QC + tid]);
    __syncthreads();

    const float dsk = D_skip[h];
    const int tq0 = (tid >> 4) * 4;
    const int tp0 = (tid & 15) * 4;
    float acc[4][4];
    #pragma unroll
    for (int i = 0; i < 4; i++)
        #pragma unroll
        for (int j = 0; j < 4; j++) acc[i][j] = 0.f;
    #pragma unroll 4
    for (int n = 0; n < DSTATE; n += 4) {
        float4 cq[4], pv[4];
        #pragma unroll
        for (int i = 0; i < 4; i++) cq[i] = *(const float4*)&Cs[(tq0 + i) * BS_STR + n];
        #pragma unroll
        for (int j = 0; j < 4; j++) pv[j] = *(const float4*)&Pv[(tp0 + j) * BS_STR + n];
        #pragma unroll
        for (int i = 0; i < 4; i++)
            #pragma unroll
            for (int j = 0; j < 4; j++) {
                acc[i][j] = fmaf(cq[i].x, pv[j].x, acc[i][j]);
                acc[i][j] = fmaf(cq[i].y, pv[j].y, acc[i][j]);
                acc[i][j] = fmaf(cq[i].z, pv[j].z, acc[i][j]);
                acc[i][j] = fmaf(cq[i].w, pv[j].w, acc[i][j]);
            }
    }
    #pragma unroll
    for (int i = 0; i < 4; i++) {
        int q = tq0 + i;
        long long row = base_bl + q;
        float4 yv = *(float4*)&g_Y[row * DINNER + h * HDIM + tp0];
        float4 xv = *(const float4*)&g_xbc[row * CDIM + h * HDIM + tp0];
        float e = eA[q];
        yv.x += e * acc[i][0] + dsk * xv.x;
        yv.y += e * acc[i][1] + dsk * xv.y;
        yv.z += e * acc[i][2] + dsk * xv.z;
        yv.w += e * acc[i][3] + dsk * xv.w;
        *(float4*)&g_Y[row * DINNER + h * HDIM + tp0] = yv;
    }
}

// ---------------- gate with silu(z) + RMSNorm, emit fp16 for gemm2 ----------------
__global__ void k_gate(const float* __restrict__ norm_w) {
    __shared__ float sv[DINNER];
    const long long row = blockIdx.x;
    float local = 0.f;
    for (int i = threadIdx.x; i < DINNER; i += blockDim.x) {
        float yv = g_Y[row * DINNER + i];
        float zv = g_zxbcdt[row * NIN + i];
        float v = yv * silu(zv);
        sv[i] = v;
        local += v * v;
    }
    float tot = block_sum(local);
    float scale = rsqrtf(tot / DINNER + 1e-5f);
    for (int i = threadIdx.x; i < DINNER; i += blockDim.x) {
        float v = sv[i] * scale * norm_w[i];
        g_y_h[row * DINNER + i] = __float2half(v);
    }
}

// ---------------- final LayerNorm + residual ----------------
__global__ void k_ln(const float* __restrict__ x, const float* __restrict__ ln_w,
                     const float* __restrict__ ln_b, float* __restrict__ out) {
    const long long row = blockIdx.x;
    const int t = threadIdx.x;
    float4 o = ((const float4*)&g_out[row * DMODEL])[t];
    float s = o.x + o.y + o.z + o.w;
    float sq = o.x*o.x + o.y*o.y + o.z*o.z + o.w*o.w;
    float sum = block_sum(s);
    float sumsq = block_sum(sq);
    float mu = sum / DMODEL;
    float var = sumsq / DMODEL - mu * mu;
    float rs = rsqrtf(var + 1e-5f);
    float4 xr = ((const float4*)&x[row * DMODEL])[t];
    float4 w = ((const float4*)ln_w)[t];
    float4 bb = ((const float4*)ln_b)[t];
    float4 r;
    r.x = xr.x + (o.x - mu) * rs * w.x + bb.x;
    r.y = xr.y + (o.y - mu) * rs * w.y + bb.y;
    r.z = xr.z + (o.z - mu) * rs * w.z + bb.z;
    r.w = xr.w + (o.w - mu) * rs * w.w + bb.w;
    ((float4*)&out[row * DMODEL])[t] = r;
}

// ---------------- launch ----------------
extern "C" void kernel_launch(void* const* d_in, const int* in_sizes, int n_in,
                              void* d_out, int out_size) {
    const float* x          = (const float*)d_in[0];
    const float* in_proj_w  = (const float*)d_in[1];
    const float* conv_w     = (const float*)d_in[2];
    const float* conv_b     = (const float*)d_in[3];
    const float* dt_bias    = (const float*)d_in[4];
    const float* A_log      = (const float*)d_in[5];
    const float* D_skip     = (const float*)d_in[6];
    const float* norm_w     = (const float*)d_in[7];
    const float* out_proj_w = (const float*)d_in[8];
    const float* ln_w       = (const float*)d_in[9];
    const float* ln_b       = (const float*)d_in[10];
    float* out = (float*)d_out;
    (void)in_sizes; (void)n_in; (void)out_size;

    cudaFuncSetAttribute(k_chunk, cudaFuncAttributeMaxDynamicSharedMemorySize,
                         SMEM_CHUNK_FLOATS * (int)sizeof(float));
    cudaFuncSetAttribute(k_yo, cudaFuncAttributeMaxDynamicSharedMemorySize,
                         SMEM_YO_FLOATS * (int)sizeof(float));
    cudaFuncSetAttribute(k_gemm_h, cudaFuncAttributeMaxDynamicSharedMemorySize,
                         GEMMH_SMEM_BYTES);

    __half *xh, *w1h, *yh, *w2h;
    float *zx, *go;
    cudaGetSymbolAddress((void**)&xh,  g_x_h);
    cudaGetSymbolAddress((void**)&w1h, g_w1_h);
    cudaGetSymbolAddress((void**)&yh,  g_y_h);
    cudaGetSymbolAddress((void**)&w2h, g_w2_h);
    cudaGetSymbolAddress((void**)&zx,  g_zxbcdt);
    cudaGetSymbolAddress((void**)&go,  g_out);

    // 0) fp16 conversions
    k_cvt_h<<<(int)(((long long)BL * DMODEL / 4 + 255) / 256), 256>>>(x, xh, (long long)BL * DMODEL / 4);
    k_cvt_h<<<(int)(((long long)NIN * DMODEL / 4 + 255) / 256), 256>>>(in_proj_w, w1h, (long long)NIN * DMODEL / 4);
    k_cvt_h<<<(int)(((long long)DMODEL * DINNER / 4 + 255) / 256), 256>>>(out_proj_w, w2h, (long long)DMODEL * DINNER / 4);

    // 1) in_proj GEMM (fp16 HMMA): [8192,1024] x [4384,1024]^T
    k_gemm_h<<<dim3((NIN + 127) / 128, BL / 128), 256, GEMMH_SMEM_BYTES>>>(
        xh, w1h, zx, BL, NIN, DMODEL);
    // 2) causal conv + SiLU
    k_conv<<<(int)(((long long)BL * CDIM + 255) / 256), 256>>>(conv_w, conv_b);
    // 3) fp32-exact dt (replaces fp16 dt columns + k_dtk)
    k_dtfix<<<BL / 64, 256>>>(x, in_proj_w, dt_bias);
    // 4) per-chunk intra work
    k_chunk<<<dim3(BATCH * NCH, NHEADS), 256, SMEM_CHUNK_FLOATS * sizeof(float)>>>(A_log);
    // 5) inter-chunk scan (fully parallel)
    k_scan<<<(BATCH * NHEADS * HDIM * DSTATE) / 256, 256>>>();
    // 6) Yo + skip
    k_yo<<<dim3(BATCH * NCH, NHEADS), 256, SMEM_YO_FLOATS * sizeof(float)>>>(D_skip);
    // 7) gate + rmsnorm (emits fp16)
    k_gate<<<BL, 256>>>(norm_w);
    // 8) out_proj GEMM (fp16 HMMA): [8192,2048] x [1024,2048]^T
    k_gemm_h<<<dim3(DMODEL / 128, BL / 128), 256, GEMMH_SMEM_BYTES>>>(
        yh, w2h, go, BL, DMODEL, DINNER);
    // 9) LayerNorm + residual
    k_ln<<<BL, 256>>>(x, ln_w, ln_b, out);
}

// round 12
// speedup vs baseline: 3.5290x; 1.2839x over previous
#include <cuda_runtime.h>
#include <cuda_bf16.h>
#include <cuda_fp16.h>
#include <cstdint>

// ---------------- problem constants ----------------
#define BATCH  2
#define SEQ    4096
#define DMODEL 1024
#define DINNER 2048
#define DSTATE 128
#define NHEADS 32
#define HDIM   64
#define CDIM   2304        // DINNER + 2*DSTATE
#define NIN    4384        // 2*DINNER + 2*DSTATE + NHEADS
#define QC     64          // chunk length
#define NCH    64          // SEQ / QC
#define BL     8192        // BATCH * SEQ
#define DTMIN  0.001f
#define DTMAX  0.1f

// ---------------- scratch (device globals; no allocs allowed) ----------------
__device__ float g_zxbcdt[(size_t)BL * NIN];       // in_proj output
__device__ float g_xbc[(size_t)BL * CDIM];         // conv+silu output (x_ssm | B | C)
__device__ float g_dt[(size_t)BL * NHEADS];        // dt after sigmoid mapping (fp32-exact)
__device__ float g_Acum[(size_t)BATCH * NCH * NHEADS * QC];
__device__ float g_cdecay[(size_t)BATCH * NCH * NHEADS];
__device__ float g_CB[(size_t)BATCH * NCH * QC * QC];     // head-independent C.B
__device__ __half g_states_h[(size_t)BATCH * NCH * NHEADS * HDIM * DSTATE];
__device__ __half g_prevs_h [(size_t)BATCH * NCH * NHEADS * HDIM * DSTATE];
__device__ float g_Y[(size_t)BL * DINNER];         // Yd then += Yo + skip
__device__ float g_out[(size_t)BL * DMODEL];       // out_proj output (pre-LN)

// fp16 operands for tensor-core GEMMs
__device__ __half g_x_h [(size_t)BL * DMODEL];
__device__ __half g_w1_h[(size_t)NIN * DMODEL];
__device__ __half g_y_h [(size_t)BL * DINNER];
__device__ __half g_w2_h[(size_t)DMODEL * DINNER];

// ---------------- helpers ----------------
__device__ __forceinline__ float block_sum(float v) {
    __shared__ float sh[32];
    __syncthreads();
    int lane = threadIdx.x & 31, wid = threadIdx.x >> 5;
    #pragma unroll
    for (int o = 16; o > 0; o >>= 1) v += __shfl_xor_sync(0xffffffffu, v, o);
    if (lane == 0) sh[wid] = v;
    __syncthreads();
    float r = (threadIdx.x < (blockDim.x >> 5)) ? sh[threadIdx.x] : 0.f;
    if (wid == 0) {
        #pragma unroll
        for (int o = 16; o > 0; o >>= 1) r += __shfl_xor_sync(0xffffffffu, r, o);
        if (lane == 0) sh[0] = r;
    }
    __syncthreads();
    return sh[0];
}

__device__ __forceinline__ float silu(float x) { return x / (1.f + __expf(-x)); }

__device__ __forceinline__ uint32_t smem_u32(const void* p) {
    uint32_t a;
    asm("{ .reg .u64 t; cvta.to.shared.u64 t, %1; cvt.u32.u64 %0, t; }" : "=r"(a) : "l"(p));
    return a;
}

// ---------------- portable async-copy / ldmatrix / mma wrappers ----------------
__device__ __forceinline__ void cp16(uint32_t dst, const void* src, bool pred) {
    int sz = pred ? 16 : 0;
    asm volatile("cp.async.cg.shared.global [%0], [%1], 16, %2;\n"
                 :: "r"(dst), "l"(src), "r"(sz) : "memory");
}
__device__ __forceinline__ void cp_commit() {
    asm volatile("cp.async.commit_group;" ::: "memory");
}
template <int N>
__device__ __forceinline__ void cp_wait() {
    asm volatile("cp.async.wait_group %0;" :: "n"(N) : "memory");
}
__device__ __forceinline__ void ldm_x4(uint32_t* r, uint32_t addr) {
    asm volatile("ldmatrix.sync.aligned.m8n8.x4.shared.b16 {%0,%1,%2,%3}, [%4];"
                 : "=r"(r[0]), "=r"(r[1]), "=r"(r[2]), "=r"(r[3]) : "r"(addr));
}
__device__ __forceinline__ void ldm_x2(uint32_t* r, uint32_t addr) {
    asm volatile("ldmatrix.sync.aligned.m8n8.x2.shared.b16 {%0,%1}, [%2];"
                 : "=r"(r[0]), "=r"(r[1]) : "r"(addr));
}
__device__ __forceinline__ void mma_f16(float* d, const uint32_t* a, const uint32_t* b) {
    asm volatile("mma.sync.aligned.m16n8k16.row.col.f32.f16.f16.f32 "
                 "{%0,%1,%2,%3}, {%4,%5,%6,%7}, {%8,%9}, {%0,%1,%2,%3};"
                 : "+f"(d[0]), "+f"(d[1]), "+f"(d[2]), "+f"(d[3])
                 : "r"(a[0]), "r"(a[1]), "r"(a[2]), "r"(a[3]), "r"(b[0]), "r"(b[1]));
}

// ---------------- fp32 -> fp16 convert ----------------
__global__ void k_cvt_h(const float* __restrict__ in, __half* __restrict__ out, long long n4) {
    long long i = (long long)blockIdx.x * blockDim.x + threadIdx.x;
    if (i >= n4) return;
    float4 v = ((const float4*)in)[i];
    ((__half2*)out)[i * 2 + 0] = __floats2half2_rn(v.x, v.y);
    ((__half2*)out)[i * 2 + 1] = __floats2half2_rn(v.z, v.w);
}

// ---------------- fp16 HMMA GEMM: C[M,N] = A[M,K] * B[N,K]^T ----------------
#define BKH    64
#define HS_STR 72
#define H_TILE (128 * HS_STR)
#define OFF_B  H_TILE
#define H_STAGE (2 * H_TILE)
#define GEMMH_SMEM_BYTES (2 * H_STAGE * 2) // 73728

__device__ __forceinline__ void load_stage_h(
    const __half* __restrict__ A, const __half* __restrict__ B,
    uint32_t smbase, int stage, int m0, int n0, int k0, int N, int K, int tid)
{
    uint32_t sb = smbase + (uint32_t)stage * (H_STAGE * 2);
    #pragma unroll
    for (int j = 0; j < 4; j++) {
        int c = tid + j * 256;
        int r = c >> 3, c8 = (c & 7) * 8;
        uint32_t soff = (uint32_t)(r * HS_STR + c8) * 2;
        cp16(sb + soff, A + (size_t)(m0 + r) * K + k0 + c8, true);
        bool ok = (n0 + r) < N;
        cp16(sb + OFF_B * 2 + soff, B + (size_t)(ok ? (n0 + r) : 0) * K + k0 + c8, ok);
    }
}

__global__ void __launch_bounds__(256, 2)
k_gemm_h(const __half* __restrict__ A, const __half* __restrict__ B,
         float* __restrict__ C, int M, int N, int K) {
    extern __shared__ __half smg[];
    const uint32_t smbase = smem_u32(smg);
    const int tid = threadIdx.x, wid = tid >> 5, lid = tid & 31;
    const int m0 = blockIdx.y * 128, n0 = blockIdx.x * 128;
    const int wm = (wid >> 2) * 64;
    const int wn = (wid & 3) * 32;
    const int l15 = lid & 15;

    float acc[4][4][4];
    #pragma unroll
    for (int mi = 0; mi < 4; mi++)
        #pragma unroll
        for (int ni = 0; ni < 4; ni++)
            #pragma unroll
            for (int k = 0; k < 4; k++) acc[mi][ni][k] = 0.f;

    const int la_row = wm + (lid & 15);
    const int la_col = (lid >> 4) * 8;
    const int lb_row = wn + (l15 & 7);
    const int lb_col = ((l15 >> 3) & 1) * 8;

    const int NIT = K / BKH;
    load_stage_h(A, B, smbase, 0, m0, n0, 0, N, K, tid);
    cp_commit();

    for (int it = 0; it < NIT; it++) {
        if (it + 1 < NIT) {
            load_stage_h(A, B, smbase, (it + 1) & 1, m0, n0, (it + 1) * BKH, N, K, tid);
            cp_commit();
            cp_wait<1>();
        } else {
            cp_wait<0>();
        }
        __syncthreads();

        uint32_t sb = smbase + (uint32_t)(it & 1) * (H_STAGE * 2);
        #pragma unroll
        for (int ks = 0; ks < 4; ks++) {
            uint32_t af[4][4], bb[4][2];
            #pragma unroll
            for (int mi = 0; mi < 4; mi++)
                ldm_x4(af[mi], sb + (uint32_t)((la_row + mi * 16) * HS_STR + ks * 16 + la_col) * 2);
            #pragma unroll
            for (int ni = 0; ni < 4; ni++)
                ldm_x2(bb[ni], sb + (uint32_t)(OFF_B + (lb_row + ni * 8) * HS_STR + ks * 16 + lb_col) * 2);
            #pragma unroll
            for (int mi = 0; mi < 4; mi++)
                #pragma unroll
                for (int ni = 0; ni < 4; ni++)
                    mma_f16(acc[mi][ni], af[mi], bb[ni]);
        }
        __syncthreads();
    }

    const int r0 = m0 + wm + (lid >> 2);
    const int c0 = n0 + wn + (lid & 3) * 2;
    #pragma unroll
    for (int mi = 0; mi < 4; mi++) {
        #pragma unroll
        for (int ni = 0; ni < 4; ni++) {
            int col = c0 + ni * 8;
            if (col < N) {
                int row = r0 + mi * 16;
                *(float2*)&C[(size_t)row * N + col] = make_float2(acc[mi][ni][0], acc[mi][ni][1]);
                *(float2*)&C[(size_t)(row + 8) * N + col] = make_float2(acc[mi][ni][2], acc[mi][ni][3]);
            }
        }
    }
}

// ---------------- fp32-exact dt ----------------
__global__ void k_dtfix(const float* __restrict__ x, const float* __restrict__ in_proj_w,
                        const float* __restrict__ dt_bias) {
    __shared__ float xs[64 * 64];
    __shared__ float ws[32 * 65];
    const int tid = threadIdx.x;
    const int h = tid & 31, rg = tid >> 5;
    const int bl0 = blockIdx.x * 64;
    const float* wdt = in_proj_w + (size_t)(DINNER + CDIM) * DMODEL;

    float acc[8];
    #pragma unroll
    for (int i = 0; i < 8; i++) acc[i] = 0.f;

    for (int k0 = 0; k0 < DMODEL; k0 += 64) {
        __syncthreads();
        #pragma unroll
        for (int it = 0; it < 4; it++) {
            int i4 = tid + it * 256;
            int r = i4 >> 4, c4 = (i4 & 15) * 4;
            *(float4*)&xs[r * 64 + c4] = *(const float4*)&x[(size_t)(bl0 + r) * DMODEL + k0 + c4];
        }
        #pragma unroll
        for (int it = 0; it < 2; it++) {
            int i4 = tid + it * 256;
            int r = i4 >> 4, c4 = (i4 & 15) * 4;
            float4 v = *(const float4*)&wdt[(size_t)r * DMODEL + k0 + c4];
            ws[r * 65 + c4 + 0] = v.x; ws[r * 65 + c4 + 1] = v.y;
            ws[r * 65 + c4 + 2] = v.z; ws[r * 65 + c4 + 3] = v.w;
        }
        __syncthreads();
        #pragma unroll 8
        for (int k = 0; k < 64; k++) {
            float w = ws[h * 65 + k];
            #pragma unroll
            for (int i = 0; i < 8; i++)
                acc[i] = fmaf(xs[(rg * 8 + i) * 64 + k], w, acc[i]);
        }
    }
    float bias = dt_bias[h];
    #pragma unroll
    for (int i = 0; i < 8; i++) {
        float raw = acc[i] + bias;
        float sg = 1.f / (1.f + __expf(-raw));
        g_dt[(size_t)(bl0 + rg * 8 + i) * NHEADS + h] = DTMIN + (DTMAX - DTMIN) * sg;
    }
}

// ---------------- conv1d (K=4, causal) + bias + SiLU, 4 channels/thread ----------------
#define CD4 (CDIM / 4)   // 576
__global__ void k_conv(const float* __restrict__ conv_w, const float* __restrict__ conv_b) {
    int idx = blockIdx.x * blockDim.x + threadIdx.x;
    if (idx >= BL * CD4) return;
    int c4 = (idx % CD4) * 4;
    int bl = idx / CD4;
    int l  = bl & (SEQ - 1);
    const float4 w0 = *(const float4*)&conv_w[(c4 + 0) * 4];
    const float4 w1 = *(const float4*)&conv_w[(c4 + 1) * 4];
    const float4 w2 = *(const float4*)&conv_w[(c4 + 2) * 4];
    const float4 w3 = *(const float4*)&conv_w[(c4 + 3) * 4];
    const float4 bias = *(const float4*)&conv_b[c4];
    float4 z = make_float4(0.f, 0.f, 0.f, 0.f);
    float4 v3 = *(const float4*)&g_zxbcdt[(size_t)bl * NIN + DINNER + c4];
    float4 v2 = (l >= 1) ? *(const float4*)&g_zxbcdt[(size_t)(bl - 1) * NIN + DINNER + c4] : z;
    float4 v1 = (l >= 2) ? *(const float4*)&g_zxbcdt[(size_t)(bl - 2) * NIN + DINNER + c4] : z;
    float4 v0 = (l >= 3) ? *(const float4*)&g_zxbcdt[(size_t)(bl - 3) * NIN + DINNER + c4] : z;
    float4 r;
    r.x = bias.x + v0.x * w0.x + v1.x * w0.y + v2.x * w0.z + v3.x * w0.w;
    r.y = bias.y + v0.y * w1.x + v1.y * w1.y + v2.y * w1.z + v3.y * w1.w;
    r.z = bias.z + v0.z * w2.x + v1.z * w2.y + v2.z * w2.z + v3.z * w2.w;
    r.w = bias.w + v0.w * w3.x + v1.w * w3.y + v2.w * w3.z + v3.w * w3.w;
    r.x = silu(r.x); r.y = silu(r.y); r.z = silu(r.z); r.w = silu(r.w);
    *(float4*)&g_xbc[(size_t)bl * CDIM + c4] = r;
}

// ---------------- head-independent CB[q][s] = C_q . B_s per (b,chunk) ----------------
#define BS_STR 132
#define XS_STR 68
#define SMEM_CB_FLOATS (64 * BS_STR * 2)

__global__ void k_cb() {
    extern __shared__ float sm[];
    float* Bs = sm;
    float* Cs = Bs + 64 * BS_STR;
    const int tid = threadIdx.x;
    const int bc = blockIdx.x;
    const int b  = bc / NCH, cc = bc % NCH;
    const long long base_bl = (long long)b * SEQ + (long long)cc * QC;

    #pragma unroll
    for (int it = 0; it < 8; it++) {
        int i4 = tid + it * 256;
        int q = i4 >> 5, n4 = (i4 & 31) * 4;
        *(float4*)&Bs[q * BS_STR + n4] = *(const float4*)&g_xbc[(base_bl + q) * CDIM + DINNER + n4];
        *(float4*)&Cs[q * BS_STR + n4] = *(const float4*)&g_xbc[(base_bl + q) * CDIM + DINNER + DSTATE + n4];
    }
    __syncthreads();

    const int tq0 = (tid >> 4) * 4;
    const int ts0 = (tid & 15) * 4;
    float acc[4][4];
    #pragma unroll
    for (int i = 0; i < 4; i++)
        #pragma unroll
        for (int j = 0; j < 4; j++) acc[i][j] = 0.f;
    #pragma unroll 4
    for (int n = 0; n < DSTATE; n += 4) {
        float4 cq[4], bs[4];
        #pragma unroll
        for (int i = 0; i < 4; i++) cq[i] = *(const float4*)&Cs[(tq0 + i) * BS_STR + n];
        #pragma unroll
        for (int j = 0; j < 4; j++) bs[j] = *(const float4*)&Bs[(ts0 + j) * BS_STR + n];
        #pragma unroll
        for (int i = 0; i < 4; i++)
            #pragma unroll
            for (int j = 0; j < 4; j++) {
                acc[i][j] = fmaf(cq[i].x, bs[j].x, acc[i][j]);
                acc[i][j] = fmaf(cq[i].y, bs[j].y, acc[i][j]);
                acc[i][j] = fmaf(cq[i].z, bs[j].z, acc[i][j]);
                acc[i][j] = fmaf(cq[i].w, bs[j].w, acc[i][j]);
            }
    }
    #pragma unroll
    for (int i = 0; i < 4; i++)
        *(float4*)&g_CB[(size_t)bc * (QC * QC) + (tq0 + i) * QC + ts0] =
            make_float4(acc[i][0], acc[i][1], acc[i][2], acc[i][3]);
}

// ---------------- per-chunk per-head: scale CB, Yd, states, decay ----------------
#define SMEM_CHUNK_FLOATS (64*BS_STR + 64*XS_STR*2 + 64*3)

__global__ void k_chunk(const float* __restrict__ A_log) {
    extern __shared__ float sm[];
    float* Bs   = sm;
    float* xs   = Bs + 64 * BS_STR;
    float* CBL  = xs + 64 * XS_STR;
    float* dt_s = CBL + 64 * XS_STR;
    float* Ac_s = dt_s + 64;
    float* ws   = Ac_s + 64;

    const int tid = threadIdx.x;
    const int bc = blockIdx.x;
    const int h  = blockIdx.y;
    const int b  = bc / NCH, cc = bc % NCH;
    const long long base_bl = (long long)b * SEQ + (long long)cc * QC;

    #pragma unroll
    for (int it = 0; it < 8; it++) {
        int i4 = tid + it * 256;
        int q = i4 >> 5, n4 = (i4 & 31) * 4;
        *(float4*)&Bs[q * BS_STR + n4] = *(const float4*)&g_xbc[(base_bl + q) * CDIM + DINNER + n4];
    }
    #pragma unroll
    for (int it = 0; it < 4; it++) {
        int i4 = tid + it * 256;
        int q = i4 >> 4, p4 = (i4 & 15) * 4;
        *(float4*)&xs[q * XS_STR + p4] = *(const float4*)&g_xbc[(base_bl + q) * CDIM + h * HDIM + p4];
    }
    #pragma unroll
    for (int it = 0; it < 4; it++) {
        int i4 = tid + it * 256;
        int q = i4 >> 4, s4 = (i4 & 15) * 4;
        *(float4*)&CBL[q * XS_STR + s4] = *(const float4*)&g_CB[(size_t)bc * (QC * QC) + q * QC + s4];
    }
    if (tid < QC) dt_s[tid] = g_dt[(base_bl + tid) * NHEADS + h];
    __syncthreads();

    if (tid == 0) {
        float Ah = -__expf(A_log[h]);
        float s = 0.f;
        for (int q = 0; q < QC; q++) { s += dt_s[q] * Ah; Ac_s[q] = s; }
    }
    __syncthreads();

    if (tid < QC) {
        float last = Ac_s[QC - 1];
        ws[tid] = __expf(last - Ac_s[tid]) * dt_s[tid];
        g_Acum[((long long)bc * NHEADS + h) * QC + tid] = Ac_s[tid];
        if (tid == 0) g_cdecay[(long long)bc * NHEADS + h] = __expf(last);
    }

    // scale CBL in place: CBL[q][s] = (s<=q) ? CB*exp(Ac_q - Ac_s)*dt_s : 0
    {
        const int tq0 = (tid >> 4) * 4;
        const int ts0 = (tid & 15) * 4;
        #pragma unroll
        for (int i = 0; i < 4; i++) {
            int q = tq0 + i;
            float eq = Ac_s[q];
            #pragma unroll
            for (int j = 0; j < 4; j++) {
                int s = ts0 + j;
                float val = 0.f;
                if (s <= q) val = CBL[q * XS_STR + s] * __expf(eq - Ac_s[s]) * dt_s[s];
                CBL[q * XS_STR + s] = val;
            }
        }
    }
    __syncthreads();

    // ---- Yd[q][p] = sum_s CBL[q][s] * xs[s][p]
    {
        const int tq0 = (tid >> 4) * 4;
        const int tp0 = (tid & 15) * 4;
        float acc[4][4];
        #pragma unroll
        for (int i = 0; i < 4; i++)
            #pragma unroll
            for (int j = 0; j < 4; j++) acc[i][j] = 0.f;
        #pragma unroll 4
        for (int s = 0; s < QC; s += 4) {
            float4 cb[4], xv[4];
            #pragma unroll
            for (int i = 0; i < 4; i++) cb[i] = *(const float4*)&CBL[(tq0 + i) * XS_STR + s];
            #pragma unroll
            for (int ss = 0; ss < 4; ss++) xv[ss] = *(const float4*)&xs[(s + ss) * XS_STR + tp0];
            #pragma unroll
            for (int i = 0; i < 4; i++) {
                acc[i][0] = fmaf(cb[i].x, xv[0].x, acc[i][0]);
                acc[i][1] = fmaf(cb[i].x, xv[0].y, acc[i][1]);
                acc[i][2] = fmaf(cb[i].x, xv[0].z, acc[i][2]);
                acc[i][3] = fmaf(cb[i].x, xv[0].w, acc[i][3]);
                acc[i][0] = fmaf(cb[i].y, xv[1].x, acc[i][0]);
                acc[i][1] = fmaf(cb[i].y, xv[1].y, acc[i][1]);
                acc[i][2] = fmaf(cb[i].y, xv[1].z, acc[i][2]);
                acc[i][3] = fmaf(cb[i].y, xv[1].w, acc[i][3]);
                acc[i][0] = fmaf(cb[i].z, xv[2].x, acc[i][0]);
                acc[i][1] = fmaf(cb[i].z, xv[2].y, acc[i][1]);
                acc[i][2] = fmaf(cb[i].z, xv[2].z, acc[i][2]);
                acc[i][3] = fmaf(cb[i].z, xv[2].w, acc[i][3]);
                acc[i][0] = fmaf(cb[i].w, xv[3].x, acc[i][0]);
                acc[i][1] = fmaf(cb[i].w, xv[3].y, acc[i][1]);
                acc[i][2] = fmaf(cb[i].w, xv[3].z, acc[i][2]);
                acc[i][3] = fmaf(cb[i].w, xv[3].w, acc[i][3]);
            }
        }
        #pragma unroll
        for (int i = 0; i < 4; i++) {
            int q = tq0 + i;
            *(float4*)&g_Y[(base_bl + q) * DINNER + h * HDIM + tp0] =
                make_float4(acc[i][0], acc[i][1], acc[i][2], acc[i][3]);
        }
    }

    // ---- states[p][n] = sum_q (B[q][n]*ws[q]) * xs[q][p]  -> fp16 store
    {
        const int tp0 = (tid >> 4) * 4;
        const int tn0 = (tid & 15) * 8;
        float acc[4][8];
        #pragma unroll
        for (int i = 0; i < 4; i++)
            #pragma unroll
            for (int j = 0; j < 8; j++) acc[i][j] = 0.f;
        #pragma unroll 4
        for (int q = 0; q < QC; q++) {
            float wq = ws[q];
            float4 xv = *(const float4*)&xs[q * XS_STR + tp0];
            float4 bv0 = *(const float4*)&Bs[q * BS_STR + tn0];
            float4 bv1 = *(const float4*)&Bs[q * BS_STR + tn0 + 4];
            float xw[4] = { xv.x * wq, xv.y * wq, xv.z * wq, xv.w * wq };
            float bb[8] = { bv0.x, bv0.y, bv0.z, bv0.w, bv1.x, bv1.y, bv1.z, bv1.w };
            #pragma unroll
            for (int i = 0; i < 4; i++)
                #pragma unroll
                for (int j = 0; j < 8; j++)
                    acc[i][j] = fmaf(xw[i], bb[j], acc[i][j]);
        }
        long long sbase = ((long long)bc * NHEADS + h) * HDIM * DSTATE;
        #pragma unroll
        for (int i = 0; i < 4; i++) {
            int p = tp0 + i;
            #pragma unroll
            for (int j = 0; j < 8; j += 2)
                *(__half2*)&g_states_h[sbase + (long long)p * DSTATE + tn0 + j] =
                    __floats2half2_rn(acc[i][j], acc[i][j + 1]);
        }
    }
}

// ---------------- parallel inter-chunk scan (half2 per thread) ----------------
__global__ void k_scan() {
    int el2 = blockIdx.x * 256 + threadIdx.x;          // 0 .. BATCH*NHEADS*4096-1
    int bh = el2 >> 12;
    int idx2 = (el2 & 4095) * 2;
    int b = bh >> 5, h = bh & 31;
    float cx = 0.f, cy = 0.f;
    for (int c = 0; c < NCH; c++) {
        long long bcn = ((long long)b * NCH + c) * NHEADS + h;
        float dec = g_cdecay[bcn];
        long long base = bcn * (HDIM * DSTATE) + idx2;
        __half2 st = *(const __half2*)&g_states_h[base];
        *(__half2*)&g_prevs_h[base] = __floats2half2_rn(cx, cy);
        cx = fmaf(dec, cx, __low2float(st));
        cy = fmaf(dec, cy, __high2float(st));
    }
}

// ---------------- Yo + D_skip*x, accumulate into g_Y ----------------
#define SMEM_YO_FLOATS (64*BS_STR*2 + 64)
__global__ void k_yo(const float* __restrict__ D_skip) {
    extern __shared__ float sm[];
    float* Cs = sm;
    float* Pv = Cs + 64 * BS_STR;
    float* eA = Pv + 64 * BS_STR;

    const int tid = threadIdx.x;
    const int bc = blockIdx.x;
    const int h  = blockIdx.y;
    const int b  = bc / NCH, cc = bc % NCH;
    const long long base_bl = (long long)b * SEQ + (long long)cc * QC;
    const long long pbase = ((long long)bc * NHEADS + h) * (HDIM * DSTATE);

    #pragma unroll
    for (int it = 0; it < 8; it++) {
        int i4 = tid + it * 256;
        int r = i4 >> 5, n4 = (i4 & 31) * 4;
        *(float4*)&Cs[r * BS_STR + n4] = *(const float4*)&g_xbc[(base_bl + r) * CDIM + DINNER + DSTATE + n4];
        __half2 p01 = *(const __half2*)&g_prevs_h[pbase + (long long)r * DSTATE + n4];
        __half2 p23 = *(const __half2*)&g_prevs_h[pbase + (long long)r * DSTATE + n4 + 2];
        Pv[r * BS_STR + n4 + 0] = __low2float(p01);
        Pv[r * BS_STR + n4 + 1] = __high2float(p01);
        Pv[r * BS_STR + n4 + 2] = __low2float(p23);
        Pv[r * BS_STR + n4 + 3] = __high2float(p23);
    }
    if (tid < QC) eA[tid] = __expf(g_Acum[((long long)bc * NHEADS + h) * QC + tid]);
    __syncthreads();

    const float dsk = D_skip[h];
    const int tq0 = (tid >> 4) * 4;
    const int tp0 = (tid & 15) * 4;
    float acc[4][4];
    #pragma unroll
    for (int i = 0; i < 4; i++)
        #pragma unroll
        for (int j = 0; j < 4; j++) acc[i][j] = 0.f;
    #pragma unroll 4
    for (int n = 0; n < DSTATE; n += 4) {
        float4 cq[4], pv[4];
        #pragma unroll
        for (int i = 0; i < 4; i++) cq[i] = *(const float4*)&Cs[(tq0 + i) * BS_STR + n];
        #pragma unroll
        for (int j = 0; j < 4; j++) pv[j] = *(const float4*)&Pv[(tp0 + j) * BS_STR + n];
        #pragma unroll
        for (int i = 0; i < 4; i++)
            #pragma unroll
            for (int j = 0; j < 4; j++) {
                acc[i][j] = fmaf(cq[i].x, pv[j].x, acc[i][j]);
                acc[i][j] = fmaf(cq[i].y, pv[j].y, acc[i][j]);
                acc[i][j] = fmaf(cq[i].z, pv[j].z, acc[i][j]);
                acc[i][j] = fmaf(cq[i].w, pv[j].w, acc[i][j]);
            }
    }
    #pragma unroll
    for (int i = 0; i < 4; i++) {
        int q = tq0 + i;
        long long row = base_bl + q;
        float4 yv = *(float4*)&g_Y[row * DINNER + h * HDIM + tp0];
        float4 xv = *(const float4*)&g_xbc[row * CDIM + h * HDIM + tp0];
        float e = eA[q];
        yv.x += e * acc[i][0] + dsk * xv.x;
        yv.y += e * acc[i][1] + dsk * xv.y;
        yv.z += e * acc[i][2] + dsk * xv.z;
        yv.w += e * acc[i][3] + dsk * xv.w;
        *(float4*)&g_Y[row * DINNER + h * HDIM + tp0] = yv;
    }
}

// ---------------- gate with silu(z) + RMSNorm, emit fp16 for gemm2 ----------------
__global__ void k_gate(const float* __restrict__ norm_w) {
    __shared__ float sv[DINNER];
    const long long row = blockIdx.x;
    float local = 0.f;
    for (int i = threadIdx.x; i < DINNER; i += blockDim.x) {
        float yv = g_Y[row * DINNER + i];
        float zv = g_zxbcdt[row * NIN + i];
        float v = yv * silu(zv);
        sv[i] = v;
        local += v * v;
    }
    float tot = block_sum(local);
    float scale = rsqrtf(tot / DINNER + 1e-5f);
    for (int i = threadIdx.x; i < DINNER; i += blockDim.x) {
        float v = sv[i] * scale * norm_w[i];
        g_y_h[row * DINNER + i] = __float2half(v);
    }
}

// ---------------- final LayerNorm + residual ----------------
__global__ void k_ln(const float* __restrict__ x, const float* __restrict__ ln_w,
                     const float* __restrict__ ln_b, float* __restrict__ out) {
    const long long row = blockIdx.x;
    const int t = threadIdx.x;
    float4 o = ((const float4*)&g_out[row * DMODEL])[t];
    float s = o.x + o.y + o.z + o.w;
    float sq = o.x*o.x + o.y*o.y + o.z*o.z + o.w*o.w;
    float sum = block_sum(s);
    float sumsq = block_sum(sq);
    float mu = sum / DMODEL;
    float var = sumsq / DMODEL - mu * mu;
    float rs = rsqrtf(var + 1e-5f);
    float4 xr = ((const float4*)&x[row * DMODEL])[t];
    float4 w = ((const float4*)ln_w)[t];
    float4 bb = ((const float4*)ln_b)[t];
    float4 r;
    r.x = xr.x + (o.x - mu) * rs * w.x + bb.x;
    r.y = xr.y + (o.y - mu) * rs * w.y + bb.y;
    r.z = xr.z + (o.z - mu) * rs * w.z + bb.z;
    r.w = xr.w + (o.w - mu) * rs * w.w + bb.w;
    ((float4*)&out[row * DMODEL])[t] = r;
}

// ---------------- launch ----------------
extern "C" void kernel_launch(void* const* d_in, const int* in_sizes, int n_in,
                              void* d_out, int out_size) {
    const float* x          = (const float*)d_in[0];
    const float* in_proj_w  = (const float*)d_in[1];
    const float* conv_w     = (const float*)d_in[2];
    const float* conv_b     = (const float*)d_in[3];
    const float* dt_bias    = (const float*)d_in[4];
    const float* A_log      = (const float*)d_in[5];
    const float* D_skip     = (const float*)d_in[6];
    const float* norm_w     = (const float*)d_in[7];
    const float* out_proj_w = (const float*)d_in[8];
    const float* ln_w       = (const float*)d_in[9];
    const float* ln_b       = (const float*)d_in[10];
    float* out = (float*)d_out;
    (void)in_sizes; (void)n_in; (void)out_size;

    cudaFuncSetAttribute(k_cb, cudaFuncAttributeMaxDynamicSharedMemorySize,
                         SMEM_CB_FLOATS * (int)sizeof(float));
    cudaFuncSetAttribute(k_chunk, cudaFuncAttributeMaxDynamicSharedMemorySize,
                         SMEM_CHUNK_FLOATS * (int)sizeof(float));
    cudaFuncSetAttribute(k_yo, cudaFuncAttributeMaxDynamicSharedMemorySize,
                         SMEM_YO_FLOATS * (int)sizeof(float));
    cudaFuncSetAttribute(k_gemm_h, cudaFuncAttributeMaxDynamicSharedMemorySize,
                         GEMMH_SMEM_BYTES);

    __half *xh, *w1h, *yh, *w2h;
    float *zx, *go;
    cudaGetSymbolAddress((void**)&xh,  g_x_h);
    cudaGetSymbolAddress((void**)&w1h, g_w1_h);
    cudaGetSymbolAddress((void**)&yh,  g_y_h);
    cudaGetSymbolAddress((void**)&w2h, g_w2_h);
    cudaGetSymbolAddress((void**)&zx,  g_zxbcdt);
    cudaGetSymbolAddress((void**)&go,  g_out);

    // 0) fp16 conversions
    k_cvt_h<<<(int)(((long long)BL * DMODEL / 4 + 255) / 256), 256>>>(x, xh, (long long)BL * DMODEL / 4);
    k_cvt_h<<<(int)(((long long)NIN * DMODEL / 4 + 255) / 256), 256>>>(in_proj_w, w1h, (long long)NIN * DMODEL / 4);
    k_cvt_h<<<(int)(((long long)DMODEL * DINNER / 4 + 255) / 256), 256>>>(out_proj_w, w2h, (long long)DMODEL * DINNER / 4);

    // 1) in_proj GEMM (fp16 HMMA)
    k_gemm_h<<<dim3((NIN + 127) / 128, BL / 128), 256, GEMMH_SMEM_BYTES>>>(
        xh, w1h, zx, BL, NIN, DMODEL);
    // 2) causal conv + SiLU (vectorized)
    k_conv<<<(BL * CD4 + 255) / 256, 256>>>(conv_w, conv_b);
    // 3) fp32-exact dt
    k_dtfix<<<BL / 64, 256>>>(x, in_proj_w, dt_bias);
    // 4a) head-independent CB
    k_cb<<<BATCH * NCH, 256, SMEM_CB_FLOATS * sizeof(float)>>>();
    // 4b) per-chunk per-head work
    k_chunk<<<dim3(BATCH * NCH, NHEADS), 256, SMEM_CHUNK_FLOATS * sizeof(float)>>>(A_log);
    // 5) inter-chunk scan (half2)
    k_scan<<<(BATCH * NHEADS * HDIM * DSTATE / 2) / 256, 256>>>();
    // 6) Yo + skip
    k_yo<<<dim3(BATCH * NCH, NHEADS), 256, SMEM_YO_FLOATS * sizeof(float)>>>(D_skip);
    // 7) gate + rmsnorm (emits fp16)
    k_gate<<<BL, 256>>>(norm_w);
    // 8) out_proj GEMM (fp16 HMMA)
    k_gemm_h<<<dim3(DMODEL / 128, BL / 128), 256, GEMMH_SMEM_BYTES>>>(
        yh, w2h, go, BL, DMODEL, DINNER);
    // 9) LayerNorm + residual
    k_ln<<<BL, 256>>>(x, ln_w, ln_b, out);
}

// round 15
// speedup vs baseline: 5.1970x; 1.4727x over previous
#include <cuda_runtime.h>
#include <cuda_bf16.h>
#include <cuda_fp16.h>
#include <cstdint>

// ---------------- problem constants ----------------
#define BATCH  2
#define SEQ    4096
#define DMODEL 1024
#define DINNER 2048
#define DSTATE 128
#define NHEADS 32
#define HDIM   64
#define CDIM   2304        // DINNER + 2*DSTATE
#define NIN    4384        // 2*DINNER + 2*DSTATE + NHEADS
#define QC     64          // chunk length
#define NCH    64          // SEQ / QC
#define BL     8192        // BATCH * SEQ
#define DTMIN  0.001f
#define DTMAX  0.1f

// ---------------- scratch (device globals; no allocs allowed) ----------------
__device__ float g_zxbcdt[(size_t)BL * NIN];       // in_proj output
__device__ float g_xbc[(size_t)BL * CDIM];         // conv+silu output (x_ssm | B | C)
__device__ float g_dt[(size_t)BL * NHEADS];        // dt after sigmoid mapping (fp32-exact)
__device__ float g_Acum[(size_t)BATCH * NCH * NHEADS * QC];
__device__ float g_cdecay[(size_t)BATCH * NCH * NHEADS];
__device__ float g_CB[(size_t)BATCH * NCH * QC * QC];     // head-independent C.B (fp32)
__device__ __half g_states_h[(size_t)BATCH * NCH * NHEADS * HDIM * DSTATE];
__device__ __half g_prevs_h [(size_t)BATCH * NCH * NHEADS * HDIM * DSTATE];
__device__ float g_Y[(size_t)BL * DINNER];         // Yd then += Yo + skip
__device__ float g_out[(size_t)BL * DMODEL];       // out_proj output (pre-LN)

// fp16 operands for tensor-core GEMMs
__device__ __half g_x_h [(size_t)BL * DMODEL];
__device__ __half g_w1_h[(size_t)NIN * DMODEL];
__device__ __half g_y_h [(size_t)BL * DINNER];
__device__ __half g_w2_h[(size_t)DMODEL * DINNER];

// ---------------- helpers ----------------
__device__ __forceinline__ float block_sum(float v) {
    __shared__ float sh[32];
    __syncthreads();
    int lane = threadIdx.x & 31, wid = threadIdx.x >> 5;
    #pragma unroll
    for (int o = 16; o > 0; o >>= 1) v += __shfl_xor_sync(0xffffffffu, v, o);
    if (lane == 0) sh[wid] = v;
    __syncthreads();
    float r = (threadIdx.x < (blockDim.x >> 5)) ? sh[threadIdx.x] : 0.f;
    if (wid == 0) {
        #pragma unroll
        for (int o = 16; o > 0; o >>= 1) r += __shfl_xor_sync(0xffffffffu, r, o);
        if (lane == 0) sh[0] = r;
    }
    __syncthreads();
    return sh[0];
}

__device__ __forceinline__ float silu(float x) { return x / (1.f + __expf(-x)); }

__device__ __forceinline__ uint32_t smem_u32(const void* p) {
    uint32_t a;
    asm("{ .reg .u64 t; cvta.to.shared.u64 t, %1; cvt.u32.u64 %0, t; }" : "=r"(a) : "l"(p));
    return a;
}

// ---------------- portable async-copy / ldmatrix / mma wrappers ----------------
__device__ __forceinline__ void cp16(uint32_t dst, const void* src, bool pred) {
    int sz = pred ? 16 : 0;
    asm volatile("cp.async.cg.shared.global [%0], [%1], 16, %2;\n"
                 :: "r"(dst), "l"(src), "r"(sz) : "memory");
}
__device__ __forceinline__ void cp_commit() {
    asm volatile("cp.async.commit_group;" ::: "memory");
}
template <int N>
__device__ __forceinline__ void cp_wait() {
    asm volatile("cp.async.wait_group %0;" :: "n"(N) : "memory");
}
__device__ __forceinline__ void ldm_x4(uint32_t* r, uint32_t addr) {
    asm volatile("ldmatrix.sync.aligned.m8n8.x4.shared.b16 {%0,%1,%2,%3}, [%4];"
                 : "=r"(r[0]), "=r"(r[1]), "=r"(r[2]), "=r"(r[3]) : "r"(addr));
}
__device__ __forceinline__ void ldm_x2(uint32_t* r, uint32_t addr) {
    asm volatile("ldmatrix.sync.aligned.m8n8.x2.shared.b16 {%0,%1}, [%2];"
                 : "=r"(r[0]), "=r"(r[1]) : "r"(addr));
}
__device__ __forceinline__ void ldm_x4_t(uint32_t* r, uint32_t addr) {
    asm volatile("ldmatrix.sync.aligned.m8n8.x4.trans.shared.b16 {%0,%1,%2,%3}, [%4];"
                 : "=r"(r[0]), "=r"(r[1]), "=r"(r[2]), "=r"(r[3]) : "r"(addr));
}
__device__ __forceinline__ void ldm_x2_t(uint32_t* r, uint32_t addr) {
    asm volatile("ldmatrix.sync.aligned.m8n8.x2.trans.shared.b16 {%0,%1}, [%2];"
                 : "=r"(r[0]), "=r"(r[1]) : "r"(addr));
}
__device__ __forceinline__ void mma_f16(float* d, const uint32_t* a, const uint32_t* b) {
    asm volatile("mma.sync.aligned.m16n8k16.row.col.f32.f16.f16.f32 "
                 "{%0,%1,%2,%3}, {%4,%5,%6,%7}, {%8,%9}, {%0,%1,%2,%3};"
                 : "+f"(d[0]), "+f"(d[1]), "+f"(d[2]), "+f"(d[3])
                 : "r"(a[0]), "r"(a[1]), "r"(a[2]), "r"(a[3]), "r"(b[0]), "r"(b[1]));
}

// ---------------- fp32 -> fp16 convert ----------------
__global__ void k_cvt_h(const float* __restrict__ in, __half* __restrict__ out, long long n4) {
    long long i = (long long)blockIdx.x * blockDim.x + threadIdx.x;
    if (i >= n4) return;
    float4 v = ((const float4*)in)[i];
    ((__half2*)out)[i * 2 + 0] = __floats2half2_rn(v.x, v.y);
    ((__half2*)out)[i * 2 + 1] = __floats2half2_rn(v.z, v.w);
}

// ---------------- fp16 HMMA GEMM: C[M,N] = A[M,K] * B[N,K]^T ----------------
#define BKH    64
#define HS_STR 72
#define H_TILE (128 * HS_STR)
#define OFF_B  H_TILE
#define H_STAGE (2 * H_TILE)
#define GEMMH_SMEM_BYTES (2 * H_STAGE * 2) // 73728

__device__ __forceinline__ void load_stage_h(
    const __half* __restrict__ A, const __half* __restrict__ B,
    uint32_t smbase, int stage, int m0, int n0, int k0, int N, int K, int tid)
{
    uint32_t sb = smbase + (uint32_t)stage * (H_STAGE * 2);
    #pragma unroll
    for (int j = 0; j < 4; j++) {
        int c = tid + j * 256;
        int r = c >> 3, c8 = (c & 7) * 8;
        uint32_t soff = (uint32_t)(r * HS_STR + c8) * 2;
        cp16(sb + soff, A + (size_t)(m0 + r) * K + k0 + c8, true);
        bool ok = (n0 + r) < N;
        cp16(sb + OFF_B * 2 + soff, B + (size_t)(ok ? (n0 + r) : 0) * K + k0 + c8, ok);
    }
}

__global__ void __launch_bounds__(256, 2)
k_gemm_h(const __half* __restrict__ A, const __half* __restrict__ B,
         float* __restrict__ C, int M, int N, int K) {
    extern __shared__ __half smg[];
    const uint32_t smbase = smem_u32(smg);
    const int tid = threadIdx.x, wid = tid >> 5, lid = tid & 31;
    const int m0 = blockIdx.y * 128, n0 = blockIdx.x * 128;
    const int wm = (wid >> 2) * 64;
    const int wn = (wid & 3) * 32;
    const int l15 = lid & 15;

    float acc[4][4][4];
    #pragma unroll
    for (int mi = 0; mi < 4; mi++)
        #pragma unroll
        for (int ni = 0; ni < 4; ni++)
            #pragma unroll
            for (int k = 0; k < 4; k++) acc[mi][ni][k] = 0.f;

    const int la_row = wm + (lid & 15);
    const int la_col = (lid >> 4) * 8;
    const int lb_row = wn + (l15 & 7);
    const int lb_col = ((l15 >> 3) & 1) * 8;

    const int NIT = K / BKH;
    load_stage_h(A, B, smbase, 0, m0, n0, 0, N, K, tid);
    cp_commit();

    for (int it = 0; it < NIT; it++) {
        if (it + 1 < NIT) {
            load_stage_h(A, B, smbase, (it + 1) & 1, m0, n0, (it + 1) * BKH, N, K, tid);
            cp_commit();
            cp_wait<1>();
        } else {
            cp_wait<0>();
        }
        __syncthreads();

        uint32_t sb = smbase + (uint32_t)(it & 1) * (H_STAGE * 2);
        #pragma unroll
        for (int ks = 0; ks < 4; ks++) {
            uint32_t af[4][4], bb[4][2];
            #pragma unroll
            for (int mi = 0; mi < 4; mi++)
                ldm_x4(af[mi], sb + (uint32_t)((la_row + mi * 16) * HS_STR + ks * 16 + la_col) * 2);
            #pragma unroll
            for (int ni = 0; ni < 4; ni++)
                ldm_x2(bb[ni], sb + (uint32_t)(OFF_B + (lb_row + ni * 8) * HS_STR + ks * 16 + lb_col) * 2);
            #pragma unroll
            for (int mi = 0; mi < 4; mi++)
                #pragma unroll
                for (int ni = 0; ni < 4; ni++)
                    mma_f16(acc[mi][ni], af[mi], bb[ni]);
        }
        __syncthreads();
    }

    const int r0 = m0 + wm + (lid >> 2);
    const int c0 = n0 + wn + (lid & 3) * 2;
    #pragma unroll
    for (int mi = 0; mi < 4; mi++) {
        #pragma unroll
        for (int ni = 0; ni < 4; ni++) {
            int col = c0 + ni * 8;
            if (col < N) {
                int row = r0 + mi * 16;
                *(float2*)&C[(size_t)row * N + col] = make_float2(acc[mi][ni][0], acc[mi][ni][1]);
                *(float2*)&C[(size_t)(row + 8) * N + col] = make_float2(acc[mi][ni][2], acc[mi][ni][3]);
            }
        }
    }
}

// ---------------- fp32-exact dt ----------------
__global__ void k_dtfix(const float* __restrict__ x, const float* __restrict__ in_proj_w,
                        const float* __restrict__ dt_bias) {
    __shared__ float xs[64 * 64];
    __shared__ float ws[32 * 65];
    const int tid = threadIdx.x;
    const int h = tid & 31, rg = tid >> 5;
    const int bl0 = blockIdx.x * 64;
    const float* wdt = in_proj_w + (size_t)(DINNER + CDIM) * DMODEL;

    float acc[8];
    #pragma unroll
    for (int i = 0; i < 8; i++) acc[i] = 0.f;

    for (int k0 = 0; k0 < DMODEL; k0 += 64) {
        __syncthreads();
        #pragma unroll
        for (int it = 0; it < 4; it++) {
            int i4 = tid + it * 256;
            int r = i4 >> 4, c4 = (i4 & 15) * 4;
            *(float4*)&xs[r * 64 + c4] = *(const float4*)&x[(size_t)(bl0 + r) * DMODEL + k0 + c4];
        }
        #pragma unroll
        for (int it = 0; it < 2; it++) {
            int i4 = tid + it * 256;
            int r = i4 >> 4, c4 = (i4 & 15) * 4;
            float4 v = *(const float4*)&wdt[(size_t)r * DMODEL + k0 + c4];
            ws[r * 65 + c4 + 0] = v.x; ws[r * 65 + c4 + 1] = v.y;
            ws[r * 65 + c4 + 2] = v.z; ws[r * 65 + c4 + 3] = v.w;
        }
        __syncthreads();
        #pragma unroll 8
        for (int k = 0; k < 64; k++) {
            float w = ws[h * 65 + k];
            #pragma unroll
            for (int i = 0; i < 8; i++)
                acc[i] = fmaf(xs[(rg * 8 + i) * 64 + k], w, acc[i]);
        }
    }
    float bias = dt_bias[h];
    #pragma unroll
    for (int i = 0; i < 8; i++) {
        float raw = acc[i] + bias;
        float sg = 1.f / (1.f + __expf(-raw));
        g_dt[(size_t)(bl0 + rg * 8 + i) * NHEADS + h] = DTMIN + (DTMAX - DTMIN) * sg;
    }
}

// ---------------- conv1d (K=4, causal) + bias + SiLU, 4 channels/thread ----------------
#define CD4 (CDIM / 4)   // 576
__global__ void k_conv(const float* __restrict__ conv_w, const float* __restrict__ conv_b) {
    int idx = blockIdx.x * blockDim.x + threadIdx.x;
    if (idx >= BL * CD4) return;
    int c4 = (idx % CD4) * 4;
    int bl = idx / CD4;
    int l  = bl & (SEQ - 1);
    const float4 w0 = *(const float4*)&conv_w[(c4 + 0) * 4];
    const float4 w1 = *(const float4*)&conv_w[(c4 + 1) * 4];
    const float4 w2 = *(const float4*)&conv_w[(c4 + 2) * 4];
    const float4 w3 = *(const float4*)&conv_w[(c4 + 3) * 4];
    const float4 bias = *(const float4*)&conv_b[c4];
    float4 z = make_float4(0.f, 0.f, 0.f, 0.f);
    float4 v3 = *(const float4*)&g_zxbcdt[(size_t)bl * NIN + DINNER + c4];
    float4 v2 = (l >= 1) ? *(const float4*)&g_zxbcdt[(size_t)(bl - 1) * NIN + DINNER + c4] : z;
    float4 v1 = (l >= 2) ? *(const float4*)&g_zxbcdt[(size_t)(bl - 2) * NIN + DINNER + c4] : z;
    float4 v0 = (l >= 3) ? *(const float4*)&g_zxbcdt[(size_t)(bl - 3) * NIN + DINNER + c4] : z;
    float4 r;
    r.x = bias.x + v0.x * w0.x + v1.x * w0.y + v2.x * w0.z + v3.x * w0.w;
    r.y = bias.y + v0.y * w1.x + v1.y * w1.y + v2.y * w1.z + v3.y * w1.w;
    r.z = bias.z + v0.z * w2.x + v1.z * w2.y + v2.z * w2.z + v3.z * w2.w;
    r.w = bias.w + v0.w * w3.x + v1.w * w3.y + v2.w * w3.z + v3.w * w3.w;
    r.x = silu(r.x); r.y = silu(r.y); r.z = silu(r.z); r.w = silu(r.w);
    *(float4*)&g_xbc[(size_t)bl * CDIM + c4] = r;
}

// ---------------- head-independent CB[q][s] = C_q . B_s per (b,chunk) (fp32) ----------------
#define BS_STR 132
#define SMEM_CB_FLOATS (64 * BS_STR * 2)

__global__ void k_cb() {
    extern __shared__ float sm[];
    float* Bs = sm;
    float* Cs = Bs + 64 * BS_STR;
    const int tid = threadIdx.x;
    const int bc = blockIdx.x;
    const int b  = bc / NCH, cc = bc % NCH;
    const long long base_bl = (long long)b * SEQ + (long long)cc * QC;

    #pragma unroll
    for (int it = 0; it < 8; it++) {
        int i4 = tid + it * 256;
        int q = i4 >> 5, n4 = (i4 & 31) * 4;
        *(float4*)&Bs[q * BS_STR + n4] = *(const float4*)&g_xbc[(base_bl + q) * CDIM + DINNER + n4];
        *(float4*)&Cs[q * BS_STR + n4] = *(const float4*)&g_xbc[(base_bl + q) * CDIM + DINNER + DSTATE + n4];
    }
    __syncthreads();

    const int tq0 = (tid >> 4) * 4;
    const int ts0 = (tid & 15) * 4;
    float acc[4][4];
    #pragma unroll
    for (int i = 0; i < 4; i++)
        #pragma unroll
        for (int j = 0; j < 4; j++) acc[i][j] = 0.f;
    #pragma unroll 4
    for (int n = 0; n < DSTATE; n += 4) {
        float4 cq[4], bs[4];
        #pragma unroll
        for (int i = 0; i < 4; i++) cq[i] = *(const float4*)&Cs[(tq0 + i) * BS_STR + n];
        #pragma unroll
        for (int j = 0; j < 4; j++) bs[j] = *(const float4*)&Bs[(ts0 + j) * BS_STR + n];
        #pragma unroll
        for (int i = 0; i < 4; i++)
            #pragma unroll
            for (int j = 0; j < 4; j++) {
                acc[i][j] = fmaf(cq[i].x, bs[j].x, acc[i][j]);
                acc[i][j] = fmaf(cq[i].y, bs[j].y, acc[i][j]);
                acc[i][j] = fmaf(cq[i].z, bs[j].z, acc[i][j]);
                acc[i][j] = fmaf(cq[i].w, bs[j].w, acc[i][j]);
            }
    }
    #pragma unroll
    for (int i = 0; i < 4; i++)
        *(float4*)&g_CB[(size_t)bc * (QC * QC) + (tq0 + i) * QC + ts0] =
            make_float4(acc[i][0], acc[i][1], acc[i][2], acc[i][3]);
}

// ---------------- per-chunk per-head via HMMA: Yd + states ----------------
// strides in halves: must be mult of 8 (16B align) and !=0 mod 64 for bank spread
#define XSH 72     // 144 B rows
#define BSH 136    // 272 B rows

__global__ void __launch_bounds__(256) k_chunk(const float* __restrict__ A_log) {
    __shared__ __half xsh[64 * XSH];    // x tile [q][p]
    __shared__ __half Bsh[64 * BSH];    // ws-scaled B tile [q][n]
    __shared__ __half CBLh[64 * XSH];   // masked/scaled CB [q][s]
    __shared__ float dt_s[64], Ac_s[64], ws_s[64];

    const int tid = threadIdx.x;
    const int bc = blockIdx.x, h = blockIdx.y;
    const int b = bc / NCH, cc = bc % NCH;
    const long long base_bl = (long long)b * SEQ + (long long)cc * QC;

    // x tile -> fp16
    #pragma unroll
    for (int it = 0; it < 4; it++) {
        int i4 = tid + it * 256;
        int q = i4 >> 4, p4 = (i4 & 15) * 4;
        float4 v = *(const float4*)&g_xbc[(base_bl + q) * CDIM + h * HDIM + p4];
        *(__half2*)&xsh[q * XSH + p4]     = __floats2half2_rn(v.x, v.y);
        *(__half2*)&xsh[q * XSH + p4 + 2] = __floats2half2_rn(v.z, v.w);
    }
    // stage B tile in regs (scaled by ws later)
    float4 breg[8];
    #pragma unroll
    for (int it = 0; it < 8; it++) {
        int i4 = tid + it * 256;
        int q = i4 >> 5, n4 = (i4 & 31) * 4;
        breg[it] = *(const float4*)&g_xbc[(base_bl + q) * CDIM + DINNER + n4];
    }
    if (tid < QC) dt_s[tid] = g_dt[(base_bl + tid) * NHEADS + h];
    __syncthreads();

    if (tid == 0) {
        float Ah = -__expf(A_log[h]);
        float s = 0.f;
        for (int q = 0; q < QC; q++) { s += dt_s[q] * Ah; Ac_s[q] = s; }
    }
    __syncthreads();

    if (tid < QC) {
        float last = Ac_s[QC - 1];
        ws_s[tid] = __expf(last - Ac_s[tid]) * dt_s[tid];
        g_Acum[((long long)bc * NHEADS + h) * QC + tid] = Ac_s[tid];
        if (tid == 0) g_cdecay[(long long)bc * NHEADS + h] = __expf(last);
    }
    // CBL -> fp16 (needs Ac_s, dt_s)
    #pragma unroll
    for (int it = 0; it < 4; it++) {
        int i4 = tid + it * 256;
        int q = i4 >> 4, s4 = (i4 & 15) * 4;
        float4 cb = *(const float4*)&g_CB[(size_t)bc * (QC * QC) + q * QC + s4];
        float eq = Ac_s[q];
        float v0 = (s4 + 0 <= q) ? cb.x * __expf(eq - Ac_s[s4 + 0]) * dt_s[s4 + 0] : 0.f;
        float v1 = (s4 + 1 <= q) ? cb.y * __expf(eq - Ac_s[s4 + 1]) * dt_s[s4 + 1] : 0.f;
        float v2 = (s4 + 2 <= q) ? cb.z * __expf(eq - Ac_s[s4 + 2]) * dt_s[s4 + 2] : 0.f;
        float v3 = (s4 + 3 <= q) ? cb.w * __expf(eq - Ac_s[s4 + 3]) * dt_s[s4 + 3] : 0.f;
        *(__half2*)&CBLh[q * XSH + s4]     = __floats2half2_rn(v0, v1);
        *(__half2*)&CBLh[q * XSH + s4 + 2] = __floats2half2_rn(v2, v3);
    }
    __syncthreads();   // ws_s visible

    // Bsh = ws[q] * B[q][n] -> fp16
    #pragma unroll
    for (int it = 0; it < 8; it++) {
        int i4 = tid + it * 256;
        int q = i4 >> 5, n4 = (i4 & 31) * 4;
        float w = ws_s[q];
        *(__half2*)&Bsh[q * BSH + n4]     = __floats2half2_rn(breg[it].x * w, breg[it].y * w);
        *(__half2*)&Bsh[q * BSH + n4 + 2] = __floats2half2_rn(breg[it].z * w, breg[it].w * w);
    }
    __syncthreads();

    const int w = tid >> 5, lid = tid & 31;
    const uint32_t xb = smem_u32(xsh), cbb = smem_u32(CBLh), bbb = smem_u32(Bsh);

    // ---- Yd[q][p] = CBL x xs : A = CBLh row-major, B = xsh ([s][p]) via trans
    {
        const int m0 = (w >> 1) * 16;
        const int nb = (w & 1) * 32;
        float acc[4][4];
        #pragma unroll
        for (int i = 0; i < 4; i++)
            #pragma unroll
            for (int j = 0; j < 4; j++) acc[i][j] = 0.f;
        const uint32_t a_base = cbb + (uint32_t)((m0 + (lid & 15)) * XSH + (lid >> 4) * 8) * 2;
        const int bk = (lid & 7) + ((lid >> 3) & 1) * 8;
        #pragma unroll
        for (int ks = 0; ks < 4; ks++) {
            uint32_t a[4];
            ldm_x4(a, a_base + ks * 32);
            #pragma unroll
            for (int ni = 0; ni < 4; ni++) {
                uint32_t bf[2];
                ldm_x2_t(bf, xb + (uint32_t)((ks * 16 + bk) * XSH + nb + ni * 8) * 2);
                mma_f16(acc[ni], a, bf);
            }
        }
        int q = m0 + (lid >> 2), p0 = nb + (lid & 3) * 2;
        #pragma unroll
        for (int ni = 0; ni < 4; ni++) {
            *(float2*)&g_Y[(base_bl + q) * DINNER + h * HDIM + p0 + ni * 8] =
                make_float2(acc[ni][0], acc[ni][1]);
            *(float2*)&g_Y[(base_bl + q + 8) * DINNER + h * HDIM + p0 + ni * 8] =
                make_float2(acc[ni][2], acc[ni][3]);
        }
    }

    // ---- states[p][n] = (x.ws)^T x B : A = xsh trans ([q][p]), B = Bsh trans ([q][n])
    {
        const int m0 = (w >> 1) * 16;       // p tile
        const int nb = (w & 1) * 64;        // n base
        float acc[8][4];
        #pragma unroll
        for (int i = 0; i < 8; i++)
            #pragma unroll
            for (int j = 0; j < 4; j++) acc[i][j] = 0.f;
        const int ak = (lid & 7) + ((lid >> 4) & 1) * 8;
        const int am = m0 + ((lid >> 3) & 1) * 8;
        const int bk = (lid & 7) + ((lid >> 3) & 1) * 8;
        #pragma unroll
        for (int ks = 0; ks < 4; ks++) {
            uint32_t a[4];
            ldm_x4_t(a, xb + (uint32_t)((ks * 16 + ak) * XSH + am) * 2);
            #pragma unroll
            for (int ni = 0; ni < 8; ni++) {
                uint32_t bf[2];
                ldm_x2_t(bf, bbb + (uint32_t)((ks * 16 + bk) * BSH + nb + ni * 8) * 2);
                mma_f16(acc[ni], a, bf);
            }
        }
        long long sbase = ((long long)bc * NHEADS + h) * HDIM * DSTATE;
        int p = m0 + (lid >> 2), n0 = nb + (lid & 3) * 2;
        #pragma unroll
        for (int ni = 0; ni < 8; ni++) {
            *(__half2*)&g_states_h[sbase + (long long)p * DSTATE + n0 + ni * 8] =
                __floats2half2_rn(acc[ni][0], acc[ni][1]);
            *(__half2*)&g_states_h[sbase + (long long)(p + 8) * DSTATE + n0 + ni * 8] =
                __floats2half2_rn(acc[ni][2], acc[ni][3]);
        }
    }
}

// ---------------- parallel inter-chunk scan (half2 per thread) ----------------
__global__ void k_scan() {
    int el2 = blockIdx.x * 256 + threadIdx.x;
    int bh = el2 >> 12;
    int idx2 = (el2 & 4095) * 2;
    int b = bh >> 5, h = bh & 31;
    float cx = 0.f, cy = 0.f;
    for (int c = 0; c < NCH; c++) {
        long long bcn = ((long long)b * NCH + c) * NHEADS + h;
        float dec = g_cdecay[bcn];
        long long base = bcn * (HDIM * DSTATE) + idx2;
        __half2 st = *(const __half2*)&g_states_h[base];
        *(__half2*)&g_prevs_h[base] = __floats2half2_rn(cx, cy);
        cx = fmaf(dec, cx, __low2float(st));
        cy = fmaf(dec, cy, __high2float(st));
    }
}

// ---------------- Yo via HMMA + D_skip*x, accumulate into g_Y ----------------
__global__ void __launch_bounds__(256) k_yo(const float* __restrict__ D_skip) {
    __shared__ __half Csh[64 * BSH];   // C tile [q][n]
    __shared__ __half Pvh[64 * BSH];   // prevs [p][n]
    __shared__ float eA[64];

    const int tid = threadIdx.x;
    const int bc = blockIdx.x, h = blockIdx.y;
    const int b = bc / NCH, cc = bc % NCH;
    const long long base_bl = (long long)b * SEQ + (long long)cc * QC;
    const long long pbase = ((long long)bc * NHEADS + h) * (HDIM * DSTATE);

    #pragma unroll
    for (int it = 0; it < 8; it++) {
        int i4 = tid + it * 256;
        int r = i4 >> 5, n4 = (i4 & 31) * 4;
        float4 c = *(const float4*)&g_xbc[(base_bl + r) * CDIM + DINNER + DSTATE + n4];
        *(__half2*)&Csh[r * BSH + n4]     = __floats2half2_rn(c.x, c.y);
        *(__half2*)&Csh[r * BSH + n4 + 2] = __floats2half2_rn(c.z, c.w);
        *(uint2*)&Pvh[r * BSH + n4] = *(const uint2*)&g_prevs_h[pbase + (long long)r * DSTATE + n4];
    }
    if (tid < QC) eA[tid] = __expf(g_Acum[((long long)bc * NHEADS + h) * QC + tid]);
    __syncthreads();

    const float dsk = D_skip[h];
    const int w = tid >> 5, lid = tid & 31;
    const int m0 = (w >> 1) * 16;       // q tile
    const int nb = (w & 1) * 32;        // p base
    const uint32_t cbm = smem_u32(Csh), pbm = smem_u32(Pvh);

    float acc[4][4];
    #pragma unroll
    for (int i = 0; i < 4; i++)
        #pragma unroll
        for (int j = 0; j < 4; j++) acc[i][j] = 0.f;

    const uint32_t a_base = cbm + (uint32_t)((m0 + (lid & 15)) * BSH + (lid >> 4) * 8) * 2;
    const int brow = lid & 7;
    const int bcol = ((lid >> 3) & 1) * 8;
    #pragma unroll
    for (int ks = 0; ks < 8; ks++) {
        uint32_t a[4];
        ldm_x4(a, a_base + ks * 32);
        #pragma unroll
        for (int ni = 0; ni < 4; ni++) {
            uint32_t bf[2];
            ldm_x2(bf, pbm + (uint32_t)((nb + ni * 8 + brow) * BSH + ks * 16 + bcol) * 2);
            mma_f16(acc[ni], a, bf);
        }
    }

    int q = m0 + (lid >> 2), p0 = nb + (lid & 3) * 2;
    float e0 = eA[q], e1 = eA[q + 8];
    #pragma unroll
    for (int ni = 0; ni < 4; ni++) {
        int p = p0 + ni * 8;
        long long r0 = base_bl + q, r1 = base_bl + q + 8;
        float2 y0 = *(float2*)&g_Y[r0 * DINNER + h * HDIM + p];
        float2 x0 = *(const float2*)&g_xbc[r0 * CDIM + h * HDIM + p];
        y0.x += e0 * acc[ni][0] + dsk * x0.x;
        y0.y += e0 * acc[ni][1] + dsk * x0.y;
        *(float2*)&g_Y[r0 * DINNER + h * HDIM + p] = y0;
        float2 y1 = *(float2*)&g_Y[r1 * DINNER + h * HDIM + p];
        float2 x1 = *(const float2*)&g_xbc[r1 * CDIM + h * HDIM + p];
        y1.x += e1 * acc[ni][2] + dsk * x1.x;
        y1.y += e1 * acc[ni][3] + dsk * x1.y;
        *(float2*)&g_Y[r1 * DINNER + h * HDIM + p] = y1;
    }
}

// ---------------- gate with silu(z) + RMSNorm, emit fp16 for gemm2 ----------------
__global__ void k_gate(const float* __restrict__ norm_w) {
    __shared__ float sv[DINNER];
    const long long row = blockIdx.x;
    float local = 0.f;
    for (int i = threadIdx.x; i < DINNER; i += blockDim.x) {
        float yv = g_Y[row * DINNER + i];
        float zv = g_zxbcdt[row * NIN + i];
        float v = yv * silu(zv);
        sv[i] = v;
        local += v * v;
    }
    float tot = block_sum(local);
    float scale = rsqrtf(tot / DINNER + 1e-5f);
    for (int i = threadIdx.x; i < DINNER; i += blockDim.x) {
        float v = sv[i] * scale * norm_w[i];
        g_y_h[row * DINNER + i] = __float2half(v);
    }
}

// ---------------- final LayerNorm + residual ----------------
__global__ void k_ln(const float* __restrict__ x, const float* __restrict__ ln_w,
                     const float* __restrict__ ln_b, float* __restrict__ out) {
    const long long row = blockIdx.x;
    const int t = threadIdx.x;
    float4 o = ((const float4*)&g_out[row * DMODEL])[t];
    float s = o.x + o.y + o.z + o.w;
    float sq = o.x*o.x + o.y*o.y + o.z*o.z + o.w*o.w;
    float sum = block_sum(s);
    float sumsq = block_sum(sq);
    float mu = sum / DMODEL;
    float var = sumsq / DMODEL - mu * mu;
    float rs = rsqrtf(var + 1e-5f);
    float4 xr = ((const float4*)&x[row * DMODEL])[t];
    float4 w = ((const float4*)ln_w)[t];
    float4 bb = ((const float4*)ln_b)[t];
    float4 r;
    r.x = xr.x + (o.x - mu) * rs * w.x + bb.x;
    r.y = xr.y + (o.y - mu) * rs * w.y + bb.y;
    r.z = xr.z + (o.z - mu) * rs * w.z + bb.z;
    r.w = xr.w + (o.w - mu) * rs * w.w + bb.w;
    ((float4*)&out[row * DMODEL])[t] = r;
}

// ---------------- launch ----------------
extern "C" void kernel_launch(void* const* d_in, const int* in_sizes, int n_in,
                              void* d_out, int out_size) {
    const float* x          = (const float*)d_in[0];
    const float* in_proj_w  = (const float*)d_in[1];
    const float* conv_w     = (const float*)d_in[2];
    const float* conv_b     = (const float*)d_in[3];
    const float* dt_bias    = (const float*)d_in[4];
    const float* A_log      = (const float*)d_in[5];
    const float* D_skip     = (const float*)d_in[6];
    const float* norm_w     = (const float*)d_in[7];
    const float* out_proj_w = (const float*)d_in[8];
    const float* ln_w       = (const float*)d_in[9];
    const float* ln_b       = (const float*)d_in[10];
    float* out = (float*)d_out;
    (void)in_sizes; (void)n_in; (void)out_size;

    cudaFuncSetAttribute(k_cb, cudaFuncAttributeMaxDynamicSharedMemorySize,
                         SMEM_CB_FLOATS * (int)sizeof(float));
    cudaFuncSetAttribute(k_gemm_h, cudaFuncAttributeMaxDynamicSharedMemorySize,
                         GEMMH_SMEM_BYTES);

    __half *xh, *w1h, *yh, *w2h;
    float *zx, *go;
    cudaGetSymbolAddress((void**)&xh,  g_x_h);
    cudaGetSymbolAddress((void**)&w1h, g_w1_h);
    cudaGetSymbolAddress((void**)&yh,  g_y_h);
    cudaGetSymbolAddress((void**)&w2h, g_w2_h);
    cudaGetSymbolAddress((void**)&zx,  g_zxbcdt);
    cudaGetSymbolAddress((void**)&go,  g_out);

    // 0) fp16 conversions
    k_cvt_h<<<(int)(((long long)BL * DMODEL / 4 + 255) / 256), 256>>>(x, xh, (long long)BL * DMODEL / 4);
    k_cvt_h<<<(int)(((long long)NIN * DMODEL / 4 + 255) / 256), 256>>>(in_proj_w, w1h, (long long)NIN * DMODEL / 4);
    k_cvt_h<<<(int)(((long long)DMODEL * DINNER / 4 + 255) / 256), 256>>>(out_proj_w, w2h, (long long)DMODEL * DINNER / 4);

    // 1) in_proj GEMM (fp16 HMMA)
    k_gemm_h<<<dim3((NIN + 127) / 128, BL / 128), 256, GEMMH_SMEM_BYTES>>>(
        xh, w1h, zx, BL, NIN, DMODEL);
    // 2) causal conv + SiLU
    k_conv<<<(BL * CD4 + 255) / 256, 256>>>(conv_w, conv_b);
    // 3) fp32-exact dt
    k_dtfix<<<BL / 64, 256>>>(x, in_proj_w, dt_bias);
    // 4a) head-independent CB (fp32)
    k_cb<<<BATCH * NCH, 256, SMEM_CB_FLOATS * sizeof(float)>>>();
    // 4b) per-chunk per-head work (HMMA)
    k_chunk<<<dim3(BATCH * NCH, NHEADS), 256>>>(A_log);
    // 5) inter-chunk scan
    k_scan<<<(BATCH * NHEADS * HDIM * DSTATE / 2) / 256, 256>>>();
    // 6) Yo + skip (HMMA)
    k_yo<<<dim3(BATCH * NCH, NHEADS), 256>>>(D_skip);
    // 7) gate + rmsnorm (emits fp16)
    k_gate<<<BL, 256>>>(norm_w);
    // 8) out_proj GEMM (fp16 HMMA)
    k_gemm_h<<<dim3(DMODEL / 128, BL / 128), 256, GEMMH_SMEM_BYTES>>>(
        yh, w2h, go, BL, DMODEL, DINNER);
    // 9) LayerNorm + residual
    k_ln<<<BL, 256>>>(x, ln_w, ln_b, out);
}

// round 16
// speedup vs baseline: 5.6653x; 1.0901x over previous
#include <cuda_runtime.h>
#include <cuda_bf16.h>
#include <cuda_fp16.h>
#include <cstdint>

// ---------------- problem constants ----------------
#define BATCH  2
#define SEQ    4096
#define DMODEL 1024
#define DINNER 2048
#define DSTATE 128
#define NHEADS 32
#define HDIM   64
#define CDIM   2304        // DINNER + 2*DSTATE
#define NIN    4384        // 2*DINNER + 2*DSTATE + NHEADS
#define QC     64          // chunk length
#define NCH    64          // SEQ / QC
#define BL     8192        // BATCH * SEQ
#define DTMIN  0.001f
#define DTMAX  0.1f

// ---------------- scratch (device globals; no allocs allowed) ----------------
__device__ float g_zxbcdt[(size_t)BL * NIN];       // in_proj output
__device__ float g_xbc[(size_t)BL * CDIM];         // conv+silu output (x_ssm | B | C)
__device__ float g_dt[(size_t)BL * NHEADS];        // dt after sigmoid mapping (fp32-exact)
__device__ float g_Acum[(size_t)BATCH * NCH * NHEADS * QC];
__device__ float g_cdecay[(size_t)BATCH * NCH * NHEADS];
__device__ __half g_CB_h[(size_t)BATCH * NCH * QC * QC];   // head-independent C.B (fp16)
__device__ __half g_states_h[(size_t)BATCH * NCH * NHEADS * HDIM * DSTATE];
__device__ __half g_prevs_h [(size_t)BATCH * NCH * NHEADS * HDIM * DSTATE];
__device__ float g_Y[(size_t)BL * DINNER];         // Yd then += Yo + skip
__device__ float g_out[(size_t)BL * DMODEL];       // out_proj output (pre-LN)

// fp16 operands for tensor-core GEMMs
__device__ __half g_x_h [(size_t)BL * DMODEL];
__device__ __half g_w1_h[(size_t)NIN * DMODEL];
__device__ __half g_y_h [(size_t)BL * DINNER];
__device__ __half g_w2_h[(size_t)DMODEL * DINNER];

// ---------------- helpers ----------------
__device__ __forceinline__ float block_sum(float v) {
    __shared__ float sh[32];
    __syncthreads();
    int lane = threadIdx.x & 31, wid = threadIdx.x >> 5;
    #pragma unroll
    for (int o = 16; o > 0; o >>= 1) v += __shfl_xor_sync(0xffffffffu, v, o);
    if (lane == 0) sh[wid] = v;
    __syncthreads();
    float r = (threadIdx.x < (blockDim.x >> 5)) ? sh[threadIdx.x] : 0.f;
    if (wid == 0) {
        #pragma unroll
        for (int o = 16; o > 0; o >>= 1) r += __shfl_xor_sync(0xffffffffu, r, o);
        if (lane == 0) sh[0] = r;
    }
    __syncthreads();
    return sh[0];
}

__device__ __forceinline__ float silu(float x) { return x / (1.f + __expf(-x)); }

__device__ __forceinline__ uint32_t smem_u32(const void* p) {
    uint32_t a;
    asm("{ .reg .u64 t; cvta.to.shared.u64 t, %1; cvt.u32.u64 %0, t; }" : "=r"(a) : "l"(p));
    return a;
}

// ---------------- portable async-copy / ldmatrix / mma wrappers ----------------
__device__ __forceinline__ void cp16(uint32_t dst, const void* src, bool pred) {
    int sz = pred ? 16 : 0;
    asm volatile("cp.async.cg.shared.global [%0], [%1], 16, %2;\n"
                 :: "r"(dst), "l"(src), "r"(sz) : "memory");
}
__device__ __forceinline__ void cp_commit() {
    asm volatile("cp.async.commit_group;" ::: "memory");
}
template <int N>
__device__ __forceinline__ void cp_wait() {
    asm volatile("cp.async.wait_group %0;" :: "n"(N) : "memory");
}
__device__ __forceinline__ void ldm_x4(uint32_t* r, uint32_t addr) {
    asm volatile("ldmatrix.sync.aligned.m8n8.x4.shared.b16 {%0,%1,%2,%3}, [%4];"
                 : "=r"(r[0]), "=r"(r[1]), "=r"(r[2]), "=r"(r[3]) : "r"(addr));
}
__device__ __forceinline__ void ldm_x2(uint32_t* r, uint32_t addr) {
    asm volatile("ldmatrix.sync.aligned.m8n8.x2.shared.b16 {%0,%1}, [%2];"
                 : "=r"(r[0]), "=r"(r[1]) : "r"(addr));
}
__device__ __forceinline__ void ldm_x4_t(uint32_t* r, uint32_t addr) {
    asm volatile("ldmatrix.sync.aligned.m8n8.x4.trans.shared.b16 {%0,%1,%2,%3}, [%4];"
                 : "=r"(r[0]), "=r"(r[1]), "=r"(r[2]), "=r"(r[3]) : "r"(addr));
}
__device__ __forceinline__ void ldm_x2_t(uint32_t* r, uint32_t addr) {
    asm volatile("ldmatrix.sync.aligned.m8n8.x2.trans.shared.b16 {%0,%1}, [%2];"
                 : "=r"(r[0]), "=r"(r[1]) : "r"(addr));
}
__device__ __forceinline__ void mma_f16(float* d, const uint32_t* a, const uint32_t* b) {
    asm volatile("mma.sync.aligned.m16n8k16.row.col.f32.f16.f16.f32 "
                 "{%0,%1,%2,%3}, {%4,%5,%6,%7}, {%8,%9}, {%0,%1,%2,%3};"
                 : "+f"(d[0]), "+f"(d[1]), "+f"(d[2]), "+f"(d[3])
                 : "r"(a[0]), "r"(a[1]), "r"(a[2]), "r"(a[3]), "r"(b[0]), "r"(b[1]));
}

// ---------------- fp32 -> fp16 convert ----------------
__global__ void k_cvt_h(const float* __restrict__ in, __half* __restrict__ out, long long n4) {
    long long i = (long long)blockIdx.x * blockDim.x + threadIdx.x;
    if (i >= n4) return;
    float4 v = ((const float4*)in)[i];
    ((__half2*)out)[i * 2 + 0] = __floats2half2_rn(v.x, v.y);
    ((__half2*)out)[i * 2 + 1] = __floats2half2_rn(v.z, v.w);
}

// ---------------- fp16 HMMA GEMM: C[M,N] = A[M,K] * B[N,K]^T, 3-stage pipeline --------
#define BKH    64
#define HS_STR 72
#define H_TILE (128 * HS_STR)
#define OFF_B  H_TILE
#define H_STAGE (2 * H_TILE)
#define H_STAGE_B (H_STAGE * 2)            // 36864 bytes
#define GEMMH_SMEM_BYTES (3 * H_STAGE_B)   // 110592

__device__ __forceinline__ void load_stage_h(
    const __half* __restrict__ A, const __half* __restrict__ B,
    uint32_t smbase, int stage, int m0, int n0, int k0, int N, int K, int tid)
{
    uint32_t sb = smbase + (uint32_t)stage * H_STAGE_B;
    #pragma unroll
    for (int j = 0; j < 4; j++) {
        int c = tid + j * 256;
        int r = c >> 3, c8 = (c & 7) * 8;
        uint32_t soff = (uint32_t)(r * HS_STR + c8) * 2;
        cp16(sb + soff, A + (size_t)(m0 + r) * K + k0 + c8, true);
        bool ok = (n0 + r) < N;
        cp16(sb + OFF_B * 2 + soff, B + (size_t)(ok ? (n0 + r) : 0) * K + k0 + c8, ok);
    }
}

__global__ void __launch_bounds__(256, 2)
k_gemm_h(const __half* __restrict__ A, const __half* __restrict__ B,
         float* __restrict__ C, int M, int N, int K) {
    extern __shared__ __half smg[];
    const uint32_t smbase = smem_u32(smg);
    const int tid = threadIdx.x, wid = tid >> 5, lid = tid & 31;
    const int m0 = blockIdx.y * 128, n0 = blockIdx.x * 128;
    const int wm = (wid >> 2) * 64;
    const int wn = (wid & 3) * 32;
    const int l15 = lid & 15;

    float acc[4][4][4];
    #pragma unroll
    for (int mi = 0; mi < 4; mi++)
        #pragma unroll
        for (int ni = 0; ni < 4; ni++)
            #pragma unroll
            for (int k = 0; k < 4; k++) acc[mi][ni][k] = 0.f;

    const int la_row = wm + (lid & 15);
    const int la_col = (lid >> 4) * 8;
    const int lb_row = wn + (l15 & 7);
    const int lb_col = ((l15 >> 3) & 1) * 8;

    const int NIT = K / BKH;
    load_stage_h(A, B, smbase, 0, m0, n0, 0, N, K, tid);
    cp_commit();
    load_stage_h(A, B, smbase, 1, m0, n0, BKH, N, K, tid);
    cp_commit();

    int stg = 0;
    for (int it = 0; it < NIT; it++) {
        if (it == NIT - 1) cp_wait<0>(); else cp_wait<1>();
        __syncthreads();

        uint32_t sb = smbase + (uint32_t)stg * H_STAGE_B;
        #pragma unroll
        for (int ks = 0; ks < 4; ks++) {
            uint32_t af[4][4], bb[4][2];
            #pragma unroll
            for (int mi = 0; mi < 4; mi++)
                ldm_x4(af[mi], sb + (uint32_t)((la_row + mi * 16) * HS_STR + ks * 16 + la_col) * 2);
            #pragma unroll
            for (int ni = 0; ni < 4; ni++)
                ldm_x2(bb[ni], sb + (uint32_t)(OFF_B + (lb_row + ni * 8) * HS_STR + ks * 16 + lb_col) * 2);
            #pragma unroll
            for (int mi = 0; mi < 4; mi++)
                #pragma unroll
                for (int ni = 0; ni < 4; ni++)
                    mma_f16(acc[mi][ni], af[mi], bb[ni]);
        }
        if (it + 2 < NIT) {
            int ns = stg;   // (it+2)%3 == stage freed two iters ago == current-1 cyclic
            ns = stg - 1; if (ns < 0) ns += 3;
            load_stage_h(A, B, smbase, ns, m0, n0, (it + 2) * BKH, N, K, tid);
            cp_commit();
        }
        stg++; if (stg == 3) stg = 0;
    }

    const int r0 = m0 + wm + (lid >> 2);
    const int c0 = n0 + wn + (lid & 3) * 2;
    #pragma unroll
    for (int mi = 0; mi < 4; mi++) {
        #pragma unroll
        for (int ni = 0; ni < 4; ni++) {
            int col = c0 + ni * 8;
            if (col < N) {
                int row = r0 + mi * 16;
                *(float2*)&C[(size_t)row * N + col] = make_float2(acc[mi][ni][0], acc[mi][ni][1]);
                *(float2*)&C[(size_t)(row + 8) * N + col] = make_float2(acc[mi][ni][2], acc[mi][ni][3]);
            }
        }
    }
}

// ---------------- fp32-exact dt ----------------
__global__ void k_dtfix(const float* __restrict__ x, const float* __restrict__ in_proj_w,
                        const float* __restrict__ dt_bias) {
    __shared__ float xs[64 * 64];
    __shared__ float ws[32 * 65];
    const int tid = threadIdx.x;
    const int h = tid & 31, rg = tid >> 5;
    const int bl0 = blockIdx.x * 64;
    const float* wdt = in_proj_w + (size_t)(DINNER + CDIM) * DMODEL;

    float acc[8];
    #pragma unroll
    for (int i = 0; i < 8; i++) acc[i] = 0.f;

    for (int k0 = 0; k0 < DMODEL; k0 += 64) {
        __syncthreads();
        #pragma unroll
        for (int it = 0; it < 4; it++) {
            int i4 = tid + it * 256;
            int r = i4 >> 4, c4 = (i4 & 15) * 4;
            *(float4*)&xs[r * 64 + c4] = *(const float4*)&x[(size_t)(bl0 + r) * DMODEL + k0 + c4];
        }
        #pragma unroll
        for (int it = 0; it < 2; it++) {
            int i4 = tid + it * 256;
            int r = i4 >> 4, c4 = (i4 & 15) * 4;
            float4 v = *(const float4*)&wdt[(size_t)r * DMODEL + k0 + c4];
            ws[r * 65 + c4 + 0] = v.x; ws[r * 65 + c4 + 1] = v.y;
            ws[r * 65 + c4 + 2] = v.z; ws[r * 65 + c4 + 3] = v.w;
        }
        __syncthreads();
        #pragma unroll 8
        for (int k = 0; k < 64; k++) {
            float w = ws[h * 65 + k];
            #pragma unroll
            for (int i = 0; i < 8; i++)
                acc[i] = fmaf(xs[(rg * 8 + i) * 64 + k], w, acc[i]);
        }
    }
    float bias = dt_bias[h];
    #pragma unroll
    for (int i = 0; i < 8; i++) {
        float raw = acc[i] + bias;
        float sg = 1.f / (1.f + __expf(-raw));
        g_dt[(size_t)(bl0 + rg * 8 + i) * NHEADS + h] = DTMIN + (DTMAX - DTMIN) * sg;
    }
}

// ---------------- conv1d (K=4, causal) + bias + SiLU, 4 channels/thread ----------------
#define CD4 (CDIM / 4)   // 576
__global__ void k_conv(const float* __restrict__ conv_w, const float* __restrict__ conv_b) {
    int idx = blockIdx.x * blockDim.x + threadIdx.x;
    if (idx >= BL * CD4) return;
    int c4 = (idx % CD4) * 4;
    int bl = idx / CD4;
    int l  = bl & (SEQ - 1);
    const float4 w0 = *(const float4*)&conv_w[(c4 + 0) * 4];
    const float4 w1 = *(const float4*)&conv_w[(c4 + 1) * 4];
    const float4 w2 = *(const float4*)&conv_w[(c4 + 2) * 4];
    const float4 w3 = *(const float4*)&conv_w[(c4 + 3) * 4];
    const float4 bias = *(const float4*)&conv_b[c4];
    float4 z = make_float4(0.f, 0.f, 0.f, 0.f);
    float4 v3 = *(const float4*)&g_zxbcdt[(size_t)bl * NIN + DINNER + c4];
    float4 v2 = (l >= 1) ? *(const float4*)&g_zxbcdt[(size_t)(bl - 1) * NIN + DINNER + c4] : z;
    float4 v1 = (l >= 2) ? *(const float4*)&g_zxbcdt[(size_t)(bl - 2) * NIN + DINNER + c4] : z;
    float4 v0 = (l >= 3) ? *(const float4*)&g_zxbcdt[(size_t)(bl - 3) * NIN + DINNER + c4] : z;
    float4 r;
    r.x = bias.x + v0.x * w0.x + v1.x * w0.y + v2.x * w0.z + v3.x * w0.w;
    r.y = bias.y + v0.y * w1.x + v1.y * w1.y + v2.y * w1.z + v3.y * w1.w;
    r.z = bias.z + v0.z * w2.x + v1.z * w2.y + v2.z * w2.z + v3.z * w2.w;
    r.w = bias.w + v0.w * w3.x + v1.w * w3.y + v2.w * w3.z + v3.w * w3.w;
    r.x = silu(r.x); r.y = silu(r.y); r.z = silu(r.z); r.w = silu(r.w);
    *(float4*)&g_xbc[(size_t)bl * CDIM + c4] = r;
}

// ---------------- head-independent CB[q][s] = C_q . B_s via HMMA (fp16 out) -----------
#define BSH 136    // stride in halves (272 B rows)

__global__ void __launch_bounds__(256) k_cb() {
    __shared__ __half Bh[64 * BSH];
    __shared__ __half Ch[64 * BSH];
    const int tid = threadIdx.x;
    const int bc = blockIdx.x;
    const int b  = bc / NCH, cc = bc % NCH;
    const long long base_bl = (long long)b * SEQ + (long long)cc * QC;

    #pragma unroll
    for (int it = 0; it < 8; it++) {
        int i4 = tid + it * 256;
        int q = i4 >> 5, n4 = (i4 & 31) * 4;
        float4 bv = *(const float4*)&g_xbc[(base_bl + q) * CDIM + DINNER + n4];
        float4 cv = *(const float4*)&g_xbc[(base_bl + q) * CDIM + DINNER + DSTATE + n4];
        *(__half2*)&Bh[q * BSH + n4]     = __floats2half2_rn(bv.x, bv.y);
        *(__half2*)&Bh[q * BSH + n4 + 2] = __floats2half2_rn(bv.z, bv.w);
        *(__half2*)&Ch[q * BSH + n4]     = __floats2half2_rn(cv.x, cv.y);
        *(__half2*)&Ch[q * BSH + n4 + 2] = __floats2half2_rn(cv.z, cv.w);
    }
    __syncthreads();

    const int w = tid >> 5, lid = tid & 31;
    const int m0 = (w >> 1) * 16;       // q tile
    const int nb = (w & 1) * 32;        // s base
    const uint32_t cbm = smem_u32(Ch), bbm = smem_u32(Bh);

    float acc[4][4];
    #pragma unroll
    for (int i = 0; i < 4; i++)
        #pragma unroll
        for (int j = 0; j < 4; j++) acc[i][j] = 0.f;

    const uint32_t a_base = cbm + (uint32_t)((m0 + (lid & 15)) * BSH + (lid >> 4) * 8) * 2;
    const int brow = lid & 7;
    const int bcol = ((lid >> 3) & 1) * 8;
    #pragma unroll
    for (int ks = 0; ks < 8; ks++) {
        uint32_t a[4];
        ldm_x4(a, a_base + ks * 32);
        #pragma unroll
        for (int ni = 0; ni < 4; ni++) {
            uint32_t bf[2];
            ldm_x2(bf, bbm + (uint32_t)((nb + ni * 8 + brow) * BSH + ks * 16 + bcol) * 2);
            mma_f16(acc[ni], a, bf);
        }
    }

    int q = m0 + (lid >> 2), s0 = nb + (lid & 3) * 2;
    size_t obase = (size_t)bc * (QC * QC);
    #pragma unroll
    for (int ni = 0; ni < 4; ni++) {
        *(__half2*)&g_CB_h[obase + (size_t)q * QC + s0 + ni * 8] =
            __floats2half2_rn(acc[ni][0], acc[ni][1]);
        *(__half2*)&g_CB_h[obase + (size_t)(q + 8) * QC + s0 + ni * 8] =
            __floats2half2_rn(acc[ni][2], acc[ni][3]);
    }
}

// ---------------- per-chunk per-head via HMMA: Yd + states ----------------
#define XSH 72     // 144 B rows

__global__ void __launch_bounds__(256) k_chunk(const float* __restrict__ A_log) {
    __shared__ __half xsh[64 * XSH];    // x tile [q][p]
    __shared__ __half Bsh[64 * BSH];    // ws-scaled B tile [q][n]
    __shared__ __half CBLh[64 * XSH];   // masked/scaled CB [q][s]
    __shared__ float dt_s[64], Ac_s[64], ws_s[64];

    const int tid = threadIdx.x;
    const int bc = blockIdx.x, h = blockIdx.y;
    const int b = bc / NCH, cc = bc % NCH;
    const long long base_bl = (long long)b * SEQ + (long long)cc * QC;

    // x tile -> fp16
    #pragma unroll
    for (int it = 0; it < 4; it++) {
        int i4 = tid + it * 256;
        int q = i4 >> 4, p4 = (i4 & 15) * 4;
        float4 v = *(const float4*)&g_xbc[(base_bl + q) * CDIM + h * HDIM + p4];
        *(__half2*)&xsh[q * XSH + p4]     = __floats2half2_rn(v.x, v.y);
        *(__half2*)&xsh[q * XSH + p4 + 2] = __floats2half2_rn(v.z, v.w);
    }
    // stage B tile in regs (scaled by ws later)
    float4 breg[8];
    #pragma unroll
    for (int it = 0; it < 8; it++) {
        int i4 = tid + it * 256;
        int q = i4 >> 5, n4 = (i4 & 31) * 4;
        breg[it] = *(const float4*)&g_xbc[(base_bl + q) * CDIM + DINNER + n4];
    }
    if (tid < QC) dt_s[tid] = g_dt[(base_bl + tid) * NHEADS + h];
    __syncthreads();

    if (tid == 0) {
        float Ah = -__expf(A_log[h]);
        float s = 0.f;
        for (int q = 0; q < QC; q++) { s += dt_s[q] * Ah; Ac_s[q] = s; }
    }
    __syncthreads();

    if (tid < QC) {
        float last = Ac_s[QC - 1];
        ws_s[tid] = __expf(last - Ac_s[tid]) * dt_s[tid];
        g_Acum[((long long)bc * NHEADS + h) * QC + tid] = Ac_s[tid];
        if (tid == 0) g_cdecay[(long long)bc * NHEADS + h] = __expf(last);
    }
    // CBL -> fp16 (needs Ac_s, dt_s)
    #pragma unroll
    for (int it = 0; it < 4; it++) {
        int i4 = tid + it * 256;
        int q = i4 >> 4, s4 = (i4 & 15) * 4;
        __half2 cb01 = *(const __half2*)&g_CB_h[(size_t)bc * (QC * QC) + q * QC + s4];
        __half2 cb23 = *(const __half2*)&g_CB_h[(size_t)bc * (QC * QC) + q * QC + s4 + 2];
        float eq = Ac_s[q];
        float v0 = (s4 + 0 <= q) ? __low2float(cb01)  * __expf(eq - Ac_s[s4 + 0]) * dt_s[s4 + 0] : 0.f;
        float v1 = (s4 + 1 <= q) ? __high2float(cb01) * __expf(eq - Ac_s[s4 + 1]) * dt_s[s4 + 1] : 0.f;
        float v2 = (s4 + 2 <= q) ? __low2float(cb23)  * __expf(eq - Ac_s[s4 + 2]) * dt_s[s4 + 2] : 0.f;
        float v3 = (s4 + 3 <= q) ? __high2float(cb23) * __expf(eq - Ac_s[s4 + 3]) * dt_s[s4 + 3] : 0.f;
        *(__half2*)&CBLh[q * XSH + s4]     = __floats2half2_rn(v0, v1);
        *(__half2*)&CBLh[q * XSH + s4 + 2] = __floats2half2_rn(v2, v3);
    }
    __syncthreads();   // ws_s visible

    // Bsh = ws[q] * B[q][n] -> fp16
    #pragma unroll
    for (int it = 0; it < 8; it++) {
        int i4 = tid + it * 256;
        int q = i4 >> 5, n4 = (i4 & 31) * 4;
        float w = ws_s[q];
        *(__half2*)&Bsh[q * BSH + n4]     = __floats2half2_rn(breg[it].x * w, breg[it].y * w);
        *(__half2*)&Bsh[q * BSH + n4 + 2] = __floats2half2_rn(breg[it].z * w, breg[it].w * w);
    }
    __syncthreads();

    const int w = tid >> 5, lid = tid & 31;
    const uint32_t xb = smem_u32(xsh), cbb = smem_u32(CBLh), bbb = smem_u32(Bsh);

    // ---- Yd[q][p] = CBL x xs : A = CBLh row-major, B = xsh ([s][p]) via trans
    {
        const int m0 = (w >> 1) * 16;
        const int nb = (w & 1) * 32;
        float acc[4][4];
        #pragma unroll
        for (int i = 0; i < 4; i++)
            #pragma unroll
            for (int j = 0; j < 4; j++) acc[i][j] = 0.f;
        const uint32_t a_base = cbb + (uint32_t)((m0 + (lid & 15)) * XSH + (lid >> 4) * 8) * 2;
        const int bk = (lid & 7) + ((lid >> 3) & 1) * 8;
        #pragma unroll
        for (int ks = 0; ks < 4; ks++) {
            uint32_t a[4];
            ldm_x4(a, a_base + ks * 32);
            #pragma unroll
            for (int ni = 0; ni < 4; ni++) {
                uint32_t bf[2];
                ldm_x2_t(bf, xb + (uint32_t)((ks * 16 + bk) * XSH + nb + ni * 8) * 2);
                mma_f16(acc[ni], a, bf);
            }
        }
        int q = m0 + (lid >> 2), p0 = nb + (lid & 3) * 2;
        #pragma unroll
        for (int ni = 0; ni < 4; ni++) {
            *(float2*)&g_Y[(base_bl + q) * DINNER + h * HDIM + p0 + ni * 8] =
                make_float2(acc[ni][0], acc[ni][1]);
            *(float2*)&g_Y[(base_bl + q + 8) * DINNER + h * HDIM + p0 + ni * 8] =
                make_float2(acc[ni][2], acc[ni][3]);
        }
    }

    // ---- states[p][n] = (x.ws)^T x B : A = xsh trans ([q][p]), B = Bsh trans ([q][n])
    {
        const int m0 = (w >> 1) * 16;       // p tile
        const int nb = (w & 1) * 64;        // n base
        float acc[8][4];
        #pragma unroll
        for (int i = 0; i < 8; i++)
            #pragma unroll
            for (int j = 0; j < 4; j++) acc[i][j] = 0.f;
        const int ak = (lid & 7) + ((lid >> 4) & 1) * 8;
        const int am = m0 + ((lid >> 3) & 1) * 8;
        const int bk = (lid & 7) + ((lid >> 3) & 1) * 8;
        #pragma unroll
        for (int ks = 0; ks < 4; ks++) {
            uint32_t a[4];
            ldm_x4_t(a, xb + (uint32_t)((ks * 16 + ak) * XSH + am) * 2);
            #pragma unroll
            for (int ni = 0; ni < 8; ni++) {
                uint32_t bf[2];
                ldm_x2_t(bf, bbb + (uint32_t)((ks * 16 + bk) * BSH + nb + ni * 8) * 2);
                mma_f16(acc[ni], a, bf);
            }
        }
        long long sbase = ((long long)bc * NHEADS + h) * HDIM * DSTATE;
        int p = m0 + (lid >> 2), n0 = nb + (lid & 3) * 2;
        #pragma unroll
        for (int ni = 0; ni < 8; ni++) {
            *(__half2*)&g_states_h[sbase + (long long)p * DSTATE + n0 + ni * 8] =
                __floats2half2_rn(acc[ni][0], acc[ni][1]);
            *(__half2*)&g_states_h[sbase + (long long)(p + 8) * DSTATE + n0 + ni * 8] =
                __floats2half2_rn(acc[ni][2], acc[ni][3]);
        }
    }
}

// ---------------- parallel inter-chunk scan (half2 per thread, prefetch) --------------
__global__ void k_scan() {
    int el2 = blockIdx.x * 256 + threadIdx.x;
    int bh = el2 >> 12;
    int idx2 = (el2 & 4095) * 2;
    int b = bh >> 5, h = bh & 31;
    float cx = 0.f, cy = 0.f;
    long long bcn = (long long)b * NCH * NHEADS + h;
    __half2 st = *(const __half2*)&g_states_h[bcn * (HDIM * DSTATE) + idx2];
    float dec = g_cdecay[bcn];
    for (int c = 0; c < NCH; c++) {
        long long bcn_n = bcn + NHEADS;
        __half2 st_n = st;
        float dec_n = dec;
        if (c + 1 < NCH) {
            st_n = *(const __half2*)&g_states_h[bcn_n * (HDIM * DSTATE) + idx2];
            dec_n = g_cdecay[bcn_n];
        }
        *(__half2*)&g_prevs_h[bcn * (HDIM * DSTATE) + idx2] = __floats2half2_rn(cx, cy);
        cx = fmaf(dec, cx, __low2float(st));
        cy = fmaf(dec, cy, __high2float(st));
        st = st_n; dec = dec_n; bcn = bcn_n;
    }
}

// ---------------- Yo via HMMA + D_skip*x, accumulate into g_Y ----------------
__global__ void __launch_bounds__(256) k_yo(const float* __restrict__ D_skip) {
    __shared__ __half Csh[64 * BSH];   // C tile [q][n]
    __shared__ __half Pvh[64 * BSH];   // prevs [p][n]
    __shared__ float eA[64];

    const int tid = threadIdx.x;
    const int bc = blockIdx.x, h = blockIdx.y;
    const int b = bc / NCH, cc = bc % NCH;
    const long long base_bl = (long long)b * SEQ + (long long)cc * QC;
    const long long pbase = ((long long)bc * NHEADS + h) * (HDIM * DSTATE);

    #pragma unroll
    for (int it = 0; it < 8; it++) {
        int i4 = tid + it * 256;
        int r = i4 >> 5, n4 = (i4 & 31) * 4;
        float4 c = *(const float4*)&g_xbc[(base_bl + r) * CDIM + DINNER + DSTATE + n4];
        *(__half2*)&Csh[r * BSH + n4]     = __floats2half2_rn(c.x, c.y);
        *(__half2*)&Csh[r * BSH + n4 + 2] = __floats2half2_rn(c.z, c.w);
        *(uint2*)&Pvh[r * BSH + n4] = *(const uint2*)&g_prevs_h[pbase + (long long)r * DSTATE + n4];
    }
    if (tid < QC) eA[tid] = __expf(g_Acum[((long long)bc * NHEADS + h) * QC + tid]);
    __syncthreads();

    const float dsk = D_skip[h];
    const int w = tid >> 5, lid = tid & 31;
    const int m0 = (w >> 1) * 16;       // q tile
    const int nb = (w & 1) * 32;        // p base
    const uint32_t cbm = smem_u32(Csh), pbm = smem_u32(Pvh);

    float acc[4][4];
    #pragma unroll
    for (int i = 0; i < 4; i++)
        #pragma unroll
        for (int j = 0; j < 4; j++) acc[i][j] = 0.f;

    const uint32_t a_base = cbm + (uint32_t)((m0 + (lid & 15)) * BSH + (lid >> 4) * 8) * 2;
    const int brow = lid & 7;
    const int bcol = ((lid >> 3) & 1) * 8;
    #pragma unroll
    for (int ks = 0; ks < 8; ks++) {
        uint32_t a[4];
        ldm_x4(a, a_base + ks * 32);
        #pragma unroll
        for (int ni = 0; ni < 4; ni++) {
            uint32_t bf[2];
            ldm_x2(bf, pbm + (uint32_t)((nb + ni * 8 + brow) * BSH + ks * 16 + bcol) * 2);
            mma_f16(acc[ni], a, bf);
        }
    }

    int q = m0 + (lid >> 2), p0 = nb + (lid & 3) * 2;
    float e0 = eA[q], e1 = eA[q + 8];
    #pragma unroll
    for (int ni = 0; ni < 4; ni++) {
        int p = p0 + ni * 8;
        long long r0 = base_bl + q, r1 = base_bl + q + 8;
        float2 y0 = *(float2*)&g_Y[r0 * DINNER + h * HDIM + p];
        float2 x0 = *(const float2*)&g_xbc[r0 * CDIM + h * HDIM + p];
        y0.x += e0 * acc[ni][0] + dsk * x0.x;
        y0.y += e0 * acc[ni][1] + dsk * x0.y;
        *(float2*)&g_Y[r0 * DINNER + h * HDIM + p] = y0;
        float2 y1 = *(float2*)&g_Y[r1 * DINNER + h * HDIM + p];
        float2 x1 = *(const float2*)&g_xbc[r1 * CDIM + h * HDIM + p];
        y1.x += e1 * acc[ni][2] + dsk * x1.x;
        y1.y += e1 * acc[ni][3] + dsk * x1.y;
        *(float2*)&g_Y[r1 * DINNER + h * HDIM + p] = y1;
    }
}

// ---------------- gate with silu(z) + RMSNorm (vectorized), emit fp16 ----------------
__global__ void k_gate(const float* __restrict__ norm_w) {
    const long long row = blockIdx.x;
    const int t = threadIdx.x;                  // 256 threads, 8 elems each
    float v[8];
    float local = 0.f;
    #pragma unroll
    for (int j = 0; j < 2; j++) {
        int i = (t + j * 256) * 4;
        float4 yv = *(const float4*)&g_Y[row * DINNER + i];
        float4 zv = *(const float4*)&g_zxbcdt[row * NIN + i];
        v[j*4+0] = yv.x * silu(zv.x);
        v[j*4+1] = yv.y * silu(zv.y);
        v[j*4+2] = yv.z * silu(zv.z);
        v[j*4+3] = yv.w * silu(zv.w);
        local += v[j*4+0]*v[j*4+0] + v[j*4+1]*v[j*4+1] + v[j*4+2]*v[j*4+2] + v[j*4+3]*v[j*4+3];
    }
    float tot = block_sum(local);
    float scale = rsqrtf(tot / DINNER + 1e-5f);
    #pragma unroll
    for (int j = 0; j < 2; j++) {
        int i = (t + j * 256) * 4;
        float4 nw = *(const float4*)&norm_w[i];
        __half2 h0 = __floats2half2_rn(v[j*4+0] * scale * nw.x, v[j*4+1] * scale * nw.y);
        __half2 h1 = __floats2half2_rn(v[j*4+2] * scale * nw.z, v[j*4+3] * scale * nw.w);
        *(__half2*)&g_y_h[row * DINNER + i]     = h0;
        *(__half2*)&g_y_h[row * DINNER + i + 2] = h1;
    }
}

// ---------------- final LayerNorm + residual ----------------
__global__ void k_ln(const float* __restrict__ x, const float* __restrict__ ln_w,
                     const float* __restrict__ ln_b, float* __restrict__ out) {
    const long long row = blockIdx.x;
    const int t = threadIdx.x;
    float4 o = ((const float4*)&g_out[row * DMODEL])[t];
    float s = o.x + o.y + o.z + o.w;
    float sq = o.x*o.x + o.y*o.y + o.z*o.z + o.w*o.w;
    float sum = block_sum(s);
    float sumsq = block_sum(sq);
    float mu = sum / DMODEL;
    float var = sumsq / DMODEL - mu * mu;
    float rs = rsqrtf(var + 1e-5f);
    float4 xr = ((const float4*)&x[row * DMODEL])[t];
    float4 w = ((const float4*)ln_w)[t];
    float4 bb = ((const float4*)ln_b)[t];
    float4 r;
    r.x = xr.x + (o.x - mu) * rs * w.x + bb.x;
    r.y = xr.y + (o.y - mu) * rs * w.y + bb.y;
    r.z = xr.z + (o.z - mu) * rs * w.z + bb.z;
    r.w = xr.w + (o.w - mu) * rs * w.w + bb.w;
    ((float4*)&out[row * DMODEL])[t] = r;
}

// ---------------- launch ----------------
extern "C" void kernel_launch(void* const* d_in, const int* in_sizes, int n_in,
                              void* d_out, int out_size) {
    const float* x          = (const float*)d_in[0];
    const float* in_proj_w  = (const float*)d_in[1];
    const float* conv_w     = (const float*)d_in[2];
    const float* conv_b     = (const float*)d_in[3];
    const float* dt_bias    = (const float*)d_in[4];
    const float* A_log      = (const float*)d_in[5];
    const float* D_skip     = (const float*)d_in[6];
    const float* norm_w     = (const float*)d_in[7];
    const float* out_proj_w = (const float*)d_in[8];
    const float* ln_w       = (const float*)d_in[9];
    const float* ln_b       = (const float*)d_in[10];
    float* out = (float*)d_out;
    (void)in_sizes; (void)n_in; (void)out_size;

    cudaFuncSetAttribute(k_gemm_h, cudaFuncAttributeMaxDynamicSharedMemorySize,
                         GEMMH_SMEM_BYTES);

    __half *xh, *w1h, *yh, *w2h;
    float *zx, *go;
    cudaGetSymbolAddress((void**)&xh,  g_x_h);
    cudaGetSymbolAddress((void**)&w1h, g_w1_h);
    cudaGetSymbolAddress((void**)&yh,  g_y_h);
    cudaGetSymbolAddress((void**)&w2h, g_w2_h);
    cudaGetSymbolAddress((void**)&zx,  g_zxbcdt);
    cudaGetSymbolAddress((void**)&go,  g_out);

    // 0) fp16 conversions
    k_cvt_h<<<(int)(((long long)BL * DMODEL / 4 + 255) / 256), 256>>>(x, xh, (long long)BL * DMODEL / 4);
    k_cvt_h<<<(int)(((long long)NIN * DMODEL / 4 + 255) / 256), 256>>>(in_proj_w, w1h, (long long)NIN * DMODEL / 4);
    k_cvt_h<<<(int)(((long long)DMODEL * DINNER / 4 + 255) / 256), 256>>>(out_proj_w, w2h, (long long)DMODEL * DINNER / 4);

    // 1) in_proj GEMM (fp16 HMMA, 3-stage)
    k_gemm_h<<<dim3((NIN + 127) / 128, BL / 128), 256, GEMMH_SMEM_BYTES>>>(
        xh, w1h, zx, BL, NIN, DMODEL);
    // 2) causal conv + SiLU
    k_conv<<<(BL * CD4 + 255) / 256, 256>>>(conv_w, conv_b);
    // 3) fp32-exact dt
    k_dtfix<<<BL / 64, 256>>>(x, in_proj_w, dt_bias);
    // 4a) head-independent CB (HMMA, fp16 out)
    k_cb<<<BATCH * NCH, 256>>>();
    // 4b) per-chunk per-head work (HMMA)
    k_chunk<<<dim3(BATCH * NCH, NHEADS), 256>>>(A_log);
    // 5) inter-chunk scan
    k_scan<<<(BATCH * NHEADS * HDIM * DSTATE / 2) / 256, 256>>>();
    // 6) Yo + skip (HMMA)
    k_yo<<<dim3(BATCH * NCH, NHEADS), 256>>>(D_skip);
    // 7) gate + rmsnorm (vectorized, emits fp16)
    k_gate<<<BL, 256>>>(norm_w);
    // 8) out_proj GEMM (fp16 HMMA, 3-stage)
    k_gemm_h<<<dim3(DMODEL / 128, BL / 128), 256, GEMMH_SMEM_BYTES>>>(
        yh, w2h, go, BL, DMODEL, DINNER);
    // 9) LayerNorm + residual
    k_ln<<<BL, 256>>>(x, ln_w, ln_b, out);
}